// round 3
// baseline (speedup 1.0000x reference)
#include <cuda_runtime.h>

// Problem constants
#define BB   8
#define TT   1024
#define CC   512
#define HH   8
#define HD   64
#define NR   137      // 2*MAXR + 1
#define MAXR 68
#define BH   64       // BB*HH
#define MM   8192     // BB*TT

// Scratch (device globals; no runtime allocation allowed)
static __device__ float g_q[BH * TT * HD];          // (bh, t, d)
static __device__ float g_k[BH * TT * HD];
static __device__ float g_v[BH * TT * HD];
static __device__ float g_proj[BH * TT * NR];       // q . rel_k^T
static __device__ float g_y[MM * CC];               // pre-output-proj activations

// ---------------------------------------------------------------------------
// 128x128 fp32 GEMM tile helper
// ---------------------------------------------------------------------------
__device__ __forceinline__ void gemm128_tile(
    const float* __restrict__ A, const float* __restrict__ W,
    int row0, int col0, float c[8][8], float* As, float* Bs)
{
    int tid = threadIdx.x;
    int tx = tid & 15, ty = tid >> 4;

    for (int k0 = 0; k0 < CC; k0 += 8) {
        {
            int r  = tid >> 1;
            int cg = (tid & 1) * 4;
            float4 a4 = *(const float4*)(A + (size_t)(row0 + r) * CC + k0 + cg);
            As[(cg + 0) * 129 + r] = a4.x;
            As[(cg + 1) * 129 + r] = a4.y;
            As[(cg + 2) * 129 + r] = a4.z;
            As[(cg + 3) * 129 + r] = a4.w;
        }
        {
            int r  = tid >> 5;
            int cg = (tid & 31) * 4;
            float4 b4 = *(const float4*)(W + (size_t)(k0 + r) * CC + col0 + cg);
            *(float4*)(Bs + r * 128 + cg) = b4;
        }
        __syncthreads();
        #pragma unroll
        for (int kk = 0; kk < 8; kk++) {
            float a[8], b[8];
            #pragma unroll
            for (int i = 0; i < 8; i++) a[i] = As[kk * 129 + ty * 8 + i];
            #pragma unroll
            for (int j = 0; j < 8; j++) b[j] = Bs[kk * 128 + tx * 8 + j];
            #pragma unroll
            for (int i = 0; i < 8; i++)
                #pragma unroll
                for (int j = 0; j < 8; j++)
                    c[i][j] += a[i] * b[j];
        }
        __syncthreads();
    }
}

// ---------------------------------------------------------------------------
// K1: q/k/v = x @ W + b   -> stored as (b, h, t, d)
// ---------------------------------------------------------------------------
__global__ __launch_bounds__(256) void qkv_gemm(
    const float* __restrict__ x,
    const float* __restrict__ Wq, const float* __restrict__ bq,
    const float* __restrict__ Wk, const float* __restrict__ bk,
    const float* __restrict__ Wv, const float* __restrict__ bv)
{
    __shared__ float As[8 * 129];
    __shared__ float Bs[8 * 128];
    int z = blockIdx.z;
    const float* W   = (z == 0) ? Wq : (z == 1) ? Wk : Wv;
    const float* bia = (z == 0) ? bq : (z == 1) ? bk : bv;
    float* out       = (z == 0) ? g_q : (z == 1) ? g_k : g_v;

    int row0 = blockIdx.y * 128, col0 = blockIdx.x * 128;
    float c[8][8];
    #pragma unroll
    for (int i = 0; i < 8; i++)
        #pragma unroll
        for (int j = 0; j < 8; j++) c[i][j] = 0.0f;

    gemm128_tile(x, W, row0, col0, c, As, Bs);

    int tx = threadIdx.x & 15, ty = threadIdx.x >> 4;
    int n0 = col0 + tx * 8;
    float bb[8];
    #pragma unroll
    for (int j = 0; j < 8; j++) bb[j] = bia[n0 + j];
    int h = n0 >> 6, d0 = n0 & 63;

    #pragma unroll
    for (int i = 0; i < 8; i++) {
        int m  = row0 + ty * 8 + i;
        int b_ = m >> 10, t = m & (TT - 1);
        size_t ob = (((size_t)b_ * HH + h) * TT + t) * HD + d0;
        float4 v0 = make_float4(c[i][0] + bb[0], c[i][1] + bb[1],
                                c[i][2] + bb[2], c[i][3] + bb[3]);
        float4 v1 = make_float4(c[i][4] + bb[4], c[i][5] + bb[5],
                                c[i][6] + bb[6], c[i][7] + bb[7]);
        *(float4*)(out + ob)     = v0;
        *(float4*)(out + ob + 4) = v1;
    }
}

// ---------------------------------------------------------------------------
// K2: proj[row, r] = q[row, :] . rel_k[r, :]
// ---------------------------------------------------------------------------
__global__ __launch_bounds__(256) void proj_kernel(const float* __restrict__ rel_k)
{
    __shared__ float qs[32 * 64];
    __shared__ float rkt[64 * NR];
    int tid = threadIdx.x;
    int r0  = blockIdx.x * 32;

    for (int idx = tid; idx < 32 * 64; idx += 256)
        qs[idx] = g_q[(size_t)r0 * 64 + idx];
    for (int idx = tid; idx < 64 * NR; idx += 256) {
        int dd = idx / NR, r = idx - dd * NR;
        rkt[idx] = rel_k[r * 64 + dd];
    }
    __syncthreads();

    int tx = tid & 31, ty = tid >> 5;
    float c[4][5];
    #pragma unroll
    for (int i = 0; i < 4; i++)
        #pragma unroll
        for (int j = 0; j < 5; j++) c[i][j] = 0.0f;
    int rr[5];
    #pragma unroll
    for (int j = 0; j < 5; j++) { int r = tx + 32 * j; rr[j] = (r < NR) ? r : (NR - 1); }

    for (int dd = 0; dd < 64; dd++) {
        float qv[4], rv[5];
        #pragma unroll
        for (int i = 0; i < 4; i++) qv[i] = qs[(ty * 4 + i) * 64 + dd];
        #pragma unroll
        for (int j = 0; j < 5; j++) rv[j] = rkt[dd * NR + rr[j]];
        #pragma unroll
        for (int i = 0; i < 4; i++)
            #pragma unroll
            for (int j = 0; j < 5; j++) c[i][j] += qv[i] * rv[j];
    }

    #pragma unroll
    for (int i = 0; i < 4; i++) {
        size_t rowg = (size_t)(r0 + ty * 4 + i);
        #pragma unroll
        for (int j = 0; j < 5; j++) {
            int r = tx + 32 * j;
            if (r < NR) g_proj[rowg * NR + r] = c[i][j];
        }
    }
}

// ---------------------------------------------------------------------------
// K3 (fused): flash-style attention per (t-tile, bh)
//   online softmax, band-bucket logits, PV accumulation, rel_v epilogue
// grid (8, 64), block 256
// ---------------------------------------------------------------------------
// smem layout (floats)
#define FA_QS    0                   // 64 x 132 (Qs[dd][t])
#define FA_KS    8448                // 64 x 65  (Ks[dd][k])
#define FA_VS    12608               // 64 x 68  (Vs[k][d])
#define FA_PS    16960               // 128 x 68 (Ps[t][k])
#define FA_BAND  25664               // 128 x 136 (logits; -1e30 = empty)
#define FA_MS    43072               // 128 row maxes (epilogue)
#define FA_FLOATS 43200
#define FA_SMEM_BYTES (FA_FLOATS * 4)   // 172800 B
// rel_v (137*64 = 8768 floats) aliases FA_QS region in the epilogue

__global__ __launch_bounds__(256) void fused_attn(const float* __restrict__ rel_v)
{
    extern __shared__ float sm[];
    float* Qs   = sm + FA_QS;
    float* Ks   = sm + FA_KS;
    float* Vs   = sm + FA_VS;
    float* Ps   = sm + FA_PS;
    float* band = sm + FA_BAND;
    float* m_s  = sm + FA_MS;
    float* rvs  = sm + FA_QS;        // epilogue alias

    int bh  = blockIdx.y;
    int t0  = blockIdx.x * 128;
    int tid = threadIdx.x;
    int tx  = tid & 15, ty = tid >> 4;

    const float* qbase = g_q + (size_t)bh * TT * HD;
    const float* kbase = g_k + (size_t)bh * TT * HD;
    const float* vbase = g_v + (size_t)bh * TT * HD;
    const float scale = 0.044194173824159216f;   // 1/sqrt(512)

    // prologue: Q tile transposed into Qs[dd][t]; band init
    #pragma unroll
    for (int s = 0; s < 8; s++) {
        int n = tid + s * 256;           // 0..2047
        int trow = n >> 4;
        int dd4  = (n & 15) * 4;
        float4 qv = *(const float4*)(qbase + (size_t)(t0 + trow) * HD + dd4);
        Qs[(dd4 + 0) * 132 + trow] = qv.x;
        Qs[(dd4 + 1) * 132 + trow] = qv.y;
        Qs[(dd4 + 2) * 132 + trow] = qv.z;
        Qs[(dd4 + 3) * 132 + trow] = qv.w;
    }
    for (int idx = tid; idx < 128 * 136; idx += 256) band[idx] = -1e30f;

    float c[8][4];
    float m[8], l[8], plo[8];
    #pragma unroll
    for (int i = 0; i < 8; i++) {
        m[i] = -1e30f; l[i] = 0.0f; plo[i] = 0.0f;
        #pragma unroll
        for (int j = 0; j < 4; j++) c[i][j] = 0.0f;
    }

    for (int k0 = 0; k0 < TT; k0 += 64) {
        __syncthreads();     // previous iteration's PV reads done
        // load K tile (transposed) + V tile
        #pragma unroll
        for (int s = 0; s < 4; s++) {
            int n = tid + s * 256;       // 0..1023
            int krow = n >> 4;
            int dd4  = (n & 15) * 4;
            float4 kv = *(const float4*)(kbase + (size_t)(k0 + krow) * HD + dd4);
            Ks[(dd4 + 0) * 65 + krow] = kv.x;
            Ks[(dd4 + 1) * 65 + krow] = kv.y;
            Ks[(dd4 + 2) * 65 + krow] = kv.z;
            Ks[(dd4 + 3) * 65 + krow] = kv.w;
            float4 vv = *(const float4*)(vbase + (size_t)(k0 + krow) * HD + dd4);
            *(float4*)(Vs + krow * 68 + dd4) = vv;
        }
        __syncthreads();

        // S chunk: cs[8][4] = Q[t] . K[k]
        float cs[8][4];
        #pragma unroll
        for (int i = 0; i < 8; i++)
            #pragma unroll
            for (int j = 0; j < 4; j++) cs[i][j] = 0.0f;

        for (int dd = 0; dd < 64; dd++) {
            float a[8], b[4];
            *(float4*)(a)     = *(const float4*)(Qs + dd * 132 + ty * 8);
            *(float4*)(a + 4) = *(const float4*)(Qs + dd * 132 + ty * 8 + 4);
            #pragma unroll
            for (int j = 0; j < 4; j++) b[j] = Ks[dd * 65 + tx * 4 + j];
            #pragma unroll
            for (int i = 0; i < 8; i++)
                #pragma unroll
                for (int j = 0; j < 4; j++) cs[i][j] += a[i] * b[j];
        }

        // online softmax update per row
        #pragma unroll
        for (int i = 0; i < 8; i++) {
            int tg = t0 + ty * 8 + i;
            const float* prow = g_proj + ((size_t)bh * TT + tg) * NR;
            float o[4];
            float mt = -1e30f;
            #pragma unroll
            for (int j = 0; j < 4; j++) {
                int kg = k0 + tx * 4 + j;
                int d  = kg - tg;
                int dc = d < -MAXR ? -MAXR : (d > MAXR ? MAXR : d);
                o[j] = (cs[i][j] + prow[dc + MAXR]) * scale;
                mt = fmaxf(mt, o[j]);
            }
            #pragma unroll
            for (int off = 8; off >= 1; off >>= 1)
                mt = fmaxf(mt, __shfl_xor_sync(0xffffffffu, mt, off, 16));
            float mnew = fmaxf(m[i], mt);
            float f = __expf(m[i] - mnew);
            m[i] = mnew;
            l[i] *= f; plo[i] *= f;
            #pragma unroll
            for (int j = 0; j < 4; j++) c[i][j] *= f;

            float p[4], ls = 0.0f, pl = 0.0f;
            #pragma unroll
            for (int j = 0; j < 4; j++) {
                p[j] = __expf(o[j] - mnew);
                ls += p[j];
                int d = (k0 + tx * 4 + j) - tg;
                if ((unsigned)(d + 67) <= 134u)
                    band[(ty * 8 + i) * 136 + d + 67] = o[j];   // raw logit
                else if (d <= -MAXR)
                    pl += p[j];
            }
            l[i] += ls; plo[i] += pl;
            *(float4*)(Ps + (ty * 8 + i) * 68 + tx * 4) =
                make_float4(p[0], p[1], p[2], p[3]);
        }
        __syncthreads();

        // PV: c += Ps[t][k] * Vs[k][d]
        for (int kk = 0; kk < 64; kk++) {
            float b[4], a[8];
            *(float4*)b = *(const float4*)(Vs + kk * 68 + tx * 4);
            #pragma unroll
            for (int i = 0; i < 8; i++) a[i] = Ps[(ty * 8 + i) * 68 + kk];
            #pragma unroll
            for (int i = 0; i < 8; i++)
                #pragma unroll
                for (int j = 0; j < 4; j++) c[i][j] += a[i] * b[j];
        }
    }

    // final cross-lane reductions (16 lanes share each row)
    #pragma unroll
    for (int i = 0; i < 8; i++) {
        #pragma unroll
        for (int off = 8; off >= 1; off >>= 1) {
            l[i]   += __shfl_xor_sync(0xffffffffu, l[i],   off, 16);
            plo[i] += __shfl_xor_sync(0xffffffffu, plo[i], off, 16);
        }
    }
    if (tx == 0) {
        #pragma unroll
        for (int i = 0; i < 8; i++) m_s[ty * 8 + i] = m[i];
    }
    __syncthreads();

    // band: logits -> probabilities (each element once)
    for (int idx = tid; idx < 128 * 135; idx += 256) {
        int row = idx / 135, cc = idx - row * 135;
        band[row * 136 + cc] = __expf(band[row * 136 + cc] - m_s[row]);
    }
    // rel_v into smem (aliases Qs/Ks — both dead now)
    for (int idx = tid * 4; idx < NR * 64; idx += 256 * 4)
        *(float4*)(rvs + idx) = *(const float4*)(rel_v + idx);
    __syncthreads();

    // epilogue: w2 = band @ rel_v  (+ running in-band sum)
    float intu[8];
    #pragma unroll
    for (int i = 0; i < 8; i++) intu[i] = 0.0f;

    for (int r = 1; r <= 135; r++) {
        float rv[4];
        *(float4*)rv = *(const float4*)(rvs + r * 64 + tx * 4);
        #pragma unroll
        for (int i = 0; i < 8; i++) {
            float sv = band[(ty * 8 + i) * 136 + (r - 1)];
            intu[i] += sv;
            #pragma unroll
            for (int j = 0; j < 4; j++) c[i][j] += sv * rv[j];
        }
    }

    int b_ = bh >> 3, h = bh & 7;
    #pragma unroll
    for (int i = 0; i < 8; i++) {
        float lr  = l[i];
        float phi = lr - plo[i] - intu[i];
        float inv = 1.0f / lr;
        float o[4];
        #pragma unroll
        for (int j = 0; j < 4; j++) {
            float w = c[i][j] + plo[i] * rvs[tx * 4 + j]
                              + phi    * rvs[136 * 64 + tx * 4 + j];
            o[j] = w * inv;
        }
        int t = t0 + ty * 8 + i;
        *(float4*)(g_y + ((size_t)(b_ * TT + t)) * CC + h * HD + tx * 4) =
            make_float4(o[0], o[1], o[2], o[3]);
    }
}

// ---------------------------------------------------------------------------
// K6: out = y @ Wo + bo
// ---------------------------------------------------------------------------
__global__ __launch_bounds__(256) void out_gemm(
    const float* __restrict__ Wo, const float* __restrict__ bo,
    float* __restrict__ out)
{
    __shared__ float As[8 * 129];
    __shared__ float Bs[8 * 128];
    int row0 = blockIdx.y * 128, col0 = blockIdx.x * 128;
    float c[8][8];
    #pragma unroll
    for (int i = 0; i < 8; i++)
        #pragma unroll
        for (int j = 0; j < 8; j++) c[i][j] = 0.0f;

    gemm128_tile(g_y, Wo, row0, col0, c, As, Bs);

    int tx = threadIdx.x & 15, ty = threadIdx.x >> 4;
    int n0 = col0 + tx * 8;
    float bb[8];
    #pragma unroll
    for (int j = 0; j < 8; j++) bb[j] = bo[n0 + j];

    #pragma unroll
    for (int i = 0; i < 8; i++) {
        int m = row0 + ty * 8 + i;
        float4 v0 = make_float4(c[i][0] + bb[0], c[i][1] + bb[1],
                                c[i][2] + bb[2], c[i][3] + bb[3]);
        float4 v1 = make_float4(c[i][4] + bb[4], c[i][5] + bb[5],
                                c[i][6] + bb[6], c[i][7] + bb[7]);
        *(float4*)(out + (size_t)m * CC + n0)     = v0;
        *(float4*)(out + (size_t)m * CC + n0 + 4) = v1;
    }
}

// ---------------------------------------------------------------------------
extern "C" void kernel_launch(void* const* d_in, const int* in_sizes, int n_in,
                              void* d_out, int out_size)
{
    const float* x     = (const float*)d_in[0];
    const float* Wq    = (const float*)d_in[1];
    const float* bq    = (const float*)d_in[2];
    const float* Wk    = (const float*)d_in[3];
    const float* bk    = (const float*)d_in[4];
    const float* Wv    = (const float*)d_in[5];
    const float* bv    = (const float*)d_in[6];
    const float* Wo    = (const float*)d_in[7];
    const float* bo    = (const float*)d_in[8];
    const float* rel_k = (const float*)d_in[9];
    const float* rel_v = (const float*)d_in[10];
    float* out = (float*)d_out;

    cudaFuncSetAttribute(fused_attn, cudaFuncAttributeMaxDynamicSharedMemorySize,
                         FA_SMEM_BYTES);

    qkv_gemm<<<dim3(4, 64, 3), 256>>>(x, Wq, bq, Wk, bk, Wv, bv);
    proj_kernel<<<BH * TT / 32, 256>>>(rel_k);
    fused_attn<<<dim3(8, 64), 256, FA_SMEM_BYTES>>>(rel_v);
    out_gemm<<<dim3(4, 64), 256>>>(Wo, bo, out);
}

// round 6
// speedup vs baseline: 1.3272x; 1.3272x over previous
#include <cuda_runtime.h>
#include <cuda_bf16.h>
#include <cstdint>

// Problem constants
#define BB   8
#define TT   1024
#define CC   512
#define HH   8
#define HD   64
#define NR   137
#define MAXR 68
#define BH   64
#define MM   8192

// ---------------------------------------------------------------------------
// Scratch (device globals)
// ---------------------------------------------------------------------------
static __device__ float g_q[BH * TT * HD];
static __device__ float g_k[BH * TT * HD];
static __device__ float g_v[BH * TT * HD];
static __device__ float g_proj[BH * TT * NR];
static __device__ float g_S[67108864];
static __device__ float g_tm[BH * 8 * TT];
static __device__ float g_ts[BH * 8 * TT];
static __device__ float g_m[BH * TT];
static __device__ float g_l[BH * TT];
static __device__ float g_y[MM * CC];

static __device__ __nv_bfloat16 g_xhi[MM * CC];
static __device__ __nv_bfloat16 g_xlo[MM * CC];
static __device__ __nv_bfloat16 g_yhi[MM * CC];
static __device__ __nv_bfloat16 g_ylo[MM * CC];
static __device__ __nv_bfloat16 g_wthi[4 * CC * CC];   // [n][k] transposed, q|k|v|o
static __device__ __nv_bfloat16 g_wtlo[4 * CC * CC];
static __device__ float g_bias[4 * CC];                // bq|bk|bv|bo

// ---------------------------------------------------------------------------
// warp-MMA helpers (arch-portable: ldmatrix + mma.sync, sm_80+)
// ---------------------------------------------------------------------------
__device__ __forceinline__ uint32_t smem_u32(const void* p) {
    uint32_t a;
    asm("{ .reg .u64 t; cvta.to.shared.u64 t, %1; cvt.u32.u64 %0, t; }"
        : "=r"(a) : "l"(p));
    return a;
}
__device__ __forceinline__ void ldsm4(uint32_t* r, uint32_t addr) {
    asm volatile("ldmatrix.sync.aligned.m8n8.x4.shared.b16 {%0,%1,%2,%3}, [%4];"
        : "=r"(r[0]), "=r"(r[1]), "=r"(r[2]), "=r"(r[3]) : "r"(addr));
}
__device__ __forceinline__ void ldsm2(uint32_t* r, uint32_t addr) {
    asm volatile("ldmatrix.sync.aligned.m8n8.x2.shared.b16 {%0,%1}, [%2];"
        : "=r"(r[0]), "=r"(r[1]) : "r"(addr));
}
__device__ __forceinline__ void mma16816(float* c, const uint32_t* a, const uint32_t* b) {
    asm volatile(
        "mma.sync.aligned.m16n8k16.row.col.f32.bf16.bf16.f32 "
        "{%0,%1,%2,%3}, {%4,%5,%6,%7}, {%8,%9}, {%0,%1,%2,%3};"
        : "+f"(c[0]), "+f"(c[1]), "+f"(c[2]), "+f"(c[3])
        : "r"(a[0]), "r"(a[1]), "r"(a[2]), "r"(a[3]), "r"(b[0]), "r"(b[1]));
}
#define SWZ128(b) ((b) ^ (((b) >> 3) & 0x70))

// ---------------------------------------------------------------------------
// conversion kernels
// ---------------------------------------------------------------------------
__global__ __launch_bounds__(512) void conv_split_x(const float* __restrict__ src, int n4)
{
    for (int i = blockIdx.x * blockDim.x + threadIdx.x; i < n4;
         i += gridDim.x * blockDim.x) {
        float4 v = *(const float4*)(src + (size_t)i * 4);
        float vv[4] = {v.x, v.y, v.z, v.w};
        #pragma unroll
        for (int j = 0; j < 4; j++) {
            __nv_bfloat16 h = __float2bfloat16(vv[j]);
            g_xhi[(size_t)i * 4 + j] = h;
            g_xlo[(size_t)i * 4 + j] = __float2bfloat16(vv[j] - __bfloat162float(h));
        }
    }
}

__global__ __launch_bounds__(512) void conv_split_y(int n4)
{
    for (int i = blockIdx.x * blockDim.x + threadIdx.x; i < n4;
         i += gridDim.x * blockDim.x) {
        float4 v = *(const float4*)(g_y + (size_t)i * 4);
        float vv[4] = {v.x, v.y, v.z, v.w};
        #pragma unroll
        for (int j = 0; j < 4; j++) {
            __nv_bfloat16 h = __float2bfloat16(vv[j]);
            g_yhi[(size_t)i * 4 + j] = h;
            g_ylo[(size_t)i * 4 + j] = __float2bfloat16(vv[j] - __bfloat162float(h));
        }
    }
}

__global__ __launch_bounds__(512) void conv_w(
    const float* __restrict__ Wq, const float* __restrict__ Wk,
    const float* __restrict__ Wv, const float* __restrict__ Wo,
    const float* __restrict__ bq, const float* __restrict__ bk,
    const float* __restrict__ bv, const float* __restrict__ bo)
{
    int gid = blockIdx.x * blockDim.x + threadIdx.x;
    int nth = gridDim.x * blockDim.x;
    for (int idx = gid; idx < 4 * CC * CC; idx += nth) {
        int z = idx >> 18;
        int rem = idx & (CC * CC - 1);
        int k = rem >> 9, n = rem & 511;
        const float* W = (z == 0) ? Wq : (z == 1) ? Wk : (z == 2) ? Wv : Wo;
        float v = W[k * CC + n];
        __nv_bfloat16 h = __float2bfloat16(v);
        size_t dst = (size_t)z * CC * CC + (size_t)n * CC + k;
        g_wthi[dst] = h;
        g_wtlo[dst] = __float2bfloat16(v - __bfloat162float(h));
    }
    if (gid < 4 * CC) {
        int z = gid >> 9, n = gid & 511;
        const float* bsrc = (z == 0) ? bq : (z == 1) ? bk : (z == 2) ? bv : bo;
        g_bias[gid] = bsrc[n];
    }
}

// ---------------------------------------------------------------------------
// bf16x3 warp-MMA GEMM: C[128,128] = A[M,512] @ Bt[N,512]^T (+bias)
// mode 1: A = x (hi/lo), B = W_{q,k,v}, scatter to g_q/g_k/g_v
// mode 0: A = y (hi/lo), B = W_o, write to outp
// grid (N/128, M/128), block 256 (8 warps, 64x32 warp tiles)
// ---------------------------------------------------------------------------
#define GT_A_HI 0
#define GT_A_LO 16384
#define GT_B_HI 32768
#define GT_B_LO 49152
#define GT_SMEM 65536

__global__ __launch_bounds__(256, 2) void gemm_mma(float* __restrict__ outp, int mode)
{
    extern __shared__ char smc[];
    const __nv_bfloat16 *Ahi, *Alo, *Bhi, *Blo;
    const float* bias;
    if (mode == 1) {
        Ahi = g_xhi; Alo = g_xlo; Bhi = g_wthi; Blo = g_wtlo; bias = g_bias;
    } else {
        Ahi = g_yhi; Alo = g_ylo;
        Bhi = g_wthi + 3 * CC * CC; Blo = g_wtlo + 3 * CC * CC;
        bias = g_bias + 3 * CC;
    }

    int tid = threadIdx.x, lane = tid & 31, wid = tid >> 5;
    int wm = wid >> 2, wn = wid & 3;
    int row0 = blockIdx.y * 128, col0 = blockIdx.x * 128;

    uint32_t sA_hi = smem_u32(smc + GT_A_HI);
    uint32_t sA_lo = smem_u32(smc + GT_A_LO);
    uint32_t sB_hi = smem_u32(smc + GT_B_HI);
    uint32_t sB_lo = smem_u32(smc + GT_B_LO);

    float c[4][4][4];
    #pragma unroll
    for (int mi = 0; mi < 4; mi++)
        #pragma unroll
        for (int ni = 0; ni < 4; ni++)
            #pragma unroll
            for (int e = 0; e < 4; e++) c[mi][ni][e] = 0.0f;

    for (int kc = 0; kc < 8; kc++) {
        int k0 = kc * 64;
        __syncthreads();
        #pragma unroll
        for (int s = 0; s < 4; s++) {
            int vec = tid + s * 256;
            int r = vec >> 3, v8 = vec & 7;
            uint32_t dst = SWZ128((uint32_t)(r * 128 + v8 * 16));
            size_t asrc = (size_t)(row0 + r) * CC + k0 + v8 * 8;
            size_t bsrc = (size_t)(col0 + r) * CC + k0 + v8 * 8;
            *(uint4*)(smc + GT_A_HI + dst) = *(const uint4*)(Ahi + asrc);
            *(uint4*)(smc + GT_A_LO + dst) = *(const uint4*)(Alo + asrc);
            *(uint4*)(smc + GT_B_HI + dst) = *(const uint4*)(Bhi + bsrc);
            *(uint4*)(smc + GT_B_LO + dst) = *(const uint4*)(Blo + bsrc);
        }
        __syncthreads();

        #pragma unroll
        for (int ks = 0; ks < 4; ks++) {
            int kbase = ks * 16;
            // B fragments (n8k16 each): lanes 0-15 supply addresses
            int lp = lane & 15;
            int bkb = kbase + (lp >> 3) * 8;
            uint32_t bh[4][2], bl[4][2];
            #pragma unroll
            for (int ni = 0; ni < 4; ni++) {
                int nloc = wn * 32 + ni * 8 + (lp & 7);
                uint32_t ad = SWZ128((uint32_t)(nloc * 128 + bkb * 2));
                ldsm2(bh[ni], sB_hi + ad);
                ldsm2(bl[ni], sB_lo + ad);
            }
            // A fragments (m16k16), 3-product accumulate
            int akb = kbase + (lane >> 4) * 8;
            int mlp = lane & 15;
            #pragma unroll
            for (int mi = 0; mi < 4; mi++) {
                int mloc = wm * 64 + mi * 16 + mlp;
                uint32_t ad = SWZ128((uint32_t)(mloc * 128 + akb * 2));
                uint32_t ah[4], al[4];
                ldsm4(ah, sA_hi + ad);
                ldsm4(al, sA_lo + ad);
                #pragma unroll
                for (int ni = 0; ni < 4; ni++) {
                    mma16816(c[mi][ni], ah, bh[ni]);
                    mma16816(c[mi][ni], ah, bl[ni]);
                    mma16816(c[mi][ni], al, bh[ni]);
                }
            }
        }
    }

    // epilogue
    int r_base = row0 + wm * 64 + (lane >> 2);
    int n_base = col0 + wn * 32 + (lane & 3) * 2;

    if (mode == 0) {
        #pragma unroll
        for (int mi = 0; mi < 4; mi++) {
            int r = r_base + mi * 16;
            #pragma unroll
            for (int ni = 0; ni < 4; ni++) {
                int n = n_base + ni * 8;
                float b0 = bias[n], b1 = bias[n + 1];
                float2 v0 = make_float2(c[mi][ni][0] + b0, c[mi][ni][1] + b1);
                float2 v1 = make_float2(c[mi][ni][2] + b0, c[mi][ni][3] + b1);
                *(float2*)(outp + (size_t)r * CC + n)       = v0;
                *(float2*)(outp + (size_t)(r + 8) * CC + n) = v1;
            }
        }
    } else {
        int z = col0 >> 9;
        float* dst = (z == 0) ? g_q : (z == 1) ? g_k : g_v;
        #pragma unroll
        for (int mi = 0; mi < 4; mi++) {
            int r = r_base + mi * 16;
            int b_ = r >> 10, t = r & (TT - 1);
            #pragma unroll
            for (int ni = 0; ni < 4; ni++) {
                int n = n_base + ni * 8;
                int nn = n & 511;
                int h = nn >> 6, d = nn & 63;
                float b0 = bias[n], b1 = bias[n + 1];
                size_t o = (((size_t)b_ * HH + h) * TT + t) * HD + d;
                float2 v0 = make_float2(c[mi][ni][0] + b0, c[mi][ni][1] + b1);
                float2 v1 = make_float2(c[mi][ni][2] + b0, c[mi][ni][3] + b1);
                *(float2*)(dst + o)           = v0;
                *(float2*)(dst + o + 8 * HD)  = v1;   // row r+8 -> t+8
            }
        }
    }
}

// ---------------------------------------------------------------------------
// proj[row, r] = q[row, :] . rel_k[r, :]
// ---------------------------------------------------------------------------
__global__ __launch_bounds__(256) void proj_kernel(const float* __restrict__ rel_k)
{
    __shared__ float qs[32 * 64];
    __shared__ float rkt[64 * NR];
    int tid = threadIdx.x;
    int r0  = blockIdx.x * 32;

    for (int idx = tid; idx < 32 * 64; idx += 256)
        qs[idx] = g_q[(size_t)r0 * 64 + idx];
    for (int idx = tid; idx < 64 * NR; idx += 256) {
        int dd = idx / NR, r = idx - dd * NR;
        rkt[idx] = rel_k[r * 64 + dd];
    }
    __syncthreads();

    int tx = tid & 31, ty = tid >> 5;
    float c[4][5];
    #pragma unroll
    for (int i = 0; i < 4; i++)
        #pragma unroll
        for (int j = 0; j < 5; j++) c[i][j] = 0.0f;
    int rr[5];
    #pragma unroll
    for (int j = 0; j < 5; j++) { int r = tx + 32 * j; rr[j] = (r < NR) ? r : (NR - 1); }

    for (int dd = 0; dd < 64; dd++) {
        float qv[4], rv[5];
        #pragma unroll
        for (int i = 0; i < 4; i++) qv[i] = qs[(ty * 4 + i) * 64 + dd];
        #pragma unroll
        for (int j = 0; j < 5; j++) rv[j] = rkt[dd * NR + rr[j]];
        #pragma unroll
        for (int i = 0; i < 4; i++)
            #pragma unroll
            for (int j = 0; j < 5; j++) c[i][j] += qv[i] * rv[j];
    }

    #pragma unroll
    for (int i = 0; i < 4; i++) {
        size_t rowg = (size_t)(r0 + ty * 4 + i);
        #pragma unroll
        for (int j = 0; j < 5; j++) {
            int r = tx + 32 * j;
            if (r < NR) g_proj[rowg * NR + r] = c[i][j];
        }
    }
}

// ---------------------------------------------------------------------------
// S kernel + per-tile max/expsum
// ---------------------------------------------------------------------------
__global__ __launch_bounds__(256) void s_kernel()
{
    __shared__ float Qs[16 * 129];
    __shared__ float Ks[16 * 129];
    int bh = blockIdx.z;
    int t0 = blockIdx.y * 128, k0 = blockIdx.x * 128;
    int tid = threadIdx.x;
    int tx = tid & 15, ty = tid >> 4;

    float c[8][8];
    #pragma unroll
    for (int i = 0; i < 8; i++)
        #pragma unroll
        for (int j = 0; j < 8; j++) c[i][j] = 0.0f;

    const float* qbase = g_q + (size_t)bh * TT * HD;
    const float* kbase = g_k + (size_t)bh * TT * HD;

    for (int dd0 = 0; dd0 < HD; dd0 += 16) {
        for (int n = tid; n < 512; n += 256) {
            int trow = n >> 2, c4 = (n & 3) * 4;
            float4 a4 = *(const float4*)(qbase + (size_t)(t0 + trow) * HD + dd0 + c4);
            Qs[(c4 + 0) * 129 + trow] = a4.x;
            Qs[(c4 + 1) * 129 + trow] = a4.y;
            Qs[(c4 + 2) * 129 + trow] = a4.z;
            Qs[(c4 + 3) * 129 + trow] = a4.w;
            float4 b4 = *(const float4*)(kbase + (size_t)(k0 + trow) * HD + dd0 + c4);
            Ks[(c4 + 0) * 129 + trow] = b4.x;
            Ks[(c4 + 1) * 129 + trow] = b4.y;
            Ks[(c4 + 2) * 129 + trow] = b4.z;
            Ks[(c4 + 3) * 129 + trow] = b4.w;
        }
        __syncthreads();
        #pragma unroll
        for (int dd = 0; dd < 16; dd++) {
            float a[8], b[8];
            #pragma unroll
            for (int i = 0; i < 8; i++) a[i] = Qs[dd * 129 + ty * 8 + i];
            #pragma unroll
            for (int j = 0; j < 8; j++) b[j] = Ks[dd * 129 + tx * 8 + j];
            #pragma unroll
            for (int i = 0; i < 8; i++)
                #pragma unroll
                for (int j = 0; j < 8; j++) c[i][j] += a[i] * b[j];
        }
        __syncthreads();
    }

    const float scale = 0.044194173824159216f;
    #pragma unroll
    for (int i = 0; i < 8; i++) {
        int tg = t0 + ty * 8 + i;
        const float* prow = g_proj + ((size_t)bh * TT + tg) * NR;
        float* srow = g_S + ((size_t)bh * TT + tg) * TT + k0 + tx * 8;
        float o[8];
        #pragma unroll
        for (int j = 0; j < 8; j++) {
            int kg = k0 + tx * 8 + j;
            int dist = kg - tg;
            dist = dist < -MAXR ? -MAXR : (dist > MAXR ? MAXR : dist);
            o[j] = (c[i][j] + prow[dist + MAXR]) * scale;
        }
        *(float4*)(srow)     = make_float4(o[0], o[1], o[2], o[3]);
        *(float4*)(srow + 4) = make_float4(o[4], o[5], o[6], o[7]);

        float mloc = o[0];
        #pragma unroll
        for (int j = 1; j < 8; j++) mloc = fmaxf(mloc, o[j]);
        #pragma unroll
        for (int off = 8; off >= 1; off >>= 1)
            mloc = fmaxf(mloc, __shfl_xor_sync(0xffffffffu, mloc, off, 16));
        float es = 0.0f;
        #pragma unroll
        for (int j = 0; j < 8; j++) es += __expf(o[j] - mloc);
        #pragma unroll
        for (int off = 8; off >= 1; off >>= 1)
            es += __shfl_xor_sync(0xffffffffu, es, off, 16);
        if (tx == 0) {
            size_t ob = ((size_t)bh * 8 + blockIdx.x) * TT + tg;
            g_tm[ob] = mloc;
            g_ts[ob] = es;
        }
    }
}

__global__ __launch_bounds__(1024) void reduce_ml()
{
    int bh = blockIdx.x;
    int t  = threadIdx.x;
    float tm[8], ts[8];
    #pragma unroll
    for (int i = 0; i < 8; i++) {
        size_t ob = ((size_t)bh * 8 + i) * TT + t;
        tm[i] = g_tm[ob];
        ts[i] = g_ts[ob];
    }
    float m = tm[0];
    #pragma unroll
    for (int i = 1; i < 8; i++) m = fmaxf(m, tm[i]);
    float l = 0.0f;
    #pragma unroll
    for (int i = 0; i < 8; i++) l += ts[i] * __expf(tm[i] - m);
    g_m[(size_t)bh * TT + t] = m;
    g_l[(size_t)bh * TT + t] = l;
}

// ---------------------------------------------------------------------------
// PV fused exp + band + rel_v epilogue
// ---------------------------------------------------------------------------
#define PV_PS    0
#define PV_VS    2064
#define PV_BAND  3088
#define PV_RELV  20496
#define PV_M     29264
#define PV_L     29392
#define PV_PLO   29520
#define PV_FLOATS 29648
#define PV_SMEM_BYTES (PV_FLOATS * 4)

__global__ __launch_bounds__(256) void pv_kernel(const float* __restrict__ rel_v)
{
    extern __shared__ float sm[];
    float* Ps    = sm + PV_PS;
    float* Vs    = sm + PV_VS;
    float* band  = sm + PV_BAND;
    float* rvs   = sm + PV_RELV;
    float* m_s   = sm + PV_M;
    float* l_s   = sm + PV_L;
    float* plo_s = sm + PV_PLO;

    int bh = blockIdx.y;
    int t0 = blockIdx.x * 128;
    int tid = threadIdx.x;
    int tx = tid & 15, ty = tid >> 4;

    for (int idx = tid; idx < 128 * 136; idx += 256) band[idx] = 0.0f;
    if (tid < 128) {
        m_s[tid] = g_m[(size_t)bh * TT + t0 + tid];
        l_s[tid] = g_l[(size_t)bh * TT + t0 + tid];
    }
    __syncthreads();

    float c[8][4];
    #pragma unroll
    for (int i = 0; i < 8; i++)
        #pragma unroll
        for (int j = 0; j < 4; j++) c[i][j] = 0.0f;

    float plo_a = 0.0f, plo_b = 0.0f;

    const float* pbase = g_S + (size_t)bh * TT * TT;
    const float* vbase = g_v + (size_t)bh * TT * HD;

    for (int k0 = 0; k0 < TT; k0 += 16) {
        #pragma unroll
        for (int half = 0; half < 2; half++) {
            int n = tid + half * 256;
            int trow = n >> 2, c4 = (n & 3) * 4;
            int tg = t0 + trow;
            float mrow = m_s[trow];
            float4 a4 = *(const float4*)(pbase + (size_t)tg * TT + k0 + c4);
            float pv0 = __expf(a4.x - mrow);
            float pv1 = __expf(a4.y - mrow);
            float pv2 = __expf(a4.z - mrow);
            float pv3 = __expf(a4.w - mrow);
            Ps[(c4 + 0) * 129 + trow] = pv0;
            Ps[(c4 + 1) * 129 + trow] = pv1;
            Ps[(c4 + 2) * 129 + trow] = pv2;
            Ps[(c4 + 3) * 129 + trow] = pv3;
            float pl = 0.0f;
            #pragma unroll
            for (int j = 0; j < 4; j++) {
                float pv = (j == 0) ? pv0 : (j == 1) ? pv1 : (j == 2) ? pv2 : pv3;
                int d = (k0 + c4 + j) - tg;
                if ((unsigned)(d + 67) <= 134u)
                    band[trow * 136 + d + 67] = pv;
                else if (d <= -MAXR)
                    pl += pv;
            }
            if (half == 0) plo_a += pl; else plo_b += pl;
        }
        {
            int krow = tid >> 4, c4v = (tid & 15) * 4;
            *(float4*)(Vs + krow * 64 + c4v) =
                *(const float4*)(vbase + (size_t)(k0 + krow) * HD + c4v);
        }
        __syncthreads();
        #pragma unroll
        for (int kk = 0; kk < 16; kk++) {
            float a[8], b[4];
            #pragma unroll
            for (int i = 0; i < 8; i++) a[i] = Ps[kk * 129 + ty * 8 + i];
            #pragma unroll
            for (int j = 0; j < 4; j++) b[j] = Vs[kk * 64 + tx * 4 + j];
            #pragma unroll
            for (int i = 0; i < 8; i++)
                #pragma unroll
                for (int j = 0; j < 4; j++) c[i][j] += a[i] * b[j];
        }
        __syncthreads();
    }

    plo_a += __shfl_xor_sync(0xffffffffu, plo_a, 1);
    plo_a += __shfl_xor_sync(0xffffffffu, plo_a, 2);
    plo_b += __shfl_xor_sync(0xffffffffu, plo_b, 1);
    plo_b += __shfl_xor_sync(0xffffffffu, plo_b, 2);
    if ((tid & 3) == 0) {
        plo_s[tid >> 2]        = plo_a;
        plo_s[64 + (tid >> 2)] = plo_b;
    }
    for (int idx = tid * 4; idx < NR * 64; idx += 256 * 4)
        *(float4*)(rvs + idx) = *(const float4*)(rel_v + idx);
    __syncthreads();

    float intu[8];
    #pragma unroll
    for (int i = 0; i < 8; i++) intu[i] = 0.0f;

    for (int r = 1; r <= 135; r++) {
        float rv[4];
        #pragma unroll
        for (int j = 0; j < 4; j++) rv[j] = rvs[r * 64 + tx * 4 + j];
        #pragma unroll
        for (int i = 0; i < 8; i++) {
            float sv = band[(ty * 8 + i) * 136 + (r - 1)];
            intu[i] += sv;
            #pragma unroll
            for (int j = 0; j < 4; j++) c[i][j] += sv * rv[j];
        }
    }

    int b_ = bh >> 3, h = bh & 7;
    #pragma unroll
    for (int i = 0; i < 8; i++) {
        int row = ty * 8 + i;
        float plo = plo_s[row];
        float lr  = l_s[row];
        float phi = lr - plo - intu[i];
        float inv = 1.0f / lr;
        float o[4];
        #pragma unroll
        for (int j = 0; j < 4; j++) {
            float w = c[i][j] + plo * rvs[tx * 4 + j]
                              + phi * rvs[136 * 64 + tx * 4 + j];
            o[j] = w * inv;
        }
        int t = t0 + row;
        *(float4*)(g_y + ((size_t)(b_ * TT + t)) * CC + h * HD + tx * 4) =
            make_float4(o[0], o[1], o[2], o[3]);
    }
}

// ---------------------------------------------------------------------------
extern "C" void kernel_launch(void* const* d_in, const int* in_sizes, int n_in,
                              void* d_out, int out_size)
{
    const float* x     = (const float*)d_in[0];
    const float* Wq    = (const float*)d_in[1];
    const float* bq    = (const float*)d_in[2];
    const float* Wk    = (const float*)d_in[3];
    const float* bk    = (const float*)d_in[4];
    const float* Wv    = (const float*)d_in[5];
    const float* bv    = (const float*)d_in[6];
    const float* Wo    = (const float*)d_in[7];
    const float* bo    = (const float*)d_in[8];
    const float* rel_k = (const float*)d_in[9];
    const float* rel_v = (const float*)d_in[10];
    float* out = (float*)d_out;

    cudaFuncSetAttribute(pv_kernel, cudaFuncAttributeMaxDynamicSharedMemorySize,
                         PV_SMEM_BYTES);
    cudaFuncSetAttribute(gemm_mma, cudaFuncAttributeMaxDynamicSharedMemorySize,
                         GT_SMEM);

    conv_w<<<1024, 512>>>(Wq, Wk, Wv, Wo, bq, bk, bv, bo);
    conv_split_x<<<1024, 512>>>(x, MM * CC / 4);
    gemm_mma<<<dim3(12, 64), 256, GT_SMEM>>>(nullptr, 1);
    proj_kernel<<<BH * TT / 32, 256>>>(rel_k);
    s_kernel<<<dim3(8, 8, 64), 256>>>();
    reduce_ml<<<64, 1024>>>();
    pv_kernel<<<dim3(8, 64), 256, PV_SMEM_BYTES>>>(rel_v);
    conv_split_y<<<1024, 512>>>(MM * CC / 4);
    gemm_mma<<<dim3(4, 64), 256, GT_SMEM>>>(out, 0);
}

// round 7
// speedup vs baseline: 1.7220x; 1.2974x over previous
#include <cuda_runtime.h>
#include <cuda_bf16.h>
#include <cstdint>

// Problem constants
#define BB   8
#define TT   1024
#define CC   512
#define HH   8
#define HD   64
#define NR   137
#define MAXR 68
#define BH   64
#define MM   8192
#define NRP  144     // NR padded to 16 multiple

// ---------------------------------------------------------------------------
// Scratch (device globals)
// ---------------------------------------------------------------------------
static __device__ float g_v[BH * TT * HD];
static __device__ float g_proj[BH * TT * NR];
static __device__ float g_S[67108864];
static __device__ float g_tm[BH * 8 * TT];
static __device__ float g_ts[BH * 8 * TT];
static __device__ float g_m[BH * TT];
static __device__ float g_l[BH * TT];
static __device__ float g_y[MM * CC];

static __device__ __nv_bfloat16 g_qhi[BH * TT * HD];
static __device__ __nv_bfloat16 g_qlo[BH * TT * HD];
static __device__ __nv_bfloat16 g_khi[BH * TT * HD];
static __device__ __nv_bfloat16 g_klo[BH * TT * HD];
static __device__ __nv_bfloat16 g_rkhi[NRP * HD];
static __device__ __nv_bfloat16 g_rklo[NRP * HD];

static __device__ __nv_bfloat16 g_xhi[MM * CC];
static __device__ __nv_bfloat16 g_xlo[MM * CC];
static __device__ __nv_bfloat16 g_yhi[MM * CC];
static __device__ __nv_bfloat16 g_ylo[MM * CC];
static __device__ __nv_bfloat16 g_wthi[4 * CC * CC];   // [n][k] transposed, q|k|v|o
static __device__ __nv_bfloat16 g_wtlo[4 * CC * CC];
static __device__ float g_bias[4 * CC];                // bq|bk|bv|bo

// ---------------------------------------------------------------------------
// warp-MMA helpers
// ---------------------------------------------------------------------------
__device__ __forceinline__ uint32_t smem_u32(const void* p) {
    uint32_t a;
    asm("{ .reg .u64 t; cvta.to.shared.u64 t, %1; cvt.u32.u64 %0, t; }"
        : "=r"(a) : "l"(p));
    return a;
}
__device__ __forceinline__ void ldsm4(uint32_t* r, uint32_t addr) {
    asm volatile("ldmatrix.sync.aligned.m8n8.x4.shared.b16 {%0,%1,%2,%3}, [%4];"
        : "=r"(r[0]), "=r"(r[1]), "=r"(r[2]), "=r"(r[3]) : "r"(addr));
}
__device__ __forceinline__ void ldsm2(uint32_t* r, uint32_t addr) {
    asm volatile("ldmatrix.sync.aligned.m8n8.x2.shared.b16 {%0,%1}, [%2];"
        : "=r"(r[0]), "=r"(r[1]) : "r"(addr));
}
__device__ __forceinline__ void mma16816(float* c, const uint32_t* a, const uint32_t* b) {
    asm volatile(
        "mma.sync.aligned.m16n8k16.row.col.f32.bf16.bf16.f32 "
        "{%0,%1,%2,%3}, {%4,%5,%6,%7}, {%8,%9}, {%0,%1,%2,%3};"
        : "+f"(c[0]), "+f"(c[1]), "+f"(c[2]), "+f"(c[3])
        : "r"(a[0]), "r"(a[1]), "r"(a[2]), "r"(a[3]), "r"(b[0]), "r"(b[1]));
}
#define SWZ128(b) ((b) ^ (((b) >> 3) & 0x70))

// ---------------------------------------------------------------------------
// conversion kernels
// ---------------------------------------------------------------------------
__global__ __launch_bounds__(512) void conv_split_x(const float* __restrict__ src, int n4)
{
    for (int i = blockIdx.x * blockDim.x + threadIdx.x; i < n4;
         i += gridDim.x * blockDim.x) {
        float4 v = *(const float4*)(src + (size_t)i * 4);
        float vv[4] = {v.x, v.y, v.z, v.w};
        #pragma unroll
        for (int j = 0; j < 4; j++) {
            __nv_bfloat16 h = __float2bfloat16(vv[j]);
            g_xhi[(size_t)i * 4 + j] = h;
            g_xlo[(size_t)i * 4 + j] = __float2bfloat16(vv[j] - __bfloat162float(h));
        }
    }
}

__global__ __launch_bounds__(512) void conv_split_y(int n4)
{
    for (int i = blockIdx.x * blockDim.x + threadIdx.x; i < n4;
         i += gridDim.x * blockDim.x) {
        float4 v = *(const float4*)(g_y + (size_t)i * 4);
        float vv[4] = {v.x, v.y, v.z, v.w};
        #pragma unroll
        for (int j = 0; j < 4; j++) {
            __nv_bfloat16 h = __float2bfloat16(vv[j]);
            g_yhi[(size_t)i * 4 + j] = h;
            g_ylo[(size_t)i * 4 + j] = __float2bfloat16(vv[j] - __bfloat162float(h));
        }
    }
}

__global__ __launch_bounds__(512) void conv_w(
    const float* __restrict__ Wq, const float* __restrict__ Wk,
    const float* __restrict__ Wv, const float* __restrict__ Wo,
    const float* __restrict__ bq, const float* __restrict__ bk,
    const float* __restrict__ bv, const float* __restrict__ bo,
    const float* __restrict__ rel_k)
{
    int gid = blockIdx.x * blockDim.x + threadIdx.x;
    int nth = gridDim.x * blockDim.x;
    for (int idx = gid; idx < 4 * CC * CC; idx += nth) {
        int z = idx >> 18;
        int rem = idx & (CC * CC - 1);
        int k = rem >> 9, n = rem & 511;
        const float* W = (z == 0) ? Wq : (z == 1) ? Wk : (z == 2) ? Wv : Wo;
        float v = W[k * CC + n];
        __nv_bfloat16 h = __float2bfloat16(v);
        size_t dst = (size_t)z * CC * CC + (size_t)n * CC + k;
        g_wthi[dst] = h;
        g_wtlo[dst] = __float2bfloat16(v - __bfloat162float(h));
    }
    for (int idx = gid; idx < NRP * HD; idx += nth) {
        int r = idx >> 6, d = idx & 63;
        float v = (r < NR) ? rel_k[r * HD + d] : 0.0f;
        __nv_bfloat16 h = __float2bfloat16(v);
        g_rkhi[idx] = h;
        g_rklo[idx] = __float2bfloat16(v - __bfloat162float(h));
    }
    if (gid < 4 * CC) {
        int z = gid >> 9, n = gid & 511;
        const float* bsrc = (z == 0) ? bq : (z == 1) ? bk : (z == 2) ? bv : bo;
        g_bias[gid] = bsrc[n];
    }
}

// ---------------------------------------------------------------------------
// bf16x3 warp-MMA GEMM: C[128,128] = A[M,512] @ Bt[N,512]^T (+bias)
// mode 1: A = x, B = W_{q,k,v}; q,k -> bf16 hi/lo, v -> fp32
// mode 0: A = y, B = W_o, write fp32 to outp
// ---------------------------------------------------------------------------
#define GT_A_HI 0
#define GT_A_LO 16384
#define GT_B_HI 32768
#define GT_B_LO 49152
#define GT_SMEM 65536

__global__ __launch_bounds__(256, 2) void gemm_mma(float* __restrict__ outp, int mode)
{
    extern __shared__ char smc[];
    const __nv_bfloat16 *Ahi, *Alo, *Bhi, *Blo;
    const float* bias;
    if (mode == 1) {
        Ahi = g_xhi; Alo = g_xlo; Bhi = g_wthi; Blo = g_wtlo; bias = g_bias;
    } else {
        Ahi = g_yhi; Alo = g_ylo;
        Bhi = g_wthi + 3 * CC * CC; Blo = g_wtlo + 3 * CC * CC;
        bias = g_bias + 3 * CC;
    }

    int tid = threadIdx.x, lane = tid & 31, wid = tid >> 5;
    int wm = wid >> 2, wn = wid & 3;
    int row0 = blockIdx.y * 128, col0 = blockIdx.x * 128;

    uint32_t sA_hi = smem_u32(smc + GT_A_HI);
    uint32_t sA_lo = smem_u32(smc + GT_A_LO);
    uint32_t sB_hi = smem_u32(smc + GT_B_HI);
    uint32_t sB_lo = smem_u32(smc + GT_B_LO);

    float c[4][4][4];
    #pragma unroll
    for (int mi = 0; mi < 4; mi++)
        #pragma unroll
        for (int ni = 0; ni < 4; ni++)
            #pragma unroll
            for (int e = 0; e < 4; e++) c[mi][ni][e] = 0.0f;

    for (int kc = 0; kc < 8; kc++) {
        int k0 = kc * 64;
        __syncthreads();
        #pragma unroll
        for (int s = 0; s < 4; s++) {
            int vec = tid + s * 256;
            int r = vec >> 3, v8 = vec & 7;
            uint32_t dst = SWZ128((uint32_t)(r * 128 + v8 * 16));
            size_t asrc = (size_t)(row0 + r) * CC + k0 + v8 * 8;
            size_t bsrc = (size_t)(col0 + r) * CC + k0 + v8 * 8;
            *(uint4*)(smc + GT_A_HI + dst) = *(const uint4*)(Ahi + asrc);
            *(uint4*)(smc + GT_A_LO + dst) = *(const uint4*)(Alo + asrc);
            *(uint4*)(smc + GT_B_HI + dst) = *(const uint4*)(Bhi + bsrc);
            *(uint4*)(smc + GT_B_LO + dst) = *(const uint4*)(Blo + bsrc);
        }
        __syncthreads();

        #pragma unroll
        for (int ks = 0; ks < 4; ks++) {
            int kbase = ks * 16;
            int lp = lane & 15;
            int bkb = kbase + (lp >> 3) * 8;
            uint32_t bh[4][2], bl[4][2];
            #pragma unroll
            for (int ni = 0; ni < 4; ni++) {
                int nloc = wn * 32 + ni * 8 + (lp & 7);
                uint32_t ad = SWZ128((uint32_t)(nloc * 128 + bkb * 2));
                ldsm2(bh[ni], sB_hi + ad);
                ldsm2(bl[ni], sB_lo + ad);
            }
            int akb = kbase + (lane >> 4) * 8;
            int mlp = lane & 15;
            #pragma unroll
            for (int mi = 0; mi < 4; mi++) {
                int mloc = wm * 64 + mi * 16 + mlp;
                uint32_t ad = SWZ128((uint32_t)(mloc * 128 + akb * 2));
                uint32_t ah[4], al[4];
                ldsm4(ah, sA_hi + ad);
                ldsm4(al, sA_lo + ad);
                #pragma unroll
                for (int ni = 0; ni < 4; ni++) {
                    mma16816(c[mi][ni], ah, bh[ni]);
                    mma16816(c[mi][ni], ah, bl[ni]);
                    mma16816(c[mi][ni], al, bh[ni]);
                }
            }
        }
    }

    int r_base = row0 + wm * 64 + (lane >> 2);
    int n_base = col0 + wn * 32 + (lane & 3) * 2;

    if (mode == 0) {
        #pragma unroll
        for (int mi = 0; mi < 4; mi++) {
            int r = r_base + mi * 16;
            #pragma unroll
            for (int ni = 0; ni < 4; ni++) {
                int n = n_base + ni * 8;
                float b0 = bias[n], b1 = bias[n + 1];
                float2 v0 = make_float2(c[mi][ni][0] + b0, c[mi][ni][1] + b1);
                float2 v1 = make_float2(c[mi][ni][2] + b0, c[mi][ni][3] + b1);
                *(float2*)(outp + (size_t)r * CC + n)       = v0;
                *(float2*)(outp + (size_t)(r + 8) * CC + n) = v1;
            }
        }
    } else {
        int z = col0 >> 9;
        #pragma unroll
        for (int mi = 0; mi < 4; mi++) {
            int r = r_base + mi * 16;
            int b_ = r >> 10, t = r & (TT - 1);
            #pragma unroll
            for (int ni = 0; ni < 4; ni++) {
                int n = n_base + ni * 8;
                int nn = n & 511;
                int h = nn >> 6, d = nn & 63;
                float b0 = bias[n], b1 = bias[n + 1];
                size_t o = (((size_t)b_ * HH + h) * TT + t) * HD + d;
                float p00 = c[mi][ni][0] + b0, p01 = c[mi][ni][1] + b1;
                float p10 = c[mi][ni][2] + b0, p11 = c[mi][ni][3] + b1;
                if (z == 2) {
                    *(float2*)(g_v + o)          = make_float2(p00, p01);
                    *(float2*)(g_v + o + 8 * HD) = make_float2(p10, p11);
                } else {
                    __nv_bfloat16* dhi = (z == 0) ? g_qhi : g_khi;
                    __nv_bfloat16* dlo = (z == 0) ? g_qlo : g_klo;
                    __nv_bfloat16 h00 = __float2bfloat16(p00);
                    __nv_bfloat16 h01 = __float2bfloat16(p01);
                    __nv_bfloat16 h10 = __float2bfloat16(p10);
                    __nv_bfloat16 h11 = __float2bfloat16(p11);
                    *(__nv_bfloat162*)(dhi + o)          = {h00, h01};
                    *(__nv_bfloat162*)(dhi + o + 8 * HD) = {h10, h11};
                    *(__nv_bfloat162*)(dlo + o) =
                        {__float2bfloat16(p00 - __bfloat162float(h00)),
                         __float2bfloat16(p01 - __bfloat162float(h01))};
                    *(__nv_bfloat162*)(dlo + o + 8 * HD) =
                        {__float2bfloat16(p10 - __bfloat162float(h10)),
                         __float2bfloat16(p11 - __bfloat162float(h11))};
                }
            }
        }
    }
}

// ---------------------------------------------------------------------------
// proj_mma: proj[row, r] = q[row,:] . rel_k[r,:]  (bf16x3 MMA)
// grid (512), block 256: 128 rows/block, warp = 16 rows x 144 cols
// ---------------------------------------------------------------------------
#define PJ_Q_HI 0
#define PJ_Q_LO 16384
#define PJ_R_HI 32768
#define PJ_R_LO (32768 + NRP * 128)
#define PJ_SMEM (32768 + 2 * NRP * 128)    // 69632

__global__ __launch_bounds__(256) void proj_mma()
{
    extern __shared__ char smc[];
    int tid = threadIdx.x, lane = tid & 31, wid = tid >> 5;
    int t0 = blockIdx.x * 128;

    uint32_t sQH = smem_u32(smc + PJ_Q_HI);
    uint32_t sQL = smem_u32(smc + PJ_Q_LO);
    uint32_t sRH = smem_u32(smc + PJ_R_HI);
    uint32_t sRL = smem_u32(smc + PJ_R_LO);

    #pragma unroll
    for (int s = 0; s < 4; s++) {
        int vec = tid + s * 256;          // 0..1023
        int r = vec >> 3, g8 = vec & 7;
        uint32_t dst = SWZ128((uint32_t)(r * 128 + g8 * 16));
        size_t src = (size_t)(t0 + r) * HD + g8 * 8;
        *(uint4*)(smc + PJ_Q_HI + dst) = *(const uint4*)(g_qhi + src);
        *(uint4*)(smc + PJ_Q_LO + dst) = *(const uint4*)(g_qlo + src);
    }
    for (int vec = tid; vec < NRP * 8; vec += 256) {
        int r = vec >> 3, g8 = vec & 7;
        uint32_t dst = SWZ128((uint32_t)(r * 128 + g8 * 16));
        size_t src = (size_t)r * HD + g8 * 8;
        *(uint4*)(smc + PJ_R_HI + dst) = *(const uint4*)(g_rkhi + src);
        *(uint4*)(smc + PJ_R_LO + dst) = *(const uint4*)(g_rklo + src);
    }
    __syncthreads();

    float c[9][2][4];
    #pragma unroll
    for (int nf = 0; nf < 9; nf++)
        #pragma unroll
        for (int p = 0; p < 2; p++)
            #pragma unroll
            for (int e = 0; e < 4; e++) c[nf][p][e] = 0.0f;

    #pragma unroll
    for (int ks = 0; ks < 4; ks++) {
        int kbase = ks * 16;
        int akb = kbase + (lane >> 4) * 8;
        uint32_t aad = SWZ128((uint32_t)((wid * 16 + (lane & 15)) * 128 + akb * 2));
        uint32_t ah[4], al[4];
        ldsm4(ah, sQH + aad);
        ldsm4(al, sQL + aad);

        int br_off = (lane & 7) + ((lane >> 4) << 3);
        int bk = kbase + (((lane >> 3) & 1) << 3);
        #pragma unroll
        for (int nf = 0; nf < 9; nf++) {
            uint32_t bad = SWZ128((uint32_t)((nf * 16 + br_off) * 128 + bk * 2));
            uint32_t bh4[4], bl4[4];
            ldsm4(bh4, sRH + bad);
            ldsm4(bl4, sRL + bad);
            mma16816(c[nf][0], ah, bh4);
            mma16816(c[nf][0], ah, bl4);
            mma16816(c[nf][0], al, bh4);
            mma16816(c[nf][1], ah, bh4 + 2);
            mma16816(c[nf][1], ah, bl4 + 2);
            mma16816(c[nf][1], al, bh4 + 2);
        }
    }

    #pragma unroll
    for (int e2 = 0; e2 < 2; e2++) {
        int row = t0 + wid * 16 + (lane >> 2) + e2 * 8;
        float* prow = g_proj + (size_t)row * NR;
        #pragma unroll
        for (int nf = 0; nf < 9; nf++)
            #pragma unroll
            for (int p = 0; p < 2; p++) {
                int col = nf * 16 + p * 8 + (lane & 3) * 2;
                if (col < NR)     prow[col]     = c[nf][p][e2 * 2];
                if (col + 1 < NR) prow[col + 1] = c[nf][p][e2 * 2 + 1];
            }
    }
}

// ---------------------------------------------------------------------------
// s_mma: S[t,k] = (q.k + proj[clip]) * scale  + per-tile max/expsum
// grid (8 ktile, 8 ttile, 64 bh), block 256, warp = 16 rows x 128 cols
// ---------------------------------------------------------------------------
#define SM_Q_HI 0
#define SM_Q_LO 16384
#define SM_K_HI 32768
#define SM_K_LO 49152
#define SM_SMEM 65536

__global__ __launch_bounds__(256) void s_mma()
{
    extern __shared__ char smc[];
    int tid = threadIdx.x, lane = tid & 31, wid = tid >> 5;
    int bh = blockIdx.z;
    int t0 = blockIdx.y * 128, k0 = blockIdx.x * 128;

    uint32_t sQH = smem_u32(smc + SM_Q_HI);
    uint32_t sQL = smem_u32(smc + SM_Q_LO);
    uint32_t sKH = smem_u32(smc + SM_K_HI);
    uint32_t sKL = smem_u32(smc + SM_K_LO);

    size_t qb = (size_t)bh * TT * HD;
    #pragma unroll
    for (int s = 0; s < 4; s++) {
        int vec = tid + s * 256;
        int r = vec >> 3, g8 = vec & 7;
        uint32_t dst = SWZ128((uint32_t)(r * 128 + g8 * 16));
        size_t qs = qb + (size_t)(t0 + r) * HD + g8 * 8;
        size_t kss = qb + (size_t)(k0 + r) * HD + g8 * 8;
        *(uint4*)(smc + SM_Q_HI + dst) = *(const uint4*)(g_qhi + qs);
        *(uint4*)(smc + SM_Q_LO + dst) = *(const uint4*)(g_qlo + qs);
        *(uint4*)(smc + SM_K_HI + dst) = *(const uint4*)(g_khi + kss);
        *(uint4*)(smc + SM_K_LO + dst) = *(const uint4*)(g_klo + kss);
    }
    __syncthreads();

    float c[8][2][4];
    #pragma unroll
    for (int nf = 0; nf < 8; nf++)
        #pragma unroll
        for (int p = 0; p < 2; p++)
            #pragma unroll
            for (int e = 0; e < 4; e++) c[nf][p][e] = 0.0f;

    #pragma unroll
    for (int ks = 0; ks < 4; ks++) {
        int kbase = ks * 16;
        int akb = kbase + (lane >> 4) * 8;
        uint32_t aad = SWZ128((uint32_t)((wid * 16 + (lane & 15)) * 128 + akb * 2));
        uint32_t ah[4], al[4];
        ldsm4(ah, sQH + aad);
        ldsm4(al, sQL + aad);

        int br_off = (lane & 7) + ((lane >> 4) << 3);
        int bk = kbase + (((lane >> 3) & 1) << 3);
        #pragma unroll
        for (int nf = 0; nf < 8; nf++) {
            uint32_t bad = SWZ128((uint32_t)((nf * 16 + br_off) * 128 + bk * 2));
            uint32_t bh4[4], bl4[4];
            ldsm4(bh4, sKH + bad);
            ldsm4(bl4, sKL + bad);
            mma16816(c[nf][0], ah, bh4);
            mma16816(c[nf][0], ah, bl4);
            mma16816(c[nf][0], al, bh4);
            mma16816(c[nf][1], ah, bh4 + 2);
            mma16816(c[nf][1], ah, bl4 + 2);
            mma16816(c[nf][1], al, bh4 + 2);
        }
    }

    const float scale = 0.044194173824159216f;
    #pragma unroll
    for (int e2 = 0; e2 < 2; e2++) {
        int trow = t0 + wid * 16 + (lane >> 2) + e2 * 8;
        const float* prow = g_proj + ((size_t)bh * TT + trow) * NR;
        float mx = -1e30f;
        #pragma unroll
        for (int nf = 0; nf < 8; nf++)
            #pragma unroll
            for (int p = 0; p < 2; p++)
                #pragma unroll
                for (int j = 0; j < 2; j++) {
                    int kg = k0 + nf * 16 + p * 8 + (lane & 3) * 2 + j;
                    int dist = kg - trow;
                    dist = dist < -MAXR ? -MAXR : (dist > MAXR ? MAXR : dist);
                    float v = (c[nf][p][e2 * 2 + j] + prow[dist + MAXR]) * scale;
                    c[nf][p][e2 * 2 + j] = v;
                    mx = fmaxf(mx, v);
                }
        mx = fmaxf(mx, __shfl_xor_sync(0xffffffffu, mx, 1));
        mx = fmaxf(mx, __shfl_xor_sync(0xffffffffu, mx, 2));
        float es = 0.0f;
        float* srow = g_S + ((size_t)bh * TT + trow) * TT + k0;
        #pragma unroll
        for (int nf = 0; nf < 8; nf++)
            #pragma unroll
            for (int p = 0; p < 2; p++) {
                float v0 = c[nf][p][e2 * 2], v1 = c[nf][p][e2 * 2 + 1];
                es += __expf(v0 - mx) + __expf(v1 - mx);
                *(float2*)(srow + nf * 16 + p * 8 + (lane & 3) * 2) =
                    make_float2(v0, v1);
            }
        es += __shfl_xor_sync(0xffffffffu, es, 1);
        es += __shfl_xor_sync(0xffffffffu, es, 2);
        if ((lane & 3) == 0) {
            size_t ob = ((size_t)bh * 8 + blockIdx.x) * TT + trow;
            g_tm[ob] = mx;
            g_ts[ob] = es;
        }
    }
}

// ---------------------------------------------------------------------------
__global__ __launch_bounds__(1024) void reduce_ml()
{
    int bh = blockIdx.x;
    int t  = threadIdx.x;
    float tm[8], ts[8];
    #pragma unroll
    for (int i = 0; i < 8; i++) {
        size_t ob = ((size_t)bh * 8 + i) * TT + t;
        tm[i] = g_tm[ob];
        ts[i] = g_ts[ob];
    }
    float m = tm[0];
    #pragma unroll
    for (int i = 1; i < 8; i++) m = fmaxf(m, tm[i]);
    float l = 0.0f;
    #pragma unroll
    for (int i = 0; i < 8; i++) l += ts[i] * __expf(tm[i] - m);
    g_m[(size_t)bh * TT + t] = m;
    g_l[(size_t)bh * TT + t] = l;
}

// ---------------------------------------------------------------------------
// PV fused exp + band + rel_v epilogue (unchanged)
// ---------------------------------------------------------------------------
#define PV_PS    0
#define PV_VS    2064
#define PV_BAND  3088
#define PV_RELV  20496
#define PV_M     29264
#define PV_L     29392
#define PV_PLO   29520
#define PV_FLOATS 29648
#define PV_SMEM_BYTES (PV_FLOATS * 4)

__global__ __launch_bounds__(256) void pv_kernel(const float* __restrict__ rel_v)
{
    extern __shared__ float sm[];
    float* Ps    = sm + PV_PS;
    float* Vs    = sm + PV_VS;
    float* band  = sm + PV_BAND;
    float* rvs   = sm + PV_RELV;
    float* m_s   = sm + PV_M;
    float* l_s   = sm + PV_L;
    float* plo_s = sm + PV_PLO;

    int bh = blockIdx.y;
    int t0 = blockIdx.x * 128;
    int tid = threadIdx.x;
    int tx = tid & 15, ty = tid >> 4;

    for (int idx = tid; idx < 128 * 136; idx += 256) band[idx] = 0.0f;
    if (tid < 128) {
        m_s[tid] = g_m[(size_t)bh * TT + t0 + tid];
        l_s[tid] = g_l[(size_t)bh * TT + t0 + tid];
    }
    __syncthreads();

    float c[8][4];
    #pragma unroll
    for (int i = 0; i < 8; i++)
        #pragma unroll
        for (int j = 0; j < 4; j++) c[i][j] = 0.0f;

    float plo_a = 0.0f, plo_b = 0.0f;

    const float* pbase = g_S + (size_t)bh * TT * TT;
    const float* vbase = g_v + (size_t)bh * TT * HD;

    for (int k0 = 0; k0 < TT; k0 += 16) {
        #pragma unroll
        for (int half = 0; half < 2; half++) {
            int n = tid + half * 256;
            int trow = n >> 2, c4 = (n & 3) * 4;
            int tg = t0 + trow;
            float mrow = m_s[trow];
            float4 a4 = *(const float4*)(pbase + (size_t)tg * TT + k0 + c4);
            float pv0 = __expf(a4.x - mrow);
            float pv1 = __expf(a4.y - mrow);
            float pv2 = __expf(a4.z - mrow);
            float pv3 = __expf(a4.w - mrow);
            Ps[(c4 + 0) * 129 + trow] = pv0;
            Ps[(c4 + 1) * 129 + trow] = pv1;
            Ps[(c4 + 2) * 129 + trow] = pv2;
            Ps[(c4 + 3) * 129 + trow] = pv3;
            float pl = 0.0f;
            #pragma unroll
            for (int j = 0; j < 4; j++) {
                float pv = (j == 0) ? pv0 : (j == 1) ? pv1 : (j == 2) ? pv2 : pv3;
                int d = (k0 + c4 + j) - tg;
                if ((unsigned)(d + 67) <= 134u)
                    band[trow * 136 + d + 67] = pv;
                else if (d <= -MAXR)
                    pl += pv;
            }
            if (half == 0) plo_a += pl; else plo_b += pl;
        }
        {
            int krow = tid >> 4, c4v = (tid & 15) * 4;
            *(float4*)(Vs + krow * 64 + c4v) =
                *(const float4*)(vbase + (size_t)(k0 + krow) * HD + c4v);
        }
        __syncthreads();
        #pragma unroll
        for (int kk = 0; kk < 16; kk++) {
            float a[8], b[4];
            #pragma unroll
            for (int i = 0; i < 8; i++) a[i] = Ps[kk * 129 + ty * 8 + i];
            #pragma unroll
            for (int j = 0; j < 4; j++) b[j] = Vs[kk * 64 + tx * 4 + j];
            #pragma unroll
            for (int i = 0; i < 8; i++)
                #pragma unroll
                for (int j = 0; j < 4; j++) c[i][j] += a[i] * b[j];
        }
        __syncthreads();
    }

    plo_a += __shfl_xor_sync(0xffffffffu, plo_a, 1);
    plo_a += __shfl_xor_sync(0xffffffffu, plo_a, 2);
    plo_b += __shfl_xor_sync(0xffffffffu, plo_b, 1);
    plo_b += __shfl_xor_sync(0xffffffffu, plo_b, 2);
    if ((tid & 3) == 0) {
        plo_s[tid >> 2]        = plo_a;
        plo_s[64 + (tid >> 2)] = plo_b;
    }
    for (int idx = tid * 4; idx < NR * 64; idx += 256 * 4)
        *(float4*)(rvs + idx) = *(const float4*)(rel_v + idx);
    __syncthreads();

    float intu[8];
    #pragma unroll
    for (int i = 0; i < 8; i++) intu[i] = 0.0f;

    for (int r = 1; r <= 135; r++) {
        float rv[4];
        #pragma unroll
        for (int j = 0; j < 4; j++) rv[j] = rvs[r * 64 + tx * 4 + j];
        #pragma unroll
        for (int i = 0; i < 8; i++) {
            float sv = band[(ty * 8 + i) * 136 + (r - 1)];
            intu[i] += sv;
            #pragma unroll
            for (int j = 0; j < 4; j++) c[i][j] += sv * rv[j];
        }
    }

    int b_ = bh >> 3, h = bh & 7;
    #pragma unroll
    for (int i = 0; i < 8; i++) {
        int row = ty * 8 + i;
        float plo = plo_s[row];
        float lr  = l_s[row];
        float phi = lr - plo - intu[i];
        float inv = 1.0f / lr;
        float o[4];
        #pragma unroll
        for (int j = 0; j < 4; j++) {
            float w = c[i][j] + plo * rvs[tx * 4 + j]
                              + phi * rvs[136 * 64 + tx * 4 + j];
            o[j] = w * inv;
        }
        int t = t0 + row;
        *(float4*)(g_y + ((size_t)(b_ * TT + t)) * CC + h * HD + tx * 4) =
            make_float4(o[0], o[1], o[2], o[3]);
    }
}

// ---------------------------------------------------------------------------
extern "C" void kernel_launch(void* const* d_in, const int* in_sizes, int n_in,
                              void* d_out, int out_size)
{
    const float* x     = (const float*)d_in[0];
    const float* Wq    = (const float*)d_in[1];
    const float* bq    = (const float*)d_in[2];
    const float* Wk    = (const float*)d_in[3];
    const float* bk    = (const float*)d_in[4];
    const float* Wv    = (const float*)d_in[5];
    const float* bv    = (const float*)d_in[6];
    const float* Wo    = (const float*)d_in[7];
    const float* bo    = (const float*)d_in[8];
    const float* rel_k = (const float*)d_in[9];
    const float* rel_v = (const float*)d_in[10];
    float* out = (float*)d_out;

    cudaFuncSetAttribute(pv_kernel, cudaFuncAttributeMaxDynamicSharedMemorySize,
                         PV_SMEM_BYTES);
    cudaFuncSetAttribute(gemm_mma, cudaFuncAttributeMaxDynamicSharedMemorySize,
                         GT_SMEM);
    cudaFuncSetAttribute(proj_mma, cudaFuncAttributeMaxDynamicSharedMemorySize,
                         PJ_SMEM);
    cudaFuncSetAttribute(s_mma, cudaFuncAttributeMaxDynamicSharedMemorySize,
                         SM_SMEM);

    conv_w<<<1024, 512>>>(Wq, Wk, Wv, Wo, bq, bk, bv, bo, rel_k);
    conv_split_x<<<1024, 512>>>(x, MM * CC / 4);
    gemm_mma<<<dim3(12, 64), 256, GT_SMEM>>>(nullptr, 1);
    proj_mma<<<512, 256, PJ_SMEM>>>();
    s_mma<<<dim3(8, 8, 64), 256, SM_SMEM>>>();
    reduce_ml<<<64, 1024>>>();
    pv_kernel<<<dim3(8, 64), 256, PV_SMEM_BYTES>>>(rel_v);
    conv_split_y<<<1024, 512>>>(MM * CC / 4);
    gemm_mma<<<dim3(4, 64), 256, GT_SMEM>>>(out, 0);
}

// round 8
// speedup vs baseline: 2.1498x; 1.2484x over previous
#include <cuda_runtime.h>
#include <cuda_bf16.h>
#include <cstdint>

// Problem constants
#define BB   8
#define TT   1024
#define CC   512
#define HH   8
#define HD   64
#define NR   137
#define MAXR 68
#define BH   64
#define MM   8192
#define NRP  144

// ---------------------------------------------------------------------------
// Scratch (device globals)
// ---------------------------------------------------------------------------
static __device__ float g_v[BH * TT * HD];
static __device__ float g_proj[BH * TT * NR];
static __device__ float g_S[67108864];
static __device__ float g_tm[BH * 8 * TT];
static __device__ float g_ts[BH * 8 * TT];
static __device__ float g_m[BH * TT];
static __device__ float g_l[BH * TT];

static __device__ __nv_bfloat16 g_qhi[BH * TT * HD];
static __device__ __nv_bfloat16 g_qlo[BH * TT * HD];
static __device__ __nv_bfloat16 g_khi[BH * TT * HD];
static __device__ __nv_bfloat16 g_klo[BH * TT * HD];
static __device__ __nv_bfloat16 g_vthi[BH * HD * TT];   // [bh][d][t]
static __device__ __nv_bfloat16 g_vtlo[BH * HD * TT];
static __device__ __nv_bfloat16 g_rkhi[NRP * HD];
static __device__ __nv_bfloat16 g_rklo[NRP * HD];

static __device__ __nv_bfloat16 g_xhi[MM * CC];
static __device__ __nv_bfloat16 g_xlo[MM * CC];
static __device__ __nv_bfloat16 g_yhi[MM * CC];
static __device__ __nv_bfloat16 g_ylo[MM * CC];
static __device__ __nv_bfloat16 g_wthi[4 * CC * CC];
static __device__ __nv_bfloat16 g_wtlo[4 * CC * CC];
static __device__ float g_bias[4 * CC];

// ---------------------------------------------------------------------------
// warp-MMA helpers
// ---------------------------------------------------------------------------
__device__ __forceinline__ uint32_t smem_u32(const void* p) {
    uint32_t a;
    asm("{ .reg .u64 t; cvta.to.shared.u64 t, %1; cvt.u32.u64 %0, t; }"
        : "=r"(a) : "l"(p));
    return a;
}
__device__ __forceinline__ void ldsm4(uint32_t* r, uint32_t addr) {
    asm volatile("ldmatrix.sync.aligned.m8n8.x4.shared.b16 {%0,%1,%2,%3}, [%4];"
        : "=r"(r[0]), "=r"(r[1]), "=r"(r[2]), "=r"(r[3]) : "r"(addr));
}
__device__ __forceinline__ void ldsm2(uint32_t* r, uint32_t addr) {
    asm volatile("ldmatrix.sync.aligned.m8n8.x2.shared.b16 {%0,%1}, [%2];"
        : "=r"(r[0]), "=r"(r[1]) : "r"(addr));
}
__device__ __forceinline__ void mma16816(float* c, const uint32_t* a, const uint32_t* b) {
    asm volatile(
        "mma.sync.aligned.m16n8k16.row.col.f32.bf16.bf16.f32 "
        "{%0,%1,%2,%3}, {%4,%5,%6,%7}, {%8,%9}, {%0,%1,%2,%3};"
        : "+f"(c[0]), "+f"(c[1]), "+f"(c[2]), "+f"(c[3])
        : "r"(a[0]), "r"(a[1]), "r"(a[2]), "r"(a[3]), "r"(b[0]), "r"(b[1]));
}
#define SWZ128(b) ((b) ^ (((b) >> 3) & 0x70))

__device__ __forceinline__ uint32_t pack_bf2(__nv_bfloat16 a, __nv_bfloat16 b) {
    __nv_bfloat162 t = {a, b};
    return *(uint32_t*)&t;
}

// ---------------------------------------------------------------------------
// conversion kernels
// ---------------------------------------------------------------------------
__global__ __launch_bounds__(512) void conv_split_x(const float* __restrict__ src, int n4)
{
    for (int i = blockIdx.x * blockDim.x + threadIdx.x; i < n4;
         i += gridDim.x * blockDim.x) {
        float4 v = *(const float4*)(src + (size_t)i * 4);
        float vv[4] = {v.x, v.y, v.z, v.w};
        #pragma unroll
        for (int j = 0; j < 4; j++) {
            __nv_bfloat16 h = __float2bfloat16(vv[j]);
            g_xhi[(size_t)i * 4 + j] = h;
            g_xlo[(size_t)i * 4 + j] = __float2bfloat16(vv[j] - __bfloat162float(h));
        }
    }
}

__global__ __launch_bounds__(512) void conv_w(
    const float* __restrict__ Wq, const float* __restrict__ Wk,
    const float* __restrict__ Wv, const float* __restrict__ Wo,
    const float* __restrict__ bq, const float* __restrict__ bk,
    const float* __restrict__ bv, const float* __restrict__ bo,
    const float* __restrict__ rel_k)
{
    int gid = blockIdx.x * blockDim.x + threadIdx.x;
    int nth = gridDim.x * blockDim.x;
    for (int idx = gid; idx < 4 * CC * CC; idx += nth) {
        int z = idx >> 18;
        int rem = idx & (CC * CC - 1);
        int k = rem >> 9, n = rem & 511;
        const float* W = (z == 0) ? Wq : (z == 1) ? Wk : (z == 2) ? Wv : Wo;
        float v = W[k * CC + n];
        __nv_bfloat16 h = __float2bfloat16(v);
        size_t dst = (size_t)z * CC * CC + (size_t)n * CC + k;
        g_wthi[dst] = h;
        g_wtlo[dst] = __float2bfloat16(v - __bfloat162float(h));
    }
    for (int idx = gid; idx < NRP * HD; idx += nth) {
        int r = idx >> 6, d = idx & 63;
        float v = (r < NR) ? rel_k[r * HD + d] : 0.0f;
        __nv_bfloat16 h = __float2bfloat16(v);
        g_rkhi[idx] = h;
        g_rklo[idx] = __float2bfloat16(v - __bfloat162float(h));
    }
    if (gid < 4 * CC) {
        int z = gid >> 9, n = gid & 511;
        const float* bsrc = (z == 0) ? bq : (z == 1) ? bk : (z == 2) ? bv : bo;
        g_bias[gid] = bsrc[n];
    }
}

// v[bh][t][d] -> vt hi/lo [bh][d][t], tiles of 64 t
__global__ __launch_bounds__(256) void conv_vt()
{
    __shared__ float tile[64][65];
    int bh = blockIdx.y, t0 = blockIdx.x * 64;
    int tid = threadIdx.x;
    #pragma unroll
    for (int s = 0; s < 4; s++) {
        int vec = tid + s * 256;
        int r = vec >> 4, c4 = (vec & 15) * 4;
        float4 v = *(const float4*)(g_v + ((size_t)bh * TT + t0 + r) * HD + c4);
        tile[r][c4 + 0] = v.x;
        tile[r][c4 + 1] = v.y;
        tile[r][c4 + 2] = v.z;
        tile[r][c4 + 3] = v.w;
    }
    __syncthreads();
    int d = tid >> 2, ts = (tid & 3) * 16;
    size_t ob = ((size_t)bh * HD + d) * TT + t0 + ts;
    uint32_t hi[8], lo[8];
    #pragma unroll
    for (int j = 0; j < 8; j++) {
        float v0 = tile[ts + j * 2][d];
        float v1 = tile[ts + j * 2 + 1][d];
        __nv_bfloat16 h0 = __float2bfloat16(v0);
        __nv_bfloat16 h1 = __float2bfloat16(v1);
        hi[j] = pack_bf2(h0, h1);
        lo[j] = pack_bf2(__float2bfloat16(v0 - __bfloat162float(h0)),
                         __float2bfloat16(v1 - __bfloat162float(h1)));
    }
    *(uint4*)(g_vthi + ob)     = make_uint4(hi[0], hi[1], hi[2], hi[3]);
    *(uint4*)(g_vthi + ob + 8) = make_uint4(hi[4], hi[5], hi[6], hi[7]);
    *(uint4*)(g_vtlo + ob)     = make_uint4(lo[0], lo[1], lo[2], lo[3]);
    *(uint4*)(g_vtlo + ob + 8) = make_uint4(lo[4], lo[5], lo[6], lo[7]);
}

// ---------------------------------------------------------------------------
// bf16x3 warp-MMA GEMM (qkv / output projection)
// ---------------------------------------------------------------------------
#define GT_A_HI 0
#define GT_A_LO 16384
#define GT_B_HI 32768
#define GT_B_LO 49152
#define GT_SMEM 65536

__global__ __launch_bounds__(256, 2) void gemm_mma(float* __restrict__ outp, int mode)
{
    extern __shared__ char smc[];
    const __nv_bfloat16 *Ahi, *Alo, *Bhi, *Blo;
    const float* bias;
    if (mode == 1) {
        Ahi = g_xhi; Alo = g_xlo; Bhi = g_wthi; Blo = g_wtlo; bias = g_bias;
    } else {
        Ahi = g_yhi; Alo = g_ylo;
        Bhi = g_wthi + 3 * CC * CC; Blo = g_wtlo + 3 * CC * CC;
        bias = g_bias + 3 * CC;
    }

    int tid = threadIdx.x, lane = tid & 31, wid = tid >> 5;
    int wm = wid >> 2, wn = wid & 3;
    int row0 = blockIdx.y * 128, col0 = blockIdx.x * 128;

    uint32_t sA_hi = smem_u32(smc + GT_A_HI);
    uint32_t sA_lo = smem_u32(smc + GT_A_LO);
    uint32_t sB_hi = smem_u32(smc + GT_B_HI);
    uint32_t sB_lo = smem_u32(smc + GT_B_LO);

    float c[4][4][4];
    #pragma unroll
    for (int mi = 0; mi < 4; mi++)
        #pragma unroll
        for (int ni = 0; ni < 4; ni++)
            #pragma unroll
            for (int e = 0; e < 4; e++) c[mi][ni][e] = 0.0f;

    for (int kc = 0; kc < 8; kc++) {
        int k0 = kc * 64;
        __syncthreads();
        #pragma unroll
        for (int s = 0; s < 4; s++) {
            int vec = tid + s * 256;
            int r = vec >> 3, v8 = vec & 7;
            uint32_t dst = SWZ128((uint32_t)(r * 128 + v8 * 16));
            size_t asrc = (size_t)(row0 + r) * CC + k0 + v8 * 8;
            size_t bsrc = (size_t)(col0 + r) * CC + k0 + v8 * 8;
            *(uint4*)(smc + GT_A_HI + dst) = *(const uint4*)(Ahi + asrc);
            *(uint4*)(smc + GT_A_LO + dst) = *(const uint4*)(Alo + asrc);
            *(uint4*)(smc + GT_B_HI + dst) = *(const uint4*)(Bhi + bsrc);
            *(uint4*)(smc + GT_B_LO + dst) = *(const uint4*)(Blo + bsrc);
        }
        __syncthreads();

        #pragma unroll
        for (int ks = 0; ks < 4; ks++) {
            int kbase = ks * 16;
            int lp = lane & 15;
            int bkb = kbase + (lp >> 3) * 8;
            uint32_t bh[4][2], bl[4][2];
            #pragma unroll
            for (int ni = 0; ni < 4; ni++) {
                int nloc = wn * 32 + ni * 8 + (lp & 7);
                uint32_t ad = SWZ128((uint32_t)(nloc * 128 + bkb * 2));
                ldsm2(bh[ni], sB_hi + ad);
                ldsm2(bl[ni], sB_lo + ad);
            }
            int akb = kbase + (lane >> 4) * 8;
            int mlp = lane & 15;
            #pragma unroll
            for (int mi = 0; mi < 4; mi++) {
                int mloc = wm * 64 + mi * 16 + mlp;
                uint32_t ad = SWZ128((uint32_t)(mloc * 128 + akb * 2));
                uint32_t ah[4], al[4];
                ldsm4(ah, sA_hi + ad);
                ldsm4(al, sA_lo + ad);
                #pragma unroll
                for (int ni = 0; ni < 4; ni++) {
                    mma16816(c[mi][ni], ah, bh[ni]);
                    mma16816(c[mi][ni], ah, bl[ni]);
                    mma16816(c[mi][ni], al, bh[ni]);
                }
            }
        }
    }

    int r_base = row0 + wm * 64 + (lane >> 2);
    int n_base = col0 + wn * 32 + (lane & 3) * 2;

    if (mode == 0) {
        #pragma unroll
        for (int mi = 0; mi < 4; mi++) {
            int r = r_base + mi * 16;
            #pragma unroll
            for (int ni = 0; ni < 4; ni++) {
                int n = n_base + ni * 8;
                float b0 = bias[n], b1 = bias[n + 1];
                float2 v0 = make_float2(c[mi][ni][0] + b0, c[mi][ni][1] + b1);
                float2 v1 = make_float2(c[mi][ni][2] + b0, c[mi][ni][3] + b1);
                *(float2*)(outp + (size_t)r * CC + n)       = v0;
                *(float2*)(outp + (size_t)(r + 8) * CC + n) = v1;
            }
        }
    } else {
        int z = col0 >> 9;
        #pragma unroll
        for (int mi = 0; mi < 4; mi++) {
            int r = r_base + mi * 16;
            int b_ = r >> 10, t = r & (TT - 1);
            #pragma unroll
            for (int ni = 0; ni < 4; ni++) {
                int n = n_base + ni * 8;
                int nn = n & 511;
                int h = nn >> 6, d = nn & 63;
                float b0 = bias[n], b1 = bias[n + 1];
                size_t o = (((size_t)b_ * HH + h) * TT + t) * HD + d;
                float p00 = c[mi][ni][0] + b0, p01 = c[mi][ni][1] + b1;
                float p10 = c[mi][ni][2] + b0, p11 = c[mi][ni][3] + b1;
                if (z == 2) {
                    *(float2*)(g_v + o)          = make_float2(p00, p01);
                    *(float2*)(g_v + o + 8 * HD) = make_float2(p10, p11);
                } else {
                    __nv_bfloat16* dhi = (z == 0) ? g_qhi : g_khi;
                    __nv_bfloat16* dlo = (z == 0) ? g_qlo : g_klo;
                    __nv_bfloat16 h00 = __float2bfloat16(p00);
                    __nv_bfloat16 h01 = __float2bfloat16(p01);
                    __nv_bfloat16 h10 = __float2bfloat16(p10);
                    __nv_bfloat16 h11 = __float2bfloat16(p11);
                    *(uint32_t*)(dhi + o)          = pack_bf2(h00, h01);
                    *(uint32_t*)(dhi + o + 8 * HD) = pack_bf2(h10, h11);
                    *(uint32_t*)(dlo + o) =
                        pack_bf2(__float2bfloat16(p00 - __bfloat162float(h00)),
                                 __float2bfloat16(p01 - __bfloat162float(h01)));
                    *(uint32_t*)(dlo + o + 8 * HD) =
                        pack_bf2(__float2bfloat16(p10 - __bfloat162float(h10)),
                                 __float2bfloat16(p11 - __bfloat162float(h11)));
                }
            }
        }
    }
}

// ---------------------------------------------------------------------------
// proj_mma
// ---------------------------------------------------------------------------
#define PJ_Q_HI 0
#define PJ_Q_LO 16384
#define PJ_R_HI 32768
#define PJ_R_LO (32768 + NRP * 128)
#define PJ_SMEM (32768 + 2 * NRP * 128)

__global__ __launch_bounds__(256) void proj_mma()
{
    extern __shared__ char smc[];
    int tid = threadIdx.x, lane = tid & 31, wid = tid >> 5;
    int t0 = blockIdx.x * 128;

    uint32_t sQH = smem_u32(smc + PJ_Q_HI);
    uint32_t sQL = smem_u32(smc + PJ_Q_LO);
    uint32_t sRH = smem_u32(smc + PJ_R_HI);
    uint32_t sRL = smem_u32(smc + PJ_R_LO);

    #pragma unroll
    for (int s = 0; s < 4; s++) {
        int vec = tid + s * 256;
        int r = vec >> 3, g8 = vec & 7;
        uint32_t dst = SWZ128((uint32_t)(r * 128 + g8 * 16));
        size_t src = (size_t)(t0 + r) * HD + g8 * 8;
        *(uint4*)(smc + PJ_Q_HI + dst) = *(const uint4*)(g_qhi + src);
        *(uint4*)(smc + PJ_Q_LO + dst) = *(const uint4*)(g_qlo + src);
    }
    for (int vec = tid; vec < NRP * 8; vec += 256) {
        int r = vec >> 3, g8 = vec & 7;
        uint32_t dst = SWZ128((uint32_t)(r * 128 + g8 * 16));
        size_t src = (size_t)r * HD + g8 * 8;
        *(uint4*)(smc + PJ_R_HI + dst) = *(const uint4*)(g_rkhi + src);
        *(uint4*)(smc + PJ_R_LO + dst) = *(const uint4*)(g_rklo + src);
    }
    __syncthreads();

    float c[9][2][4];
    #pragma unroll
    for (int nf = 0; nf < 9; nf++)
        #pragma unroll
        for (int p = 0; p < 2; p++)
            #pragma unroll
            for (int e = 0; e < 4; e++) c[nf][p][e] = 0.0f;

    #pragma unroll
    for (int ks = 0; ks < 4; ks++) {
        int kbase = ks * 16;
        int akb = kbase + (lane >> 4) * 8;
        uint32_t aad = SWZ128((uint32_t)((wid * 16 + (lane & 15)) * 128 + akb * 2));
        uint32_t ah[4], al[4];
        ldsm4(ah, sQH + aad);
        ldsm4(al, sQL + aad);

        int br_off = (lane & 7) + ((lane >> 4) << 3);
        int bk = kbase + (((lane >> 3) & 1) << 3);
        #pragma unroll
        for (int nf = 0; nf < 9; nf++) {
            uint32_t bad = SWZ128((uint32_t)((nf * 16 + br_off) * 128 + bk * 2));
            uint32_t bh4[4], bl4[4];
            ldsm4(bh4, sRH + bad);
            ldsm4(bl4, sRL + bad);
            mma16816(c[nf][0], ah, bh4);
            mma16816(c[nf][0], ah, bl4);
            mma16816(c[nf][0], al, bh4);
            mma16816(c[nf][1], ah, bh4 + 2);
            mma16816(c[nf][1], ah, bl4 + 2);
            mma16816(c[nf][1], al, bh4 + 2);
        }
    }

    #pragma unroll
    for (int e2 = 0; e2 < 2; e2++) {
        int row = t0 + wid * 16 + (lane >> 2) + e2 * 8;
        float* prow = g_proj + (size_t)row * NR;
        #pragma unroll
        for (int nf = 0; nf < 9; nf++)
            #pragma unroll
            for (int p = 0; p < 2; p++) {
                int col = nf * 16 + p * 8 + (lane & 3) * 2;
                if (col < NR)     prow[col]     = c[nf][p][e2 * 2];
                if (col + 1 < NR) prow[col + 1] = c[nf][p][e2 * 2 + 1];
            }
    }
}

// ---------------------------------------------------------------------------
// s_mma: S[t,k] + per-tile max/expsum
// ---------------------------------------------------------------------------
#define SM_Q_HI 0
#define SM_Q_LO 16384
#define SM_K_HI 32768
#define SM_K_LO 49152
#define SM_SMEM 65536

__global__ __launch_bounds__(256) void s_mma()
{
    extern __shared__ char smc[];
    int tid = threadIdx.x, lane = tid & 31, wid = tid >> 5;
    int bh = blockIdx.z;
    int t0 = blockIdx.y * 128, k0 = blockIdx.x * 128;

    uint32_t sQH = smem_u32(smc + SM_Q_HI);
    uint32_t sQL = smem_u32(smc + SM_Q_LO);
    uint32_t sKH = smem_u32(smc + SM_K_HI);
    uint32_t sKL = smem_u32(smc + SM_K_LO);

    size_t qb = (size_t)bh * TT * HD;
    #pragma unroll
    for (int s = 0; s < 4; s++) {
        int vec = tid + s * 256;
        int r = vec >> 3, g8 = vec & 7;
        uint32_t dst = SWZ128((uint32_t)(r * 128 + g8 * 16));
        size_t qs = qb + (size_t)(t0 + r) * HD + g8 * 8;
        size_t kss = qb + (size_t)(k0 + r) * HD + g8 * 8;
        *(uint4*)(smc + SM_Q_HI + dst) = *(const uint4*)(g_qhi + qs);
        *(uint4*)(smc + SM_Q_LO + dst) = *(const uint4*)(g_qlo + qs);
        *(uint4*)(smc + SM_K_HI + dst) = *(const uint4*)(g_khi + kss);
        *(uint4*)(smc + SM_K_LO + dst) = *(const uint4*)(g_klo + kss);
    }
    __syncthreads();

    float c[8][2][4];
    #pragma unroll
    for (int nf = 0; nf < 8; nf++)
        #pragma unroll
        for (int p = 0; p < 2; p++)
            #pragma unroll
            for (int e = 0; e < 4; e++) c[nf][p][e] = 0.0f;

    #pragma unroll
    for (int ks = 0; ks < 4; ks++) {
        int kbase = ks * 16;
        int akb = kbase + (lane >> 4) * 8;
        uint32_t aad = SWZ128((uint32_t)((wid * 16 + (lane & 15)) * 128 + akb * 2));
        uint32_t ah[4], al[4];
        ldsm4(ah, sQH + aad);
        ldsm4(al, sQL + aad);

        int br_off = (lane & 7) + ((lane >> 4) << 3);
        int bk = kbase + (((lane >> 3) & 1) << 3);
        #pragma unroll
        for (int nf = 0; nf < 8; nf++) {
            uint32_t bad = SWZ128((uint32_t)((nf * 16 + br_off) * 128 + bk * 2));
            uint32_t bh4[4], bl4[4];
            ldsm4(bh4, sKH + bad);
            ldsm4(bl4, sKL + bad);
            mma16816(c[nf][0], ah, bh4);
            mma16816(c[nf][0], ah, bl4);
            mma16816(c[nf][0], al, bh4);
            mma16816(c[nf][1], ah, bh4 + 2);
            mma16816(c[nf][1], ah, bl4 + 2);
            mma16816(c[nf][1], al, bh4 + 2);
        }
    }

    const float scale = 0.044194173824159216f;
    #pragma unroll
    for (int e2 = 0; e2 < 2; e2++) {
        int trow = t0 + wid * 16 + (lane >> 2) + e2 * 8;
        const float* prow = g_proj + ((size_t)bh * TT + trow) * NR;
        float mx = -1e30f;
        #pragma unroll
        for (int nf = 0; nf < 8; nf++)
            #pragma unroll
            for (int p = 0; p < 2; p++)
                #pragma unroll
                for (int j = 0; j < 2; j++) {
                    int kg = k0 + nf * 16 + p * 8 + (lane & 3) * 2 + j;
                    int dist = kg - trow;
                    dist = dist < -MAXR ? -MAXR : (dist > MAXR ? MAXR : dist);
                    float v = (c[nf][p][e2 * 2 + j] + prow[dist + MAXR]) * scale;
                    c[nf][p][e2 * 2 + j] = v;
                    mx = fmaxf(mx, v);
                }
        mx = fmaxf(mx, __shfl_xor_sync(0xffffffffu, mx, 1));
        mx = fmaxf(mx, __shfl_xor_sync(0xffffffffu, mx, 2));
        float es = 0.0f;
        float* srow = g_S + ((size_t)bh * TT + trow) * TT + k0;
        #pragma unroll
        for (int nf = 0; nf < 8; nf++)
            #pragma unroll
            for (int p = 0; p < 2; p++) {
                float v0 = c[nf][p][e2 * 2], v1 = c[nf][p][e2 * 2 + 1];
                es += __expf(v0 - mx) + __expf(v1 - mx);
                *(float2*)(srow + nf * 16 + p * 8 + (lane & 3) * 2) =
                    make_float2(v0, v1);
            }
        es += __shfl_xor_sync(0xffffffffu, es, 1);
        es += __shfl_xor_sync(0xffffffffu, es, 2);
        if ((lane & 3) == 0) {
            size_t ob = ((size_t)bh * 8 + blockIdx.x) * TT + trow;
            g_tm[ob] = mx;
            g_ts[ob] = es;
        }
    }
}

// ---------------------------------------------------------------------------
__global__ __launch_bounds__(1024) void reduce_ml()
{
    int bh = blockIdx.x;
    int t  = threadIdx.x;
    float tm[8], ts[8];
    #pragma unroll
    for (int i = 0; i < 8; i++) {
        size_t ob = ((size_t)bh * 8 + i) * TT + t;
        tm[i] = g_tm[ob];
        ts[i] = g_ts[ob];
    }
    float m = tm[0];
    #pragma unroll
    for (int i = 1; i < 8; i++) m = fmaxf(m, tm[i]);
    float l = 0.0f;
    #pragma unroll
    for (int i = 0; i < 8; i++) l += ts[i] * __expf(tm[i] - m);
    g_m[(size_t)bh * TT + t] = m;
    g_l[(size_t)bh * TT + t] = l;
}

// ---------------------------------------------------------------------------
// pv_mma: p = exp(S - m) -> bf16 hi/lo -> MMA vs Vt; band + rel_v epilogue;
// writes y as bf16 hi/lo. grid (8, 64), block 256.
// ---------------------------------------------------------------------------
#define PV2_PHI  0
#define PV2_PLO  16384
#define PV2_VHI  32768
#define PV2_VLO  40960
#define PV2_BAND 49152                       // 128*136*4 = 69632
#define PV2_M    118784
#define PV2_L    119296
#define PV2_PS   119808
#define PV2_SMEM 120320

__global__ __launch_bounds__(256) void pv_mma(const float* __restrict__ rel_v)
{
    extern __shared__ char smc[];
    float* band = (float*)(smc + PV2_BAND);
    float* m_s  = (float*)(smc + PV2_M);
    float* l_s  = (float*)(smc + PV2_L);
    float* ps_s = (float*)(smc + PV2_PS);
    float* rvs  = (float*)(smc);             // epilogue alias of P/V tiles

    int tid = threadIdx.x, lane = tid & 31, wid = tid >> 5;
    int bh = blockIdx.y, t0 = blockIdx.x * 128;

    uint32_t uPHI = smem_u32(smc + PV2_PHI);
    uint32_t uPLO = smem_u32(smc + PV2_PLO);
    uint32_t uVHI = smem_u32(smc + PV2_VHI);
    uint32_t uVLO = smem_u32(smc + PV2_VLO);

    for (int idx = tid; idx < 128 * 136; idx += 256) band[idx] = 0.0f;
    if (tid < 128) {
        m_s[tid] = g_m[(size_t)bh * TT + t0 + tid];
        l_s[tid] = g_l[(size_t)bh * TT + t0 + tid];
    }
    __syncthreads();

    int lrow = tid >> 1;                     // fixed row for load phase
    int lcs  = (tid & 1) * 32;
    float mrow = m_s[lrow];
    int tg = t0 + lrow;
    float plo = 0.0f;

    float c[4][2][4];
    #pragma unroll
    for (int nf = 0; nf < 4; nf++)
        #pragma unroll
        for (int p = 0; p < 2; p++)
            #pragma unroll
            for (int e = 0; e < 4; e++) c[nf][p][e] = 0.0f;

    const float* sbase = g_S + ((size_t)bh * TT + t0) * TT;
    size_t vtb = (size_t)bh * HD * TT;

    for (int kc = 0; kc < 16; kc++) {
        int k0 = kc * 64;
        if (kc) __syncthreads();             // prior MMA reads complete

        // --- load S chunk, exp, band/plo, store P bf16 hi/lo ---
        const float* srow = sbase + (size_t)lrow * TT + k0 + lcs;
        #pragma unroll
        for (int g = 0; g < 4; g++) {
            float p[8];
            #pragma unroll
            for (int q = 0; q < 2; q++) {
                float4 s4 = *(const float4*)(srow + g * 8 + q * 4);
                p[q * 4 + 0] = __expf(s4.x - mrow);
                p[q * 4 + 1] = __expf(s4.y - mrow);
                p[q * 4 + 2] = __expf(s4.z - mrow);
                p[q * 4 + 3] = __expf(s4.w - mrow);
            }
            #pragma unroll
            for (int j = 0; j < 8; j++) {
                int d = (k0 + lcs + g * 8 + j) - tg;
                if ((unsigned)(d + 67) <= 134u)
                    band[lrow * 136 + d + 67] = p[j];
                else if (d <= -MAXR)
                    plo += p[j];
            }
            uint32_t hi[4], lo[4];
            #pragma unroll
            for (int j = 0; j < 4; j++) {
                __nv_bfloat16 h0 = __float2bfloat16(p[2 * j]);
                __nv_bfloat16 h1 = __float2bfloat16(p[2 * j + 1]);
                hi[j] = pack_bf2(h0, h1);
                lo[j] = pack_bf2(
                    __float2bfloat16(p[2 * j]     - __bfloat162float(h0)),
                    __float2bfloat16(p[2 * j + 1] - __bfloat162float(h1)));
            }
            uint32_t dst = SWZ128((uint32_t)(lrow * 128 + (lcs + g * 8) * 2));
            *(uint4*)(smc + PV2_PHI + dst) = make_uint4(hi[0], hi[1], hi[2], hi[3]);
            *(uint4*)(smc + PV2_PLO + dst) = make_uint4(lo[0], lo[1], lo[2], lo[3]);
        }

        // --- load Vt chunk (64 d rows x 64 k) ---
        #pragma unroll
        for (int s = 0; s < 2; s++) {
            int vec = tid + s * 256;
            int r = vec >> 3, g8 = vec & 7;
            uint32_t dst = SWZ128((uint32_t)(r * 128 + g8 * 16));
            size_t src = vtb + (size_t)r * TT + k0 + g8 * 8;
            *(uint4*)(smc + PV2_VHI + dst) = *(const uint4*)(g_vthi + src);
            *(uint4*)(smc + PV2_VLO + dst) = *(const uint4*)(g_vtlo + src);
        }
        __syncthreads();

        // --- MMA: warp rows wid*16..+15, N = 64 ---
        #pragma unroll
        for (int ks = 0; ks < 4; ks++) {
            uint32_t aad = SWZ128((uint32_t)(
                (wid * 16 + (lane & 15)) * 128 + (ks * 16 + (lane >> 4) * 8) * 2));
            uint32_t ah[4], al[4];
            ldsm4(ah, uPHI + aad);
            ldsm4(al, uPLO + aad);
            int br_off = (lane & 7) + ((lane >> 4) << 3);
            int bk = ks * 16 + (((lane >> 3) & 1) << 3);
            #pragma unroll
            for (int nf = 0; nf < 4; nf++) {
                uint32_t bad = SWZ128((uint32_t)((nf * 16 + br_off) * 128 + bk * 2));
                uint32_t bh4[4], bl4[4];
                ldsm4(bh4, uVHI + bad);
                ldsm4(bl4, uVLO + bad);
                mma16816(c[nf][0], ah, bh4);
                mma16816(c[nf][0], ah, bl4);
                mma16816(c[nf][0], al, bh4);
                mma16816(c[nf][1], ah, bh4 + 2);
                mma16816(c[nf][1], ah, bl4 + 2);
                mma16816(c[nf][1], al, bh4 + 2);
            }
        }
    }

    // plo: combine the 2 threads sharing a row, store per-row
    plo += __shfl_xor_sync(0xffffffffu, plo, 1);
    if ((tid & 1) == 0) ps_s[lrow] = plo;
    __syncthreads();

    // rel_v into alias region
    for (int idx = tid * 4; idx < NR * 64; idx += 1024)
        *(float4*)(rvs + idx) = *(const float4*)(rel_v + idx);
    __syncthreads();

    // band @ rel_v epilogue on fragment layout
    float intu[2] = {0.0f, 0.0f};
    for (int r = 1; r <= 135; r++) {
        #pragma unroll
        for (int e2 = 0; e2 < 2; e2++) {
            int rowl = wid * 16 + (lane >> 2) + e2 * 8;
            float sv = band[rowl * 136 + r - 1];
            intu[e2] += sv;
            #pragma unroll
            for (int nf = 0; nf < 4; nf++)
                #pragma unroll
                for (int p = 0; p < 2; p++) {
                    int d = nf * 16 + p * 8 + (lane & 3) * 2;
                    float2 rv = *(float2*)(rvs + r * 64 + d);
                    c[nf][p][e2 * 2]     += sv * rv.x;
                    c[nf][p][e2 * 2 + 1] += sv * rv.y;
                }
        }
    }

    int b_ = bh >> 3, h = bh & 7;
    #pragma unroll
    for (int e2 = 0; e2 < 2; e2++) {
        int rowl = wid * 16 + (lane >> 2) + e2 * 8;
        int t = t0 + rowl;
        float lr = l_s[rowl], pl = ps_s[rowl];
        float phi = lr - pl - intu[e2];
        float inv = 1.0f / lr;
        #pragma unroll
        for (int nf = 0; nf < 4; nf++)
            #pragma unroll
            for (int p = 0; p < 2; p++) {
                int d = nf * 16 + p * 8 + (lane & 3) * 2;
                float w0 = c[nf][p][e2 * 2]     + pl * rvs[d]
                         + phi * rvs[136 * 64 + d];
                float w1 = c[nf][p][e2 * 2 + 1] + pl * rvs[d + 1]
                         + phi * rvs[136 * 64 + d + 1];
                float o0 = w0 * inv, o1 = w1 * inv;
                size_t ob = ((size_t)(b_ * TT + t)) * CC + h * HD + d;
                __nv_bfloat16 h0 = __float2bfloat16(o0);
                __nv_bfloat16 h1 = __float2bfloat16(o1);
                *(uint32_t*)(g_yhi + ob) = pack_bf2(h0, h1);
                *(uint32_t*)(g_ylo + ob) = pack_bf2(
                    __float2bfloat16(o0 - __bfloat162float(h0)),
                    __float2bfloat16(o1 - __bfloat162float(h1)));
            }
    }
}

// ---------------------------------------------------------------------------
extern "C" void kernel_launch(void* const* d_in, const int* in_sizes, int n_in,
                              void* d_out, int out_size)
{
    const float* x     = (const float*)d_in[0];
    const float* Wq    = (const float*)d_in[1];
    const float* bq    = (const float*)d_in[2];
    const float* Wk    = (const float*)d_in[3];
    const float* bk    = (const float*)d_in[4];
    const float* Wv    = (const float*)d_in[5];
    const float* bv    = (const float*)d_in[6];
    const float* Wo    = (const float*)d_in[7];
    const float* bo    = (const float*)d_in[8];
    const float* rel_k = (const float*)d_in[9];
    const float* rel_v = (const float*)d_in[10];
    float* out = (float*)d_out;

    cudaFuncSetAttribute(gemm_mma, cudaFuncAttributeMaxDynamicSharedMemorySize,
                         GT_SMEM);
    cudaFuncSetAttribute(proj_mma, cudaFuncAttributeMaxDynamicSharedMemorySize,
                         PJ_SMEM);
    cudaFuncSetAttribute(s_mma, cudaFuncAttributeMaxDynamicSharedMemorySize,
                         SM_SMEM);
    cudaFuncSetAttribute(pv_mma, cudaFuncAttributeMaxDynamicSharedMemorySize,
                         PV2_SMEM);

    conv_w<<<1024, 512>>>(Wq, Wk, Wv, Wo, bq, bk, bv, bo, rel_k);
    conv_split_x<<<1024, 512>>>(x, MM * CC / 4);
    gemm_mma<<<dim3(12, 64), 256, GT_SMEM>>>(nullptr, 1);
    conv_vt<<<dim3(16, 64), 256>>>();
    proj_mma<<<512, 256, PJ_SMEM>>>();
    s_mma<<<dim3(8, 8, 64), 256, SM_SMEM>>>();
    reduce_ml<<<64, 1024>>>();
    pv_mma<<<dim3(8, 64), 256, PV2_SMEM>>>(rel_v);
    gemm_mma<<<dim3(4, 64), 256, GT_SMEM>>>(out, 0);
}

// round 9
// speedup vs baseline: 2.6401x; 1.2281x over previous
#include <cuda_runtime.h>
#include <cuda_bf16.h>
#include <cstdint>

// Problem constants
#define BB   8
#define TT   1024
#define CC   512
#define HH   8
#define HD   64
#define NR   137
#define MAXR 68
#define BH   64
#define MM   8192
#define NRP  144

// ---------------------------------------------------------------------------
// Scratch (device globals)
// ---------------------------------------------------------------------------
static __device__ float g_v[BH * TT * HD];
static __device__ float g_proj[BH * TT * NR];
static __device__ float g_band[BH * TT * 136];          // raw logits, block-private rows

static __device__ __nv_bfloat16 g_qhi[BH * TT * HD];
static __device__ __nv_bfloat16 g_qlo[BH * TT * HD];
static __device__ __nv_bfloat16 g_khi[BH * TT * HD];
static __device__ __nv_bfloat16 g_klo[BH * TT * HD];
static __device__ __nv_bfloat16 g_vthi[BH * HD * TT];   // [bh][d][t]
static __device__ __nv_bfloat16 g_vtlo[BH * HD * TT];
static __device__ __nv_bfloat16 g_rkhi[NRP * HD];
static __device__ __nv_bfloat16 g_rklo[NRP * HD];

static __device__ __nv_bfloat16 g_xhi[MM * CC];
static __device__ __nv_bfloat16 g_xlo[MM * CC];
static __device__ __nv_bfloat16 g_yhi[MM * CC];
static __device__ __nv_bfloat16 g_ylo[MM * CC];
static __device__ __nv_bfloat16 g_wthi[4 * CC * CC];
static __device__ __nv_bfloat16 g_wtlo[4 * CC * CC];
static __device__ float g_bias[4 * CC];

// ---------------------------------------------------------------------------
// warp-MMA helpers
// ---------------------------------------------------------------------------
__device__ __forceinline__ uint32_t smem_u32(const void* p) {
    uint32_t a;
    asm("{ .reg .u64 t; cvta.to.shared.u64 t, %1; cvt.u32.u64 %0, t; }"
        : "=r"(a) : "l"(p));
    return a;
}
__device__ __forceinline__ void ldsm4(uint32_t* r, uint32_t addr) {
    asm volatile("ldmatrix.sync.aligned.m8n8.x4.shared.b16 {%0,%1,%2,%3}, [%4];"
        : "=r"(r[0]), "=r"(r[1]), "=r"(r[2]), "=r"(r[3]) : "r"(addr));
}
__device__ __forceinline__ void ldsm2(uint32_t* r, uint32_t addr) {
    asm volatile("ldmatrix.sync.aligned.m8n8.x2.shared.b16 {%0,%1}, [%2];"
        : "=r"(r[0]), "=r"(r[1]) : "r"(addr));
}
__device__ __forceinline__ void mma16816(float* c, const uint32_t* a, const uint32_t* b) {
    asm volatile(
        "mma.sync.aligned.m16n8k16.row.col.f32.bf16.bf16.f32 "
        "{%0,%1,%2,%3}, {%4,%5,%6,%7}, {%8,%9}, {%0,%1,%2,%3};"
        : "+f"(c[0]), "+f"(c[1]), "+f"(c[2]), "+f"(c[3])
        : "r"(a[0]), "r"(a[1]), "r"(a[2]), "r"(a[3]), "r"(b[0]), "r"(b[1]));
}
#define SWZ128(b) ((b) ^ (((b) >> 3) & 0x70))

__device__ __forceinline__ uint32_t pack_bf2(__nv_bfloat16 a, __nv_bfloat16 b) {
    __nv_bfloat162 t = {a, b};
    return *(uint32_t*)&t;
}

// ---------------------------------------------------------------------------
// conversion kernels
// ---------------------------------------------------------------------------
__global__ __launch_bounds__(512) void conv_split_x(const float* __restrict__ src, int n4)
{
    for (int i = blockIdx.x * blockDim.x + threadIdx.x; i < n4;
         i += gridDim.x * blockDim.x) {
        float4 v = *(const float4*)(src + (size_t)i * 4);
        float vv[4] = {v.x, v.y, v.z, v.w};
        #pragma unroll
        for (int j = 0; j < 4; j++) {
            __nv_bfloat16 h = __float2bfloat16(vv[j]);
            g_xhi[(size_t)i * 4 + j] = h;
            g_xlo[(size_t)i * 4 + j] = __float2bfloat16(vv[j] - __bfloat162float(h));
        }
    }
}

__global__ __launch_bounds__(512) void conv_w(
    const float* __restrict__ Wq, const float* __restrict__ Wk,
    const float* __restrict__ Wv, const float* __restrict__ Wo,
    const float* __restrict__ bq, const float* __restrict__ bk,
    const float* __restrict__ bv, const float* __restrict__ bo,
    const float* __restrict__ rel_k)
{
    int gid = blockIdx.x * blockDim.x + threadIdx.x;
    int nth = gridDim.x * blockDim.x;
    for (int idx = gid; idx < 4 * CC * CC; idx += nth) {
        int z = idx >> 18;
        int rem = idx & (CC * CC - 1);
        int k = rem >> 9, n = rem & 511;
        const float* W = (z == 0) ? Wq : (z == 1) ? Wk : (z == 2) ? Wv : Wo;
        float v = W[k * CC + n];
        __nv_bfloat16 h = __float2bfloat16(v);
        size_t dst = (size_t)z * CC * CC + (size_t)n * CC + k;
        g_wthi[dst] = h;
        g_wtlo[dst] = __float2bfloat16(v - __bfloat162float(h));
    }
    for (int idx = gid; idx < NRP * HD; idx += nth) {
        int r = idx >> 6, d = idx & 63;
        float v = (r < NR) ? rel_k[r * HD + d] : 0.0f;
        __nv_bfloat16 h = __float2bfloat16(v);
        g_rkhi[idx] = h;
        g_rklo[idx] = __float2bfloat16(v - __bfloat162float(h));
    }
    if (gid < 4 * CC) {
        int z = gid >> 9, n = gid & 511;
        const float* bsrc = (z == 0) ? bq : (z == 1) ? bk : (z == 2) ? bv : bo;
        g_bias[gid] = bsrc[n];
    }
}

// v[bh][t][d] -> vt hi/lo [bh][d][t]
__global__ __launch_bounds__(256) void conv_vt()
{
    __shared__ float tile[64][65];
    int bh = blockIdx.y, t0 = blockIdx.x * 64;
    int tid = threadIdx.x;
    #pragma unroll
    for (int s = 0; s < 4; s++) {
        int vec = tid + s * 256;
        int r = vec >> 4, c4 = (vec & 15) * 4;
        float4 v = *(const float4*)(g_v + ((size_t)bh * TT + t0 + r) * HD + c4);
        tile[r][c4 + 0] = v.x;
        tile[r][c4 + 1] = v.y;
        tile[r][c4 + 2] = v.z;
        tile[r][c4 + 3] = v.w;
    }
    __syncthreads();
    int d = tid >> 2, ts = (tid & 3) * 16;
    size_t ob = ((size_t)bh * HD + d) * TT + t0 + ts;
    uint32_t hi[8], lo[8];
    #pragma unroll
    for (int j = 0; j < 8; j++) {
        float v0 = tile[ts + j * 2][d];
        float v1 = tile[ts + j * 2 + 1][d];
        __nv_bfloat16 h0 = __float2bfloat16(v0);
        __nv_bfloat16 h1 = __float2bfloat16(v1);
        hi[j] = pack_bf2(h0, h1);
        lo[j] = pack_bf2(__float2bfloat16(v0 - __bfloat162float(h0)),
                         __float2bfloat16(v1 - __bfloat162float(h1)));
    }
    *(uint4*)(g_vthi + ob)     = make_uint4(hi[0], hi[1], hi[2], hi[3]);
    *(uint4*)(g_vthi + ob + 8) = make_uint4(hi[4], hi[5], hi[6], hi[7]);
    *(uint4*)(g_vtlo + ob)     = make_uint4(lo[0], lo[1], lo[2], lo[3]);
    *(uint4*)(g_vtlo + ob + 8) = make_uint4(lo[4], lo[5], lo[6], lo[7]);
}

// ---------------------------------------------------------------------------
// bf16x3 warp-MMA GEMM (qkv / output projection) — unchanged
// ---------------------------------------------------------------------------
#define GT_A_HI 0
#define GT_A_LO 16384
#define GT_B_HI 32768
#define GT_B_LO 49152
#define GT_SMEM 65536

__global__ __launch_bounds__(256, 2) void gemm_mma(float* __restrict__ outp, int mode)
{
    extern __shared__ char smc[];
    const __nv_bfloat16 *Ahi, *Alo, *Bhi, *Blo;
    const float* bias;
    if (mode == 1) {
        Ahi = g_xhi; Alo = g_xlo; Bhi = g_wthi; Blo = g_wtlo; bias = g_bias;
    } else {
        Ahi = g_yhi; Alo = g_ylo;
        Bhi = g_wthi + 3 * CC * CC; Blo = g_wtlo + 3 * CC * CC;
        bias = g_bias + 3 * CC;
    }

    int tid = threadIdx.x, lane = tid & 31, wid = tid >> 5;
    int wm = wid >> 2, wn = wid & 3;
    int row0 = blockIdx.y * 128, col0 = blockIdx.x * 128;

    uint32_t sA_hi = smem_u32(smc + GT_A_HI);
    uint32_t sA_lo = smem_u32(smc + GT_A_LO);
    uint32_t sB_hi = smem_u32(smc + GT_B_HI);
    uint32_t sB_lo = smem_u32(smc + GT_B_LO);

    float c[4][4][4];
    #pragma unroll
    for (int mi = 0; mi < 4; mi++)
        #pragma unroll
        for (int ni = 0; ni < 4; ni++)
            #pragma unroll
            for (int e = 0; e < 4; e++) c[mi][ni][e] = 0.0f;

    for (int kc = 0; kc < 8; kc++) {
        int k0 = kc * 64;
        __syncthreads();
        #pragma unroll
        for (int s = 0; s < 4; s++) {
            int vec = tid + s * 256;
            int r = vec >> 3, v8 = vec & 7;
            uint32_t dst = SWZ128((uint32_t)(r * 128 + v8 * 16));
            size_t asrc = (size_t)(row0 + r) * CC + k0 + v8 * 8;
            size_t bsrc = (size_t)(col0 + r) * CC + k0 + v8 * 8;
            *(uint4*)(smc + GT_A_HI + dst) = *(const uint4*)(Ahi + asrc);
            *(uint4*)(smc + GT_A_LO + dst) = *(const uint4*)(Alo + asrc);
            *(uint4*)(smc + GT_B_HI + dst) = *(const uint4*)(Bhi + bsrc);
            *(uint4*)(smc + GT_B_LO + dst) = *(const uint4*)(Blo + bsrc);
        }
        __syncthreads();

        #pragma unroll
        for (int ks = 0; ks < 4; ks++) {
            int kbase = ks * 16;
            int lp = lane & 15;
            int bkb = kbase + (lp >> 3) * 8;
            uint32_t bh[4][2], bl[4][2];
            #pragma unroll
            for (int ni = 0; ni < 4; ni++) {
                int nloc = wn * 32 + ni * 8 + (lp & 7);
                uint32_t ad = SWZ128((uint32_t)(nloc * 128 + bkb * 2));
                ldsm2(bh[ni], sB_hi + ad);
                ldsm2(bl[ni], sB_lo + ad);
            }
            int akb = kbase + (lane >> 4) * 8;
            int mlp = lane & 15;
            #pragma unroll
            for (int mi = 0; mi < 4; mi++) {
                int mloc = wm * 64 + mi * 16 + mlp;
                uint32_t ad = SWZ128((uint32_t)(mloc * 128 + akb * 2));
                uint32_t ah[4], al[4];
                ldsm4(ah, sA_hi + ad);
                ldsm4(al, sA_lo + ad);
                #pragma unroll
                for (int ni = 0; ni < 4; ni++) {
                    mma16816(c[mi][ni], ah, bh[ni]);
                    mma16816(c[mi][ni], ah, bl[ni]);
                    mma16816(c[mi][ni], al, bh[ni]);
                }
            }
        }
    }

    int r_base = row0 + wm * 64 + (lane >> 2);
    int n_base = col0 + wn * 32 + (lane & 3) * 2;

    if (mode == 0) {
        #pragma unroll
        for (int mi = 0; mi < 4; mi++) {
            int r = r_base + mi * 16;
            #pragma unroll
            for (int ni = 0; ni < 4; ni++) {
                int n = n_base + ni * 8;
                float b0 = bias[n], b1 = bias[n + 1];
                float2 v0 = make_float2(c[mi][ni][0] + b0, c[mi][ni][1] + b1);
                float2 v1 = make_float2(c[mi][ni][2] + b0, c[mi][ni][3] + b1);
                *(float2*)(outp + (size_t)r * CC + n)       = v0;
                *(float2*)(outp + (size_t)(r + 8) * CC + n) = v1;
            }
        }
    } else {
        int z = col0 >> 9;
        #pragma unroll
        for (int mi = 0; mi < 4; mi++) {
            int r = r_base + mi * 16;
            int b_ = r >> 10, t = r & (TT - 1);
            #pragma unroll
            for (int ni = 0; ni < 4; ni++) {
                int n = n_base + ni * 8;
                int nn = n & 511;
                int h = nn >> 6, d = nn & 63;
                float b0 = bias[n], b1 = bias[n + 1];
                size_t o = (((size_t)b_ * HH + h) * TT + t) * HD + d;
                float p00 = c[mi][ni][0] + b0, p01 = c[mi][ni][1] + b1;
                float p10 = c[mi][ni][2] + b0, p11 = c[mi][ni][3] + b1;
                if (z == 2) {
                    *(float2*)(g_v + o)          = make_float2(p00, p01);
                    *(float2*)(g_v + o + 8 * HD) = make_float2(p10, p11);
                } else {
                    __nv_bfloat16* dhi = (z == 0) ? g_qhi : g_khi;
                    __nv_bfloat16* dlo = (z == 0) ? g_qlo : g_klo;
                    __nv_bfloat16 h00 = __float2bfloat16(p00);
                    __nv_bfloat16 h01 = __float2bfloat16(p01);
                    __nv_bfloat16 h10 = __float2bfloat16(p10);
                    __nv_bfloat16 h11 = __float2bfloat16(p11);
                    *(uint32_t*)(dhi + o)          = pack_bf2(h00, h01);
                    *(uint32_t*)(dhi + o + 8 * HD) = pack_bf2(h10, h11);
                    *(uint32_t*)(dlo + o) =
                        pack_bf2(__float2bfloat16(p00 - __bfloat162float(h00)),
                                 __float2bfloat16(p01 - __bfloat162float(h01)));
                    *(uint32_t*)(dlo + o + 8 * HD) =
                        pack_bf2(__float2bfloat16(p10 - __bfloat162float(h10)),
                                 __float2bfloat16(p11 - __bfloat162float(h11)));
                }
            }
        }
    }
}

// ---------------------------------------------------------------------------
// proj_mma — unchanged
// ---------------------------------------------------------------------------
#define PJ_Q_HI 0
#define PJ_Q_LO 16384
#define PJ_R_HI 32768
#define PJ_R_LO (32768 + NRP * 128)
#define PJ_SMEM (32768 + 2 * NRP * 128)

__global__ __launch_bounds__(256) void proj_mma()
{
    extern __shared__ char smc[];
    int tid = threadIdx.x, lane = tid & 31, wid = tid >> 5;
    int t0 = blockIdx.x * 128;

    uint32_t sQH = smem_u32(smc + PJ_Q_HI);
    uint32_t sQL = smem_u32(smc + PJ_Q_LO);
    uint32_t sRH = smem_u32(smc + PJ_R_HI);
    uint32_t sRL = smem_u32(smc + PJ_R_LO);

    #pragma unroll
    for (int s = 0; s < 4; s++) {
        int vec = tid + s * 256;
        int r = vec >> 3, g8 = vec & 7;
        uint32_t dst = SWZ128((uint32_t)(r * 128 + g8 * 16));
        size_t src = (size_t)(t0 + r) * HD + g8 * 8;
        *(uint4*)(smc + PJ_Q_HI + dst) = *(const uint4*)(g_qhi + src);
        *(uint4*)(smc + PJ_Q_LO + dst) = *(const uint4*)(g_qlo + src);
    }
    for (int vec = tid; vec < NRP * 8; vec += 256) {
        int r = vec >> 3, g8 = vec & 7;
        uint32_t dst = SWZ128((uint32_t)(r * 128 + g8 * 16));
        size_t src = (size_t)r * HD + g8 * 8;
        *(uint4*)(smc + PJ_R_HI + dst) = *(const uint4*)(g_rkhi + src);
        *(uint4*)(smc + PJ_R_LO + dst) = *(const uint4*)(g_rklo + src);
    }
    __syncthreads();

    float c[9][2][4];
    #pragma unroll
    for (int nf = 0; nf < 9; nf++)
        #pragma unroll
        for (int p = 0; p < 2; p++)
            #pragma unroll
            for (int e = 0; e < 4; e++) c[nf][p][e] = 0.0f;

    #pragma unroll
    for (int ks = 0; ks < 4; ks++) {
        int kbase = ks * 16;
        int akb = kbase + (lane >> 4) * 8;
        uint32_t aad = SWZ128((uint32_t)((wid * 16 + (lane & 15)) * 128 + akb * 2));
        uint32_t ah[4], al[4];
        ldsm4(ah, sQH + aad);
        ldsm4(al, sQL + aad);

        int br_off = (lane & 7) + ((lane >> 4) << 3);
        int bk = kbase + (((lane >> 3) & 1) << 3);
        #pragma unroll
        for (int nf = 0; nf < 9; nf++) {
            uint32_t bad = SWZ128((uint32_t)((nf * 16 + br_off) * 128 + bk * 2));
            uint32_t bh4[4], bl4[4];
            ldsm4(bh4, sRH + bad);
            ldsm4(bl4, sRL + bad);
            mma16816(c[nf][0], ah, bh4);
            mma16816(c[nf][0], ah, bl4);
            mma16816(c[nf][0], al, bh4);
            mma16816(c[nf][1], ah, bh4 + 2);
            mma16816(c[nf][1], ah, bl4 + 2);
            mma16816(c[nf][1], al, bh4 + 2);
        }
    }

    #pragma unroll
    for (int e2 = 0; e2 < 2; e2++) {
        int row = t0 + wid * 16 + (lane >> 2) + e2 * 8;
        float* prow = g_proj + (size_t)row * NR;
        #pragma unroll
        for (int nf = 0; nf < 9; nf++)
            #pragma unroll
            for (int p = 0; p < 2; p++) {
                int col = nf * 16 + p * 8 + (lane & 3) * 2;
                if (col < NR)     prow[col]     = c[nf][p][e2 * 2];
                if (col + 1 < NR) prow[col + 1] = c[nf][p][e2 * 2 + 1];
            }
    }
}

// ---------------------------------------------------------------------------
// attn_mma: fused S-MMA + online softmax + PV-MMA + band/rel_v epilogue
// grid (8, 64), block 256 (8 warps x 16 t-rows), k-chunks of 64
// ---------------------------------------------------------------------------
#define FA_QHI 0
#define FA_QLO 16384
#define FA_KHI 32768
#define FA_KLO 40960
#define FA_VHI 49152
#define FA_VLO 57344
#define FA_PHI 65536
#define FA_PLO 81920
#define FA_SMEM 98304

__global__ __launch_bounds__(256, 2) void attn_mma(const float* __restrict__ rel_v)
{
    extern __shared__ char smc[];
    int tid = threadIdx.x, lane = tid & 31, wid = tid >> 5;
    int bh = blockIdx.y, t0 = blockIdx.x * 128;

    uint32_t uQH = smem_u32(smc + FA_QHI);
    uint32_t uQL = smem_u32(smc + FA_QLO);
    uint32_t uKH = smem_u32(smc + FA_KHI);
    uint32_t uKL = smem_u32(smc + FA_KLO);
    uint32_t uVH = smem_u32(smc + FA_VHI);
    uint32_t uVL = smem_u32(smc + FA_VLO);
    uint32_t uPH = smem_u32(smc + FA_PHI);
    uint32_t uPL = smem_u32(smc + FA_PLO);

    size_t qb = (size_t)bh * TT * HD;
    size_t vtb = (size_t)bh * HD * TT;
    float* bandb = g_band + ((size_t)bh * TT + t0) * 136;

    // Q tile (128x64) hi/lo swizzled; band init
    #pragma unroll
    for (int s = 0; s < 4; s++) {
        int vec = tid + s * 256;
        int r = vec >> 3, g8 = vec & 7;
        uint32_t dst = SWZ128((uint32_t)(r * 128 + g8 * 16));
        size_t src = qb + (size_t)(t0 + r) * HD + g8 * 8;
        *(uint4*)(smc + FA_QHI + dst) = *(const uint4*)(g_qhi + src);
        *(uint4*)(smc + FA_QLO + dst) = *(const uint4*)(g_qlo + src);
    }
    for (int idx = tid; idx < 128 * 136; idx += 256) bandb[idx] = -1e30f;

    float m[2] = {-1e30f, -1e30f}, l[2] = {0.0f, 0.0f}, plo[2] = {0.0f, 0.0f};
    float c[4][2][4];
    #pragma unroll
    for (int nf = 0; nf < 4; nf++)
        #pragma unroll
        for (int p = 0; p < 2; p++)
            #pragma unroll
            for (int e = 0; e < 4; e++) c[nf][p][e] = 0.0f;

    const float scale = 0.044194173824159216f;   // 1/sqrt(512)
    int rbase = wid * 16 + (lane >> 2);

    for (int kc = 0; kc < 16; kc++) {
        int k0 = kc * 64;
        __syncthreads();       // prior chunk's MMA reads of K/V done

        // K chunk (64 k-rows x 64 d) + Vt chunk (64 d-rows x 64 k)
        #pragma unroll
        for (int s = 0; s < 2; s++) {
            int vec = tid + s * 256;
            int r = vec >> 3, g8 = vec & 7;
            uint32_t dst = SWZ128((uint32_t)(r * 128 + g8 * 16));
            size_t ksrc = qb + (size_t)(k0 + r) * HD + g8 * 8;
            size_t vsrc = vtb + (size_t)r * TT + k0 + g8 * 8;
            *(uint4*)(smc + FA_KHI + dst) = *(const uint4*)(g_khi + ksrc);
            *(uint4*)(smc + FA_KLO + dst) = *(const uint4*)(g_klo + ksrc);
            *(uint4*)(smc + FA_VHI + dst) = *(const uint4*)(g_vthi + vsrc);
            *(uint4*)(smc + FA_VLO + dst) = *(const uint4*)(g_vtlo + vsrc);
        }
        __syncthreads();

        // S chunk MMA: cs[4nf][2p][4]
        float cs[4][2][4];
        #pragma unroll
        for (int nf = 0; nf < 4; nf++)
            #pragma unroll
            for (int p = 0; p < 2; p++)
                #pragma unroll
                for (int e = 0; e < 4; e++) cs[nf][p][e] = 0.0f;

        #pragma unroll
        for (int ks = 0; ks < 4; ks++) {
            uint32_t aad = SWZ128((uint32_t)(
                (wid * 16 + (lane & 15)) * 128 + (ks * 16 + (lane >> 4) * 8) * 2));
            uint32_t ah[4], al[4];
            ldsm4(ah, uQH + aad);
            ldsm4(al, uQL + aad);
            int br_off = (lane & 7) + ((lane >> 4) << 3);
            int bk = ks * 16 + (((lane >> 3) & 1) << 3);
            #pragma unroll
            for (int nf = 0; nf < 4; nf++) {
                uint32_t bad = SWZ128((uint32_t)((nf * 16 + br_off) * 128 + bk * 2));
                uint32_t bh4[4], bl4[4];
                ldsm4(bh4, uKH + bad);
                ldsm4(bl4, uKL + bad);
                mma16816(cs[nf][0], ah, bh4);
                mma16816(cs[nf][0], ah, bl4);
                mma16816(cs[nf][0], al, bh4);
                mma16816(cs[nf][1], ah, bh4 + 2);
                mma16816(cs[nf][1], ah, bl4 + 2);
                mma16816(cs[nf][1], al, bh4 + 2);
            }
        }

        // online softmax per fragment row
        #pragma unroll
        for (int e2 = 0; e2 < 2; e2++) {
            int rowl = rbase + e2 * 8;
            int trow = t0 + rowl;
            const float* prow = g_proj + ((size_t)bh * TT + trow) * NR;
            float mx = -1e30f;
            #pragma unroll
            for (int nf = 0; nf < 4; nf++)
                #pragma unroll
                for (int p = 0; p < 2; p++)
                    #pragma unroll
                    for (int j = 0; j < 2; j++) {
                        int kg = k0 + nf * 16 + p * 8 + (lane & 3) * 2 + j;
                        int dist = kg - trow;
                        dist = dist < -MAXR ? -MAXR : (dist > MAXR ? MAXR : dist);
                        float v = (cs[nf][p][e2 * 2 + j] + prow[dist + MAXR]) * scale;
                        cs[nf][p][e2 * 2 + j] = v;
                        mx = fmaxf(mx, v);
                    }
            mx = fmaxf(mx, __shfl_xor_sync(0xffffffffu, mx, 1));
            mx = fmaxf(mx, __shfl_xor_sync(0xffffffffu, mx, 2));
            float mnew = fmaxf(m[e2], mx);
            float f = __expf(m[e2] - mnew);
            m[e2] = mnew;
            l[e2] *= f; plo[e2] *= f;
            #pragma unroll
            for (int nf = 0; nf < 4; nf++)
                #pragma unroll
                for (int p = 0; p < 2; p++) {
                    c[nf][p][e2 * 2]     *= f;
                    c[nf][p][e2 * 2 + 1] *= f;
                }

            float es = 0.0f, pl = 0.0f;
            #pragma unroll
            for (int nf = 0; nf < 4; nf++)
                #pragma unroll
                for (int p = 0; p < 2; p++) {
                    float v0 = cs[nf][p][e2 * 2], v1 = cs[nf][p][e2 * 2 + 1];
                    float p0 = __expf(v0 - mnew), p1 = __expf(v1 - mnew);
                    es += p0 + p1;
                    int kcol = nf * 16 + p * 8 + (lane & 3) * 2;
                    int d0 = (k0 + kcol) - trow;
                    if ((unsigned)(d0 + 67) <= 134u) bandb[rowl * 136 + d0 + 67] = v0;
                    else if (d0 <= -MAXR) pl += p0;
                    int d1 = d0 + 1;
                    if ((unsigned)(d1 + 67) <= 134u) bandb[rowl * 136 + d1 + 67] = v1;
                    else if (d1 <= -MAXR) pl += p1;

                    __nv_bfloat16 h0 = __float2bfloat16(p0);
                    __nv_bfloat16 h1 = __float2bfloat16(p1);
                    uint32_t dst = SWZ128((uint32_t)(rowl * 128 + kcol * 2));
                    *(uint32_t*)(smc + FA_PHI + dst) = pack_bf2(h0, h1);
                    *(uint32_t*)(smc + FA_PLO + dst) = pack_bf2(
                        __float2bfloat16(p0 - __bfloat162float(h0)),
                        __float2bfloat16(p1 - __bfloat162float(h1)));
                }
            es += __shfl_xor_sync(0xffffffffu, es, 1);
            es += __shfl_xor_sync(0xffffffffu, es, 2);
            pl += __shfl_xor_sync(0xffffffffu, pl, 1);
            pl += __shfl_xor_sync(0xffffffffu, pl, 2);
            l[e2] += es; plo[e2] += pl;
        }
        __syncwarp();   // P stores visible to own warp's ldmatrix

        // PV MMA: A = P rows of this warp, B = Vt chunk
        #pragma unroll
        for (int ks = 0; ks < 4; ks++) {
            uint32_t aad = SWZ128((uint32_t)(
                (wid * 16 + (lane & 15)) * 128 + (ks * 16 + (lane >> 4) * 8) * 2));
            uint32_t ah[4], al[4];
            ldsm4(ah, uPH + aad);
            ldsm4(al, uPL + aad);
            int br_off = (lane & 7) + ((lane >> 4) << 3);
            int bk = ks * 16 + (((lane >> 3) & 1) << 3);
            #pragma unroll
            for (int nf = 0; nf < 4; nf++) {
                uint32_t bad = SWZ128((uint32_t)((nf * 16 + br_off) * 128 + bk * 2));
                uint32_t bh4[4], bl4[4];
                ldsm4(bh4, uVH + bad);
                ldsm4(bl4, uVL + bad);
                mma16816(c[nf][0], ah, bh4);
                mma16816(c[nf][0], ah, bl4);
                mma16816(c[nf][0], al, bh4);
                mma16816(c[nf][1], ah, bh4 + 2);
                mma16816(c[nf][1], ah, bl4 + 2);
                mma16816(c[nf][1], al, bh4 + 2);
            }
        }
    }

    // stage rel_v into smem (tiles dead now)
    __syncthreads();
    float* rvs = (float*)smc;
    for (int idx = tid * 4; idx < NR * 64; idx += 1024)
        *(float4*)(rvs + idx) = *(const float4*)(rel_v + idx);
    __syncthreads();

    // band @ rel_v epilogue (exp with final m)
    float intu[2] = {0.0f, 0.0f};
    for (int r = 1; r <= 135; r++) {
        #pragma unroll
        for (int e2 = 0; e2 < 2; e2++) {
            int rowl = rbase + e2 * 8;
            float sv = __expf(bandb[rowl * 136 + r - 1] - m[e2]);
            intu[e2] += sv;
            #pragma unroll
            for (int nf = 0; nf < 4; nf++)
                #pragma unroll
                for (int p = 0; p < 2; p++) {
                    int d = nf * 16 + p * 8 + (lane & 3) * 2;
                    float2 rv = *(float2*)(rvs + r * 64 + d);
                    c[nf][p][e2 * 2]     += sv * rv.x;
                    c[nf][p][e2 * 2 + 1] += sv * rv.y;
                }
        }
    }

    int b_ = bh >> 3, h = bh & 7;
    #pragma unroll
    for (int e2 = 0; e2 < 2; e2++) {
        int rowl = rbase + e2 * 8;
        int t = t0 + rowl;
        float lr = l[e2], pl = plo[e2];
        float phi = lr - pl - intu[e2];
        float inv = 1.0f / lr;
        #pragma unroll
        for (int nf = 0; nf < 4; nf++)
            #pragma unroll
            for (int p = 0; p < 2; p++) {
                int d = nf * 16 + p * 8 + (lane & 3) * 2;
                float w0 = c[nf][p][e2 * 2]     + pl * rvs[d]
                         + phi * rvs[136 * 64 + d];
                float w1 = c[nf][p][e2 * 2 + 1] + pl * rvs[d + 1]
                         + phi * rvs[136 * 64 + d + 1];
                float o0 = w0 * inv, o1 = w1 * inv;
                size_t ob = ((size_t)(b_ * TT + t)) * CC + h * HD + d;
                __nv_bfloat16 h0 = __float2bfloat16(o0);
                __nv_bfloat16 h1 = __float2bfloat16(o1);
                *(uint32_t*)(g_yhi + ob) = pack_bf2(h0, h1);
                *(uint32_t*)(g_ylo + ob) = pack_bf2(
                    __float2bfloat16(o0 - __bfloat162float(h0)),
                    __float2bfloat16(o1 - __bfloat162float(h1)));
            }
    }
}

// ---------------------------------------------------------------------------
extern "C" void kernel_launch(void* const* d_in, const int* in_sizes, int n_in,
                              void* d_out, int out_size)
{
    const float* x     = (const float*)d_in[0];
    const float* Wq    = (const float*)d_in[1];
    const float* bq    = (const float*)d_in[2];
    const float* Wk    = (const float*)d_in[3];
    const float* bk    = (const float*)d_in[4];
    const float* Wv    = (const float*)d_in[5];
    const float* bv    = (const float*)d_in[6];
    const float* Wo    = (const float*)d_in[7];
    const float* bo    = (const float*)d_in[8];
    const float* rel_k = (const float*)d_in[9];
    const float* rel_v = (const float*)d_in[10];
    float* out = (float*)d_out;

    cudaFuncSetAttribute(gemm_mma, cudaFuncAttributeMaxDynamicSharedMemorySize,
                         GT_SMEM);
    cudaFuncSetAttribute(proj_mma, cudaFuncAttributeMaxDynamicSharedMemorySize,
                         PJ_SMEM);
    cudaFuncSetAttribute(attn_mma, cudaFuncAttributeMaxDynamicSharedMemorySize,
                         FA_SMEM);

    conv_w<<<1024, 512>>>(Wq, Wk, Wv, Wo, bq, bk, bv, bo, rel_k);
    conv_split_x<<<1024, 512>>>(x, MM * CC / 4);
    gemm_mma<<<dim3(12, 64), 256, GT_SMEM>>>(nullptr, 1);
    conv_vt<<<dim3(16, 64), 256>>>();
    proj_mma<<<512, 256, PJ_SMEM>>>();
    attn_mma<<<dim3(8, 64), 256, FA_SMEM>>>(rel_v);
    gemm_mma<<<dim3(4, 64), 256, GT_SMEM>>>(out, 0);
}

// round 10
// speedup vs baseline: 2.6965x; 1.0214x over previous
#include <cuda_runtime.h>
#include <cuda_bf16.h>
#include <cstdint>

// Problem constants
#define BB   8
#define TT   1024
#define CC   512
#define HH   8
#define HD   64
#define NR   137
#define MAXR 68
#define BH   64
#define MM   8192
#define NRP  144

// ---------------------------------------------------------------------------
// Scratch (device globals)
// ---------------------------------------------------------------------------
static __device__ float g_proj[BH * TT * NR];
static __device__ float g_band[BH * TT * 136];          // raw logits, block-private rows

static __device__ __nv_bfloat16 g_qhi[BH * TT * HD];
static __device__ __nv_bfloat16 g_qlo[BH * TT * HD];
static __device__ __nv_bfloat16 g_khi[BH * TT * HD];
static __device__ __nv_bfloat16 g_klo[BH * TT * HD];
static __device__ __nv_bfloat16 g_vthi[BH * HD * TT];   // [bh][d][t]
static __device__ __nv_bfloat16 g_vtlo[BH * HD * TT];
static __device__ __nv_bfloat16 g_rkhi[NRP * HD];
static __device__ __nv_bfloat16 g_rklo[NRP * HD];

static __device__ __nv_bfloat16 g_xhi[MM * CC];
static __device__ __nv_bfloat16 g_xlo[MM * CC];
static __device__ __nv_bfloat16 g_yhi[MM * CC];
static __device__ __nv_bfloat16 g_ylo[MM * CC];
static __device__ __nv_bfloat16 g_wthi[4 * CC * CC];
static __device__ __nv_bfloat16 g_wtlo[4 * CC * CC];
static __device__ float g_bias[4 * CC];

// ---------------------------------------------------------------------------
// warp-MMA / async-copy helpers
// ---------------------------------------------------------------------------
__device__ __forceinline__ uint32_t smem_u32(const void* p) {
    uint32_t a;
    asm("{ .reg .u64 t; cvta.to.shared.u64 t, %1; cvt.u32.u64 %0, t; }"
        : "=r"(a) : "l"(p));
    return a;
}
__device__ __forceinline__ void ldsm4(uint32_t* r, uint32_t addr) {
    asm volatile("ldmatrix.sync.aligned.m8n8.x4.shared.b16 {%0,%1,%2,%3}, [%4];"
        : "=r"(r[0]), "=r"(r[1]), "=r"(r[2]), "=r"(r[3]) : "r"(addr));
}
__device__ __forceinline__ void ldsm2(uint32_t* r, uint32_t addr) {
    asm volatile("ldmatrix.sync.aligned.m8n8.x2.shared.b16 {%0,%1}, [%2];"
        : "=r"(r[0]), "=r"(r[1]) : "r"(addr));
}
__device__ __forceinline__ void mma16816(float* c, const uint32_t* a, const uint32_t* b) {
    asm volatile(
        "mma.sync.aligned.m16n8k16.row.col.f32.bf16.bf16.f32 "
        "{%0,%1,%2,%3}, {%4,%5,%6,%7}, {%8,%9}, {%0,%1,%2,%3};"
        : "+f"(c[0]), "+f"(c[1]), "+f"(c[2]), "+f"(c[3])
        : "r"(a[0]), "r"(a[1]), "r"(a[2]), "r"(a[3]), "r"(b[0]), "r"(b[1]));
}
#define SWZ128(b) ((b) ^ (((b) >> 3) & 0x70))

#define CP_A16(dst, src) \
    asm volatile("cp.async.cg.shared.global [%0], [%1], 16;" \
                 :: "r"(dst), "l"(src) : "memory")
#define CP_COMMIT() asm volatile("cp.async.commit_group;" ::: "memory")
#define CP_WAIT1()  asm volatile("cp.async.wait_group 1;" ::: "memory")
#define CP_WAIT0()  asm volatile("cp.async.wait_group 0;" ::: "memory")

__device__ __forceinline__ uint32_t pack_bf2(__nv_bfloat16 a, __nv_bfloat16 b) {
    __nv_bfloat162 t = {a, b};
    return *(uint32_t*)&t;
}

// ---------------------------------------------------------------------------
// conv_all: weight transpose/split + rel_k split + bias + x split (one launch)
// ---------------------------------------------------------------------------
__global__ __launch_bounds__(512) void conv_all(
    const float* __restrict__ x,
    const float* __restrict__ Wq, const float* __restrict__ Wk,
    const float* __restrict__ Wv, const float* __restrict__ Wo,
    const float* __restrict__ bq, const float* __restrict__ bk,
    const float* __restrict__ bv, const float* __restrict__ bo,
    const float* __restrict__ rel_k)
{
    int gid = blockIdx.x * blockDim.x + threadIdx.x;
    int nth = gridDim.x * blockDim.x;
    for (int idx = gid; idx < 4 * CC * CC; idx += nth) {
        int z = idx >> 18;
        int rem = idx & (CC * CC - 1);
        int k = rem >> 9, n = rem & 511;
        const float* W = (z == 0) ? Wq : (z == 1) ? Wk : (z == 2) ? Wv : Wo;
        float v = W[k * CC + n];
        __nv_bfloat16 h = __float2bfloat16(v);
        size_t dst = (size_t)z * CC * CC + (size_t)n * CC + k;
        g_wthi[dst] = h;
        g_wtlo[dst] = __float2bfloat16(v - __bfloat162float(h));
    }
    for (int i = gid; i < MM * CC / 4; i += nth) {
        float4 v = *(const float4*)(x + (size_t)i * 4);
        float vv[4] = {v.x, v.y, v.z, v.w};
        #pragma unroll
        for (int j = 0; j < 4; j++) {
            __nv_bfloat16 h = __float2bfloat16(vv[j]);
            g_xhi[(size_t)i * 4 + j] = h;
            g_xlo[(size_t)i * 4 + j] = __float2bfloat16(vv[j] - __bfloat162float(h));
        }
    }
    for (int idx = gid; idx < NRP * HD; idx += nth) {
        int r = idx >> 6, d = idx & 63;
        float v = (r < NR) ? rel_k[r * HD + d] : 0.0f;
        __nv_bfloat16 h = __float2bfloat16(v);
        g_rkhi[idx] = h;
        g_rklo[idx] = __float2bfloat16(v - __bfloat162float(h));
    }
    if (gid < 4 * CC) {
        int z = gid >> 9, n = gid & 511;
        const float* bsrc = (z == 0) ? bq : (z == 1) ? bk : (z == 2) ? bv : bo;
        g_bias[gid] = bsrc[n];
    }
}

// ---------------------------------------------------------------------------
// bf16x3 warp-MMA GEMM, 2-stage cp.async pipeline (stage-paired 128B rows)
// K-chunk = 32; stage s occupies byte cols [s*64, s*64+64) of each row.
// mode 1: A = x, B = W_{q,k,v}; q,k -> bf16 hi/lo (b,h,t,d); v -> vt hi/lo [bh][d][t]
// mode 0: A = y, B = W_o -> fp32 out
// ---------------------------------------------------------------------------
#define GT_A_HI 0
#define GT_A_LO 16384
#define GT_B_HI 32768
#define GT_B_LO 49152
#define GT_SMEM 65536

__global__ __launch_bounds__(256, 2) void gemm_mma(float* __restrict__ outp, int mode)
{
    extern __shared__ char smc[];
    const __nv_bfloat16 *Ahi, *Alo, *Bhi, *Blo;
    const float* bias;
    if (mode == 1) {
        Ahi = g_xhi; Alo = g_xlo; Bhi = g_wthi; Blo = g_wtlo; bias = g_bias;
    } else {
        Ahi = g_yhi; Alo = g_ylo;
        Bhi = g_wthi + 3 * CC * CC; Blo = g_wtlo + 3 * CC * CC;
        bias = g_bias + 3 * CC;
    }

    int tid = threadIdx.x, lane = tid & 31, wid = tid >> 5;
    int wm = wid >> 2, wn = wid & 3;
    int row0 = blockIdx.y * 128, col0 = blockIdx.x * 128;

    uint32_t uAH = smem_u32(smc + GT_A_HI);
    uint32_t uAL = smem_u32(smc + GT_A_LO);
    uint32_t uBH = smem_u32(smc + GT_B_HI);
    uint32_t uBL = smem_u32(smc + GT_B_LO);

    float c[4][4][4];
    #pragma unroll
    for (int mi = 0; mi < 4; mi++)
        #pragma unroll
        for (int ni = 0; ni < 4; ni++)
            #pragma unroll
            for (int e = 0; e < 4; e++) c[mi][ni][e] = 0.0f;

    // chunk loader: K-chunk kc (32 elems) into stage kc&1
    auto load_chunk = [&](int kc) {
        int k0 = kc * 32;
        int sb64 = (kc & 1) * 64;
        #pragma unroll
        for (int s2 = 0; s2 < 2; s2++) {
            int vec = tid + s2 * 256;              // 0..511
            int idx = vec >> 2, v4 = vec & 3;
            // interleave rows (r, r+4) within a phase for conflict-free stores
            int r = (idx & ~7) | ((idx & 1) << 2) | ((idx >> 1) & 3);
            uint32_t dst = SWZ128((uint32_t)(r * 128 + sb64 + v4 * 16));
            size_t asrc = (size_t)(row0 + r) * CC + k0 + v4 * 8;
            size_t bsrc = (size_t)(col0 + r) * CC + k0 + v4 * 8;
            CP_A16(uAH + dst, Ahi + asrc);
            CP_A16(uAL + dst, Alo + asrc);
            CP_A16(uBH + dst, Bhi + bsrc);
            CP_A16(uBL + dst, Blo + bsrc);
        }
        CP_COMMIT();
    };

    load_chunk(0);
    load_chunk(1);

    for (int kc = 0; kc < 16; kc++) {
        if (kc < 15) { CP_WAIT1(); } else { CP_WAIT0(); }
        __syncthreads();

        int sbe = (kc & 1) * 32;                   // stage base in elements
        #pragma unroll
        for (int ks = 0; ks < 2; ks++) {
            int kbase = sbe + ks * 16;
            int lp = lane & 15;
            int bkb = kbase + (lp >> 3) * 8;
            uint32_t bh[4][2], bl[4][2];
            #pragma unroll
            for (int ni = 0; ni < 4; ni++) {
                int nloc = wn * 32 + ni * 8 + (lp & 7);
                uint32_t ad = SWZ128((uint32_t)(nloc * 128 + bkb * 2));
                ldsm2(bh[ni], uBH + ad);
                ldsm2(bl[ni], uBL + ad);
            }
            int akb = kbase + (lane >> 4) * 8;
            int mlp = lane & 15;
            #pragma unroll
            for (int mi = 0; mi < 4; mi++) {
                int mloc = wm * 64 + mi * 16 + mlp;
                uint32_t ad = SWZ128((uint32_t)(mloc * 128 + akb * 2));
                uint32_t ah[4], al[4];
                ldsm4(ah, uAH + ad);
                ldsm4(al, uAL + ad);
                #pragma unroll
                for (int ni = 0; ni < 4; ni++) {
                    mma16816(c[mi][ni], ah, bh[ni]);
                    mma16816(c[mi][ni], ah, bl[ni]);
                    mma16816(c[mi][ni], al, bh[ni]);
                }
            }
        }
        __syncthreads();
        if (kc + 2 < 16) load_chunk(kc + 2);
    }

    int r_base = row0 + wm * 64 + (lane >> 2);
    int n_base = col0 + wn * 32 + (lane & 3) * 2;

    if (mode == 0) {
        #pragma unroll
        for (int mi = 0; mi < 4; mi++) {
            int r = r_base + mi * 16;
            #pragma unroll
            for (int ni = 0; ni < 4; ni++) {
                int n = n_base + ni * 8;
                float b0 = bias[n], b1 = bias[n + 1];
                float2 v0 = make_float2(c[mi][ni][0] + b0, c[mi][ni][1] + b1);
                float2 v1 = make_float2(c[mi][ni][2] + b0, c[mi][ni][3] + b1);
                *(float2*)(outp + (size_t)r * CC + n)       = v0;
                *(float2*)(outp + (size_t)(r + 8) * CC + n) = v1;
            }
        }
    } else {
        int z = col0 >> 9;
        #pragma unroll
        for (int mi = 0; mi < 4; mi++) {
            int r = r_base + mi * 16;
            int b_ = r >> 10, t = r & (TT - 1);
            #pragma unroll
            for (int ni = 0; ni < 4; ni++) {
                int n = n_base + ni * 8;
                int nn = n & 511;
                int h = nn >> 6, d = nn & 63;
                float b0 = bias[n], b1 = bias[n + 1];
                float p00 = c[mi][ni][0] + b0, p01 = c[mi][ni][1] + b1;
                float p10 = c[mi][ni][2] + b0, p11 = c[mi][ni][3] + b1;
                __nv_bfloat16 h00 = __float2bfloat16(p00);
                __nv_bfloat16 h01 = __float2bfloat16(p01);
                __nv_bfloat16 h10 = __float2bfloat16(p10);
                __nv_bfloat16 h11 = __float2bfloat16(p11);
                __nv_bfloat16 l00 = __float2bfloat16(p00 - __bfloat162float(h00));
                __nv_bfloat16 l01 = __float2bfloat16(p01 - __bfloat162float(h01));
                __nv_bfloat16 l10 = __float2bfloat16(p10 - __bfloat162float(h10));
                __nv_bfloat16 l11 = __float2bfloat16(p11 - __bfloat162float(h11));
                if (z == 2) {
                    // transposed vt [bh][d][t] scalar stores
                    size_t vb = (((size_t)(b_ * HH + h)) * HD + d) * TT + t;
                    g_vthi[vb]          = h00;
                    g_vthi[vb + TT]     = h01;   // d+1
                    g_vthi[vb + 8]      = h10;   // t+8
                    g_vthi[vb + TT + 8] = h11;
                    g_vtlo[vb]          = l00;
                    g_vtlo[vb + TT]     = l01;
                    g_vtlo[vb + 8]      = l10;
                    g_vtlo[vb + TT + 8] = l11;
                } else {
                    __nv_bfloat16* dhi = (z == 0) ? g_qhi : g_khi;
                    __nv_bfloat16* dlo = (z == 0) ? g_qlo : g_klo;
                    size_t o = (((size_t)b_ * HH + h) * TT + t) * HD + d;
                    *(uint32_t*)(dhi + o)          = pack_bf2(h00, h01);
                    *(uint32_t*)(dhi + o + 8 * HD) = pack_bf2(h10, h11);
                    *(uint32_t*)(dlo + o)          = pack_bf2(l00, l01);
                    *(uint32_t*)(dlo + o + 8 * HD) = pack_bf2(l10, l11);
                }
            }
        }
    }
}

// ---------------------------------------------------------------------------
// proj_mma — unchanged
// ---------------------------------------------------------------------------
#define PJ_Q_HI 0
#define PJ_Q_LO 16384
#define PJ_R_HI 32768
#define PJ_R_LO (32768 + NRP * 128)
#define PJ_SMEM (32768 + 2 * NRP * 128)

__global__ __launch_bounds__(256) void proj_mma()
{
    extern __shared__ char smc[];
    int tid = threadIdx.x, lane = tid & 31, wid = tid >> 5;
    int t0 = blockIdx.x * 128;

    uint32_t sQH = smem_u32(smc + PJ_Q_HI);
    uint32_t sQL = smem_u32(smc + PJ_Q_LO);
    uint32_t sRH = smem_u32(smc + PJ_R_HI);
    uint32_t sRL = smem_u32(smc + PJ_R_LO);

    #pragma unroll
    for (int s = 0; s < 4; s++) {
        int vec = tid + s * 256;
        int r = vec >> 3, g8 = vec & 7;
        uint32_t dst = SWZ128((uint32_t)(r * 128 + g8 * 16));
        size_t src = (size_t)(t0 + r) * HD + g8 * 8;
        *(uint4*)(smc + PJ_Q_HI + dst) = *(const uint4*)(g_qhi + src);
        *(uint4*)(smc + PJ_Q_LO + dst) = *(const uint4*)(g_qlo + src);
    }
    for (int vec = tid; vec < NRP * 8; vec += 256) {
        int r = vec >> 3, g8 = vec & 7;
        uint32_t dst = SWZ128((uint32_t)(r * 128 + g8 * 16));
        size_t src = (size_t)r * HD + g8 * 8;
        *(uint4*)(smc + PJ_R_HI + dst) = *(const uint4*)(g_rkhi + src);
        *(uint4*)(smc + PJ_R_LO + dst) = *(const uint4*)(g_rklo + src);
    }
    __syncthreads();

    float c[9][2][4];
    #pragma unroll
    for (int nf = 0; nf < 9; nf++)
        #pragma unroll
        for (int p = 0; p < 2; p++)
            #pragma unroll
            for (int e = 0; e < 4; e++) c[nf][p][e] = 0.0f;

    #pragma unroll
    for (int ks = 0; ks < 4; ks++) {
        int kbase = ks * 16;
        int akb = kbase + (lane >> 4) * 8;
        uint32_t aad = SWZ128((uint32_t)((wid * 16 + (lane & 15)) * 128 + akb * 2));
        uint32_t ah[4], al[4];
        ldsm4(ah, sQH + aad);
        ldsm4(al, sQL + aad);

        int br_off = (lane & 7) + ((lane >> 4) << 3);
        int bk = kbase + (((lane >> 3) & 1) << 3);
        #pragma unroll
        for (int nf = 0; nf < 9; nf++) {
            uint32_t bad = SWZ128((uint32_t)((nf * 16 + br_off) * 128 + bk * 2));
            uint32_t bh4[4], bl4[4];
            ldsm4(bh4, sRH + bad);
            ldsm4(bl4, sRL + bad);
            mma16816(c[nf][0], ah, bh4);
            mma16816(c[nf][0], ah, bl4);
            mma16816(c[nf][0], al, bh4);
            mma16816(c[nf][1], ah, bh4 + 2);
            mma16816(c[nf][1], ah, bl4 + 2);
            mma16816(c[nf][1], al, bh4 + 2);
        }
    }

    #pragma unroll
    for (int e2 = 0; e2 < 2; e2++) {
        int row = t0 + wid * 16 + (lane >> 2) + e2 * 8;
        float* prow = g_proj + (size_t)row * NR;
        #pragma unroll
        for (int nf = 0; nf < 9; nf++)
            #pragma unroll
            for (int p = 0; p < 2; p++) {
                int col = nf * 16 + p * 8 + (lane & 3) * 2;
                if (col < NR)     prow[col]     = c[nf][p][e2 * 2];
                if (col + 1 < NR) prow[col + 1] = c[nf][p][e2 * 2 + 1];
            }
    }
}

// ---------------------------------------------------------------------------
// attn_mma: fused S-MMA + online softmax + PV-MMA + band/rel_v epilogue
// (unchanged from R9)
// ---------------------------------------------------------------------------
#define FA_QHI 0
#define FA_QLO 16384
#define FA_KHI 32768
#define FA_KLO 40960
#define FA_VHI 49152
#define FA_VLO 57344
#define FA_PHI 65536
#define FA_PLO 81920
#define FA_SMEM 98304

__global__ __launch_bounds__(256, 2) void attn_mma(const float* __restrict__ rel_v)
{
    extern __shared__ char smc[];
    int tid = threadIdx.x, lane = tid & 31, wid = tid >> 5;
    int bh = blockIdx.y, t0 = blockIdx.x * 128;

    uint32_t uQH = smem_u32(smc + FA_QHI);
    uint32_t uQL = smem_u32(smc + FA_QLO);
    uint32_t uKH = smem_u32(smc + FA_KHI);
    uint32_t uKL = smem_u32(smc + FA_KLO);
    uint32_t uVH = smem_u32(smc + FA_VHI);
    uint32_t uVL = smem_u32(smc + FA_VLO);
    uint32_t uPH = smem_u32(smc + FA_PHI);
    uint32_t uPL = smem_u32(smc + FA_PLO);

    size_t qb = (size_t)bh * TT * HD;
    size_t vtb = (size_t)bh * HD * TT;
    float* bandb = g_band + ((size_t)bh * TT + t0) * 136;

    #pragma unroll
    for (int s = 0; s < 4; s++) {
        int vec = tid + s * 256;
        int r = vec >> 3, g8 = vec & 7;
        uint32_t dst = SWZ128((uint32_t)(r * 128 + g8 * 16));
        size_t src = qb + (size_t)(t0 + r) * HD + g8 * 8;
        *(uint4*)(smc + FA_QHI + dst) = *(const uint4*)(g_qhi + src);
        *(uint4*)(smc + FA_QLO + dst) = *(const uint4*)(g_qlo + src);
    }
    for (int idx = tid; idx < 128 * 136; idx += 256) bandb[idx] = -1e30f;

    float m[2] = {-1e30f, -1e30f}, l[2] = {0.0f, 0.0f}, plo[2] = {0.0f, 0.0f};
    float c[4][2][4];
    #pragma unroll
    for (int nf = 0; nf < 4; nf++)
        #pragma unroll
        for (int p = 0; p < 2; p++)
            #pragma unroll
            for (int e = 0; e < 4; e++) c[nf][p][e] = 0.0f;

    const float scale = 0.044194173824159216f;
    int rbase = wid * 16 + (lane >> 2);

    for (int kc = 0; kc < 16; kc++) {
        int k0 = kc * 64;
        __syncthreads();

        #pragma unroll
        for (int s = 0; s < 2; s++) {
            int vec = tid + s * 256;
            int r = vec >> 3, g8 = vec & 7;
            uint32_t dst = SWZ128((uint32_t)(r * 128 + g8 * 16));
            size_t ksrc = qb + (size_t)(k0 + r) * HD + g8 * 8;
            size_t vsrc = vtb + (size_t)r * TT + k0 + g8 * 8;
            *(uint4*)(smc + FA_KHI + dst) = *(const uint4*)(g_khi + ksrc);
            *(uint4*)(smc + FA_KLO + dst) = *(const uint4*)(g_klo + ksrc);
            *(uint4*)(smc + FA_VHI + dst) = *(const uint4*)(g_vthi + vsrc);
            *(uint4*)(smc + FA_VLO + dst) = *(const uint4*)(g_vtlo + vsrc);
        }
        __syncthreads();

        float cs[4][2][4];
        #pragma unroll
        for (int nf = 0; nf < 4; nf++)
            #pragma unroll
            for (int p = 0; p < 2; p++)
                #pragma unroll
                for (int e = 0; e < 4; e++) cs[nf][p][e] = 0.0f;

        #pragma unroll
        for (int ks = 0; ks < 4; ks++) {
            uint32_t aad = SWZ128((uint32_t)(
                (wid * 16 + (lane & 15)) * 128 + (ks * 16 + (lane >> 4) * 8) * 2));
            uint32_t ah[4], al[4];
            ldsm4(ah, uQH + aad);
            ldsm4(al, uQL + aad);
            int br_off = (lane & 7) + ((lane >> 4) << 3);
            int bk = ks * 16 + (((lane >> 3) & 1) << 3);
            #pragma unroll
            for (int nf = 0; nf < 4; nf++) {
                uint32_t bad = SWZ128((uint32_t)((nf * 16 + br_off) * 128 + bk * 2));
                uint32_t bh4[4], bl4[4];
                ldsm4(bh4, uKH + bad);
                ldsm4(bl4, uKL + bad);
                mma16816(cs[nf][0], ah, bh4);
                mma16816(cs[nf][0], ah, bl4);
                mma16816(cs[nf][0], al, bh4);
                mma16816(cs[nf][1], ah, bh4 + 2);
                mma16816(cs[nf][1], ah, bl4 + 2);
                mma16816(cs[nf][1], al, bh4 + 2);
            }
        }

        #pragma unroll
        for (int e2 = 0; e2 < 2; e2++) {
            int rowl = rbase + e2 * 8;
            int trow = t0 + rowl;
            const float* prow = g_proj + ((size_t)bh * TT + trow) * NR;
            float mx = -1e30f;
            #pragma unroll
            for (int nf = 0; nf < 4; nf++)
                #pragma unroll
                for (int p = 0; p < 2; p++)
                    #pragma unroll
                    for (int j = 0; j < 2; j++) {
                        int kg = k0 + nf * 16 + p * 8 + (lane & 3) * 2 + j;
                        int dist = kg - trow;
                        dist = dist < -MAXR ? -MAXR : (dist > MAXR ? MAXR : dist);
                        float v = (cs[nf][p][e2 * 2 + j] + prow[dist + MAXR]) * scale;
                        cs[nf][p][e2 * 2 + j] = v;
                        mx = fmaxf(mx, v);
                    }
            mx = fmaxf(mx, __shfl_xor_sync(0xffffffffu, mx, 1));
            mx = fmaxf(mx, __shfl_xor_sync(0xffffffffu, mx, 2));
            float mnew = fmaxf(m[e2], mx);
            float f = __expf(m[e2] - mnew);
            m[e2] = mnew;
            l[e2] *= f; plo[e2] *= f;
            #pragma unroll
            for (int nf = 0; nf < 4; nf++)
                #pragma unroll
                for (int p = 0; p < 2; p++) {
                    c[nf][p][e2 * 2]     *= f;
                    c[nf][p][e2 * 2 + 1] *= f;
                }

            float es = 0.0f, pl = 0.0f;
            #pragma unroll
            for (int nf = 0; nf < 4; nf++)
                #pragma unroll
                for (int p = 0; p < 2; p++) {
                    float v0 = cs[nf][p][e2 * 2], v1 = cs[nf][p][e2 * 2 + 1];
                    float p0 = __expf(v0 - mnew), p1 = __expf(v1 - mnew);
                    es += p0 + p1;
                    int kcol = nf * 16 + p * 8 + (lane & 3) * 2;
                    int d0 = (k0 + kcol) - trow;
                    if ((unsigned)(d0 + 67) <= 134u) bandb[rowl * 136 + d0 + 67] = v0;
                    else if (d0 <= -MAXR) pl += p0;
                    int d1 = d0 + 1;
                    if ((unsigned)(d1 + 67) <= 134u) bandb[rowl * 136 + d1 + 67] = v1;
                    else if (d1 <= -MAXR) pl += p1;

                    __nv_bfloat16 h0 = __float2bfloat16(p0);
                    __nv_bfloat16 h1 = __float2bfloat16(p1);
                    uint32_t dst = SWZ128((uint32_t)(rowl * 128 + kcol * 2));
                    *(uint32_t*)(smc + FA_PHI + dst) = pack_bf2(h0, h1);
                    *(uint32_t*)(smc + FA_PLO + dst) = pack_bf2(
                        __float2bfloat16(p0 - __bfloat162float(h0)),
                        __float2bfloat16(p1 - __bfloat162float(h1)));
                }
            es += __shfl_xor_sync(0xffffffffu, es, 1);
            es += __shfl_xor_sync(0xffffffffu, es, 2);
            pl += __shfl_xor_sync(0xffffffffu, pl, 1);
            pl += __shfl_xor_sync(0xffffffffu, pl, 2);
            l[e2] += es; plo[e2] += pl;
        }
        __syncwarp();

        #pragma unroll
        for (int ks = 0; ks < 4; ks++) {
            uint32_t aad = SWZ128((uint32_t)(
                (wid * 16 + (lane & 15)) * 128 + (ks * 16 + (lane >> 4) * 8) * 2));
            uint32_t ah[4], al[4];
            ldsm4(ah, uPH + aad);
            ldsm4(al, uPL + aad);
            int br_off = (lane & 7) + ((lane >> 4) << 3);
            int bk = ks * 16 + (((lane >> 3) & 1) << 3);
            #pragma unroll
            for (int nf = 0; nf < 4; nf++) {
                uint32_t bad = SWZ128((uint32_t)((nf * 16 + br_off) * 128 + bk * 2));
                uint32_t bh4[4], bl4[4];
                ldsm4(bh4, uVH + bad);
                ldsm4(bl4, uVL + bad);
                mma16816(c[nf][0], ah, bh4);
                mma16816(c[nf][0], ah, bl4);
                mma16816(c[nf][0], al, bh4);
                mma16816(c[nf][1], ah, bh4 + 2);
                mma16816(c[nf][1], ah, bl4 + 2);
                mma16816(c[nf][1], al, bh4 + 2);
            }
        }
    }

    __syncthreads();
    float* rvs = (float*)smc;
    for (int idx = tid * 4; idx < NR * 64; idx += 1024)
        *(float4*)(rvs + idx) = *(const float4*)(rel_v + idx);
    __syncthreads();

    float intu[2] = {0.0f, 0.0f};
    for (int r = 1; r <= 135; r++) {
        #pragma unroll
        for (int e2 = 0; e2 < 2; e2++) {
            int rowl = rbase + e2 * 8;
            float sv = __expf(bandb[rowl * 136 + r - 1] - m[e2]);
            intu[e2] += sv;
            #pragma unroll
            for (int nf = 0; nf < 4; nf++)
                #pragma unroll
                for (int p = 0; p < 2; p++) {
                    int d = nf * 16 + p * 8 + (lane & 3) * 2;
                    float2 rv = *(float2*)(rvs + r * 64 + d);
                    c[nf][p][e2 * 2]     += sv * rv.x;
                    c[nf][p][e2 * 2 + 1] += sv * rv.y;
                }
        }
    }

    int b_ = bh >> 3, h = bh & 7;
    #pragma unroll
    for (int e2 = 0; e2 < 2; e2++) {
        int rowl = rbase + e2 * 8;
        int t = t0 + rowl;
        float lr = l[e2], pl = plo[e2];
        float phi = lr - pl - intu[e2];
        float inv = 1.0f / lr;
        #pragma unroll
        for (int nf = 0; nf < 4; nf++)
            #pragma unroll
            for (int p = 0; p < 2; p++) {
                int d = nf * 16 + p * 8 + (lane & 3) * 2;
                float w0 = c[nf][p][e2 * 2]     + pl * rvs[d]
                         + phi * rvs[136 * 64 + d];
                float w1 = c[nf][p][e2 * 2 + 1] + pl * rvs[d + 1]
                         + phi * rvs[136 * 64 + d + 1];
                float o0 = w0 * inv, o1 = w1 * inv;
                size_t ob = ((size_t)(b_ * TT + t)) * CC + h * HD + d;
                __nv_bfloat16 h0 = __float2bfloat16(o0);
                __nv_bfloat16 h1 = __float2bfloat16(o1);
                *(uint32_t*)(g_yhi + ob) = pack_bf2(h0, h1);
                *(uint32_t*)(g_ylo + ob) = pack_bf2(
                    __float2bfloat16(o0 - __bfloat162float(h0)),
                    __float2bfloat16(o1 - __bfloat162float(h1)));
            }
    }
}

// ---------------------------------------------------------------------------
extern "C" void kernel_launch(void* const* d_in, const int* in_sizes, int n_in,
                              void* d_out, int out_size)
{
    const float* x     = (const float*)d_in[0];
    const float* Wq    = (const float*)d_in[1];
    const float* bq    = (const float*)d_in[2];
    const float* Wk    = (const float*)d_in[3];
    const float* bk    = (const float*)d_in[4];
    const float* Wv    = (const float*)d_in[5];
    const float* bv    = (const float*)d_in[6];
    const float* Wo    = (const float*)d_in[7];
    const float* bo    = (const float*)d_in[8];
    const float* rel_k = (const float*)d_in[9];
    const float* rel_v = (const float*)d_in[10];
    float* out = (float*)d_out;

    cudaFuncSetAttribute(gemm_mma, cudaFuncAttributeMaxDynamicSharedMemorySize,
                         GT_SMEM);
    cudaFuncSetAttribute(proj_mma, cudaFuncAttributeMaxDynamicSharedMemorySize,
                         PJ_SMEM);
    cudaFuncSetAttribute(attn_mma, cudaFuncAttributeMaxDynamicSharedMemorySize,
                         FA_SMEM);

    conv_all<<<1024, 512>>>(x, Wq, Wk, Wv, Wo, bq, bk, bv, bo, rel_k);
    gemm_mma<<<dim3(12, 64), 256, GT_SMEM>>>(nullptr, 1);
    proj_mma<<<512, 256, PJ_SMEM>>>();
    attn_mma<<<dim3(8, 64), 256, FA_SMEM>>>(rel_v);
    gemm_mma<<<dim3(4, 64), 256, GT_SMEM>>>(out, 0);
}

// round 12
// speedup vs baseline: 2.9309x; 1.0869x over previous
#include <cuda_runtime.h>
#include <cuda_bf16.h>
#include <cstdint>

// Problem constants
#define BB   8
#define TT   1024
#define CC   512
#define HH   8
#define HD   64
#define NR   137
#define MAXR 68
#define BH   64
#define MM   8192
#define NRP  144

// ---------------------------------------------------------------------------
// Scratch (device globals)
// ---------------------------------------------------------------------------
static __device__ float g_proj[BH * TT * NR];
static __device__ float g_band[BH * TT * 136];          // raw logits, block-private rows
static __device__ float g_rv0[HD];                      // rel_v row 0
static __device__ float g_rv136[HD];                    // rel_v row 136

static __device__ __nv_bfloat16 g_qhi[BH * TT * HD];
static __device__ __nv_bfloat16 g_qlo[BH * TT * HD];
static __device__ __nv_bfloat16 g_khi[BH * TT * HD];
static __device__ __nv_bfloat16 g_klo[BH * TT * HD];
static __device__ __nv_bfloat16 g_vthi[BH * HD * TT];   // [bh][d][t]
static __device__ __nv_bfloat16 g_vtlo[BH * HD * TT];
static __device__ __nv_bfloat16 g_rkhi[NRP * HD];
static __device__ __nv_bfloat16 g_rklo[NRP * HD];
static __device__ __nv_bfloat16 g_rvthi[HD * 192];      // rvt[d][j] = rel_v[j+1][d], j<135
static __device__ __nv_bfloat16 g_rvtlo[HD * 192];

static __device__ __nv_bfloat16 g_xhi[MM * CC];
static __device__ __nv_bfloat16 g_xlo[MM * CC];
static __device__ __nv_bfloat16 g_yhi[MM * CC];
static __device__ __nv_bfloat16 g_ylo[MM * CC];
static __device__ __nv_bfloat16 g_wthi[4 * CC * CC];
static __device__ __nv_bfloat16 g_wtlo[4 * CC * CC];
static __device__ float g_bias[4 * CC];

// ---------------------------------------------------------------------------
// warp-MMA / async-copy helpers
// ---------------------------------------------------------------------------
__device__ __forceinline__ uint32_t smem_u32(const void* p) {
    uint32_t a;
    asm("{ .reg .u64 t; cvta.to.shared.u64 t, %1; cvt.u32.u64 %0, t; }"
        : "=r"(a) : "l"(p));
    return a;
}
__device__ __forceinline__ void ldsm4(uint32_t* r, uint32_t addr) {
    asm volatile("ldmatrix.sync.aligned.m8n8.x4.shared.b16 {%0,%1,%2,%3}, [%4];"
        : "=r"(r[0]), "=r"(r[1]), "=r"(r[2]), "=r"(r[3]) : "r"(addr));
}
__device__ __forceinline__ void ldsm2(uint32_t* r, uint32_t addr) {
    asm volatile("ldmatrix.sync.aligned.m8n8.x2.shared.b16 {%0,%1}, [%2];"
        : "=r"(r[0]), "=r"(r[1]) : "r"(addr));
}
__device__ __forceinline__ void mma16816(float* c, const uint32_t* a, const uint32_t* b) {
    asm volatile(
        "mma.sync.aligned.m16n8k16.row.col.f32.bf16.bf16.f32 "
        "{%0,%1,%2,%3}, {%4,%5,%6,%7}, {%8,%9}, {%0,%1,%2,%3};"
        : "+f"(c[0]), "+f"(c[1]), "+f"(c[2]), "+f"(c[3])
        : "r"(a[0]), "r"(a[1]), "r"(a[2]), "r"(a[3]), "r"(b[0]), "r"(b[1]));
}
#define SWZ128(b) ((b) ^ (((b) >> 3) & 0x70))

#define CP_A16(dst, src) \
    asm volatile("cp.async.cg.shared.global [%0], [%1], 16;" \
                 :: "r"(dst), "l"(src) : "memory")
#define CP_COMMIT() asm volatile("cp.async.commit_group;" ::: "memory")
#define CP_WAIT1()  asm volatile("cp.async.wait_group 1;" ::: "memory")
#define CP_WAIT0()  asm volatile("cp.async.wait_group 0;" ::: "memory")

__device__ __forceinline__ uint32_t pack_bf2(__nv_bfloat16 a, __nv_bfloat16 b) {
    __nv_bfloat162 t = {a, b};
    return *(uint32_t*)&t;
}

// ---------------------------------------------------------------------------
// conv_edge: rel_v edge rows to fp32 globals
// ---------------------------------------------------------------------------
__global__ void conv_edge(const float* __restrict__ rel_v)
{
    int d = threadIdx.x;
    if (d < HD) {
        g_rv0[d]   = rel_v[d];
        g_rv136[d] = rel_v[136 * HD + d];
    }
}

// ---------------------------------------------------------------------------
// conv_all: weights/x/rel_k/rel_v conversion (one launch)
// ---------------------------------------------------------------------------
__global__ __launch_bounds__(512) void conv_all(
    const float* __restrict__ x,
    const float* __restrict__ Wq, const float* __restrict__ Wk,
    const float* __restrict__ Wv, const float* __restrict__ Wo,
    const float* __restrict__ bq, const float* __restrict__ bk,
    const float* __restrict__ bv, const float* __restrict__ bo,
    const float* __restrict__ rel_k, const float* __restrict__ rel_v)
{
    int gid = blockIdx.x * blockDim.x + threadIdx.x;
    int nth = gridDim.x * blockDim.x;
    for (int idx = gid; idx < 4 * CC * CC; idx += nth) {
        int z = idx >> 18;
        int rem = idx & (CC * CC - 1);
        int k = rem >> 9, n = rem & 511;
        const float* W = (z == 0) ? Wq : (z == 1) ? Wk : (z == 2) ? Wv : Wo;
        float v = W[k * CC + n];
        __nv_bfloat16 h = __float2bfloat16(v);
        size_t dst = (size_t)z * CC * CC + (size_t)n * CC + k;
        g_wthi[dst] = h;
        g_wtlo[dst] = __float2bfloat16(v - __bfloat162float(h));
    }
    for (int i = gid; i < MM * CC / 4; i += nth) {
        float4 v = *(const float4*)(x + (size_t)i * 4);
        float vv[4] = {v.x, v.y, v.z, v.w};
        #pragma unroll
        for (int j = 0; j < 4; j++) {
            __nv_bfloat16 h = __float2bfloat16(vv[j]);
            g_xhi[(size_t)i * 4 + j] = h;
            g_xlo[(size_t)i * 4 + j] = __float2bfloat16(vv[j] - __bfloat162float(h));
        }
    }
    for (int idx = gid; idx < NRP * HD; idx += nth) {
        int r = idx >> 6, d = idx & 63;
        float v = (r < NR) ? rel_k[r * HD + d] : 0.0f;
        __nv_bfloat16 h = __float2bfloat16(v);
        g_rkhi[idx] = h;
        g_rklo[idx] = __float2bfloat16(v - __bfloat162float(h));
    }
    for (int idx = gid; idx < HD * 192; idx += nth) {
        int d = idx / 192, j = idx - d * 192;
        float v = (j < 135) ? rel_v[(j + 1) * HD + d] : 0.0f;
        __nv_bfloat16 h = __float2bfloat16(v);
        g_rvthi[idx] = h;
        g_rvtlo[idx] = __float2bfloat16(v - __bfloat162float(h));
    }
    if (gid < 4 * CC) {
        int z = gid >> 9, n = gid & 511;
        const float* bsrc = (z == 0) ? bq : (z == 1) ? bk : (z == 2) ? bv : bo;
        g_bias[gid] = bsrc[n];
    }
}

// ---------------------------------------------------------------------------
// bf16x3 warp-MMA GEMM, 2-stage cp.async pipeline
// ---------------------------------------------------------------------------
#define GT_A_HI 0
#define GT_A_LO 16384
#define GT_B_HI 32768
#define GT_B_LO 49152
#define GT_SMEM 65536

__global__ __launch_bounds__(256, 2) void gemm_mma(float* __restrict__ outp, int mode)
{
    extern __shared__ char smc[];
    const __nv_bfloat16 *Ahi, *Alo, *Bhi, *Blo;
    const float* bias;
    if (mode == 1) {
        Ahi = g_xhi; Alo = g_xlo; Bhi = g_wthi; Blo = g_wtlo; bias = g_bias;
    } else {
        Ahi = g_yhi; Alo = g_ylo;
        Bhi = g_wthi + 3 * CC * CC; Blo = g_wtlo + 3 * CC * CC;
        bias = g_bias + 3 * CC;
    }

    int tid = threadIdx.x, lane = tid & 31, wid = tid >> 5;
    int wm = wid >> 2, wn = wid & 3;
    int row0 = blockIdx.y * 128, col0 = blockIdx.x * 128;

    uint32_t uAH = smem_u32(smc + GT_A_HI);
    uint32_t uAL = smem_u32(smc + GT_A_LO);
    uint32_t uBH = smem_u32(smc + GT_B_HI);
    uint32_t uBL = smem_u32(smc + GT_B_LO);

    float c[4][4][4];
    #pragma unroll
    for (int mi = 0; mi < 4; mi++)
        #pragma unroll
        for (int ni = 0; ni < 4; ni++)
            #pragma unroll
            for (int e = 0; e < 4; e++) c[mi][ni][e] = 0.0f;

    auto load_chunk = [&](int kc) {
        int k0 = kc * 32;
        int sb64 = (kc & 1) * 64;
        #pragma unroll
        for (int s2 = 0; s2 < 2; s2++) {
            int vec = tid + s2 * 256;
            int idx = vec >> 2, v4 = vec & 3;
            int r = (idx & ~7) | ((idx & 1) << 2) | ((idx >> 1) & 3);
            uint32_t dst = SWZ128((uint32_t)(r * 128 + sb64 + v4 * 16));
            size_t asrc = (size_t)(row0 + r) * CC + k0 + v4 * 8;
            size_t bsrc = (size_t)(col0 + r) * CC + k0 + v4 * 8;
            CP_A16(uAH + dst, Ahi + asrc);
            CP_A16(uAL + dst, Alo + asrc);
            CP_A16(uBH + dst, Bhi + bsrc);
            CP_A16(uBL + dst, Blo + bsrc);
        }
        CP_COMMIT();
    };

    load_chunk(0);
    load_chunk(1);

    for (int kc = 0; kc < 16; kc++) {
        if (kc < 15) { CP_WAIT1(); } else { CP_WAIT0(); }
        __syncthreads();

        int sbe = (kc & 1) * 32;
        #pragma unroll
        for (int ks = 0; ks < 2; ks++) {
            int kbase = sbe + ks * 16;
            int lp = lane & 15;
            int bkb = kbase + (lp >> 3) * 8;
            uint32_t bh[4][2], bl[4][2];
            #pragma unroll
            for (int ni = 0; ni < 4; ni++) {
                int nloc = wn * 32 + ni * 8 + (lp & 7);
                uint32_t ad = SWZ128((uint32_t)(nloc * 128 + bkb * 2));
                ldsm2(bh[ni], uBH + ad);
                ldsm2(bl[ni], uBL + ad);
            }
            int akb = kbase + (lane >> 4) * 8;
            int mlp = lane & 15;
            #pragma unroll
            for (int mi = 0; mi < 4; mi++) {
                int mloc = wm * 64 + mi * 16 + mlp;
                uint32_t ad = SWZ128((uint32_t)(mloc * 128 + akb * 2));
                uint32_t ah[4], al[4];
                ldsm4(ah, uAH + ad);
                ldsm4(al, uAL + ad);
                #pragma unroll
                for (int ni = 0; ni < 4; ni++) {
                    mma16816(c[mi][ni], ah, bh[ni]);
                    mma16816(c[mi][ni], ah, bl[ni]);
                    mma16816(c[mi][ni], al, bh[ni]);
                }
            }
        }
        __syncthreads();
        if (kc + 2 < 16) load_chunk(kc + 2);
    }

    int r_base = row0 + wm * 64 + (lane >> 2);
    int n_base = col0 + wn * 32 + (lane & 3) * 2;

    if (mode == 0) {
        #pragma unroll
        for (int mi = 0; mi < 4; mi++) {
            int r = r_base + mi * 16;
            #pragma unroll
            for (int ni = 0; ni < 4; ni++) {
                int n = n_base + ni * 8;
                float b0 = bias[n], b1 = bias[n + 1];
                float2 v0 = make_float2(c[mi][ni][0] + b0, c[mi][ni][1] + b1);
                float2 v1 = make_float2(c[mi][ni][2] + b0, c[mi][ni][3] + b1);
                *(float2*)(outp + (size_t)r * CC + n)       = v0;
                *(float2*)(outp + (size_t)(r + 8) * CC + n) = v1;
            }
        }
    } else {
        int z = col0 >> 9;
        #pragma unroll
        for (int mi = 0; mi < 4; mi++) {
            int r = r_base + mi * 16;
            int b_ = r >> 10, t = r & (TT - 1);
            #pragma unroll
            for (int ni = 0; ni < 4; ni++) {
                int n = n_base + ni * 8;
                int nn = n & 511;
                int h = nn >> 6, d = nn & 63;
                float b0 = bias[n], b1 = bias[n + 1];
                float p00 = c[mi][ni][0] + b0, p01 = c[mi][ni][1] + b1;
                float p10 = c[mi][ni][2] + b0, p11 = c[mi][ni][3] + b1;
                __nv_bfloat16 h00 = __float2bfloat16(p00);
                __nv_bfloat16 h01 = __float2bfloat16(p01);
                __nv_bfloat16 h10 = __float2bfloat16(p10);
                __nv_bfloat16 h11 = __float2bfloat16(p11);
                __nv_bfloat16 l00 = __float2bfloat16(p00 - __bfloat162float(h00));
                __nv_bfloat16 l01 = __float2bfloat16(p01 - __bfloat162float(h01));
                __nv_bfloat16 l10 = __float2bfloat16(p10 - __bfloat162float(h10));
                __nv_bfloat16 l11 = __float2bfloat16(p11 - __bfloat162float(h11));
                if (z == 2) {
                    size_t vb = (((size_t)(b_ * HH + h)) * HD + d) * TT + t;
                    g_vthi[vb]          = h00;
                    g_vthi[vb + TT]     = h01;
                    g_vthi[vb + 8]      = h10;
                    g_vthi[vb + TT + 8] = h11;
                    g_vtlo[vb]          = l00;
                    g_vtlo[vb + TT]     = l01;
                    g_vtlo[vb + 8]      = l10;
                    g_vtlo[vb + TT + 8] = l11;
                } else {
                    __nv_bfloat16* dhi = (z == 0) ? g_qhi : g_khi;
                    __nv_bfloat16* dlo = (z == 0) ? g_qlo : g_klo;
                    size_t o = (((size_t)b_ * HH + h) * TT + t) * HD + d;
                    *(uint32_t*)(dhi + o)          = pack_bf2(h00, h01);
                    *(uint32_t*)(dhi + o + 8 * HD) = pack_bf2(h10, h11);
                    *(uint32_t*)(dlo + o)          = pack_bf2(l00, l01);
                    *(uint32_t*)(dlo + o + 8 * HD) = pack_bf2(l10, l11);
                }
            }
        }
    }
}

// ---------------------------------------------------------------------------
// proj_mma
// ---------------------------------------------------------------------------
#define PJ_Q_HI 0
#define PJ_Q_LO 16384
#define PJ_R_HI 32768
#define PJ_R_LO (32768 + NRP * 128)
#define PJ_SMEM (32768 + 2 * NRP * 128)

__global__ __launch_bounds__(256) void proj_mma()
{
    extern __shared__ char smc[];
    int tid = threadIdx.x, lane = tid & 31, wid = tid >> 5;
    int t0 = blockIdx.x * 128;

    uint32_t sQH = smem_u32(smc + PJ_Q_HI);
    uint32_t sQL = smem_u32(smc + PJ_Q_LO);
    uint32_t sRH = smem_u32(smc + PJ_R_HI);
    uint32_t sRL = smem_u32(smc + PJ_R_LO);

    #pragma unroll
    for (int s = 0; s < 4; s++) {
        int vec = tid + s * 256;
        int r = vec >> 3, g8 = vec & 7;
        uint32_t dst = SWZ128((uint32_t)(r * 128 + g8 * 16));
        size_t src = (size_t)(t0 + r) * HD + g8 * 8;
        *(uint4*)(smc + PJ_Q_HI + dst) = *(const uint4*)(g_qhi + src);
        *(uint4*)(smc + PJ_Q_LO + dst) = *(const uint4*)(g_qlo + src);
    }
    for (int vec = tid; vec < NRP * 8; vec += 256) {
        int r = vec >> 3, g8 = vec & 7;
        uint32_t dst = SWZ128((uint32_t)(r * 128 + g8 * 16));
        size_t src = (size_t)r * HD + g8 * 8;
        *(uint4*)(smc + PJ_R_HI + dst) = *(const uint4*)(g_rkhi + src);
        *(uint4*)(smc + PJ_R_LO + dst) = *(const uint4*)(g_rklo + src);
    }
    __syncthreads();

    float c[9][2][4];
    #pragma unroll
    for (int nf = 0; nf < 9; nf++)
        #pragma unroll
        for (int p = 0; p < 2; p++)
            #pragma unroll
            for (int e = 0; e < 4; e++) c[nf][p][e] = 0.0f;

    #pragma unroll
    for (int ks = 0; ks < 4; ks++) {
        int kbase = ks * 16;
        int akb = kbase + (lane >> 4) * 8;
        uint32_t aad = SWZ128((uint32_t)((wid * 16 + (lane & 15)) * 128 + akb * 2));
        uint32_t ah[4], al[4];
        ldsm4(ah, sQH + aad);
        ldsm4(al, sQL + aad);

        int br_off = (lane & 7) + ((lane >> 4) << 3);
        int bk = kbase + (((lane >> 3) & 1) << 3);
        #pragma unroll
        for (int nf = 0; nf < 9; nf++) {
            uint32_t bad = SWZ128((uint32_t)((nf * 16 + br_off) * 128 + bk * 2));
            uint32_t bh4[4], bl4[4];
            ldsm4(bh4, sRH + bad);
            ldsm4(bl4, sRL + bad);
            mma16816(c[nf][0], ah, bh4);
            mma16816(c[nf][0], ah, bl4);
            mma16816(c[nf][0], al, bh4);
            mma16816(c[nf][1], ah, bh4 + 2);
            mma16816(c[nf][1], ah, bl4 + 2);
            mma16816(c[nf][1], al, bh4 + 2);
        }
    }

    #pragma unroll
    for (int e2 = 0; e2 < 2; e2++) {
        int row = t0 + wid * 16 + (lane >> 2) + e2 * 8;
        float* prow = g_proj + (size_t)row * NR;
        #pragma unroll
        for (int nf = 0; nf < 9; nf++)
            #pragma unroll
            for (int p = 0; p < 2; p++) {
                int col = nf * 16 + p * 8 + (lane & 3) * 2;
                if (col < NR)     prow[col]     = c[nf][p][e2 * 2];
                if (col + 1 < NR) prow[col + 1] = c[nf][p][e2 * 2 + 1];
            }
    }
}

// ---------------------------------------------------------------------------
// attn_mma v2: chunk classification (low/mixed/high) + MMA band epilogue
// ---------------------------------------------------------------------------
#define FA_QHI 0
#define FA_QLO 16384
#define FA_KHI 32768
#define FA_KLO 40960
#define FA_VHI 49152
#define FA_VLO 57344
#define FA_PHI 65536
#define FA_PLO 81920
#define FA_SMEM 98304

__global__ __launch_bounds__(256, 2) void attn_mma()
{
    extern __shared__ char smc[];
    int tid = threadIdx.x, lane = tid & 31, wid = tid >> 5;
    int bh = blockIdx.y, t0 = blockIdx.x * 128;

    uint32_t uQH = smem_u32(smc + FA_QHI);
    uint32_t uQL = smem_u32(smc + FA_QLO);
    uint32_t uKH = smem_u32(smc + FA_KHI);
    uint32_t uKL = smem_u32(smc + FA_KLO);
    uint32_t uVH = smem_u32(smc + FA_VHI);
    uint32_t uVL = smem_u32(smc + FA_VLO);
    uint32_t uPH = smem_u32(smc + FA_PHI);
    uint32_t uPL = smem_u32(smc + FA_PLO);

    size_t qb = (size_t)bh * TT * HD;
    size_t vtb = (size_t)bh * HD * TT;
    float* bandb = g_band + ((size_t)bh * TT + t0) * 136;

    #pragma unroll
    for (int s = 0; s < 4; s++) {
        int vec = tid + s * 256;
        int r = vec >> 3, g8 = vec & 7;
        uint32_t dst = SWZ128((uint32_t)(r * 128 + g8 * 16));
        size_t src = qb + (size_t)(t0 + r) * HD + g8 * 8;
        *(uint4*)(smc + FA_QHI + dst) = *(const uint4*)(g_qhi + src);
        *(uint4*)(smc + FA_QLO + dst) = *(const uint4*)(g_qlo + src);
    }
    for (int idx = tid; idx < 128 * 136; idx += 256) bandb[idx] = -1e30f;

    float m[2] = {-1e30f, -1e30f}, l[2] = {0.0f, 0.0f}, plo[2] = {0.0f, 0.0f};
    float c[4][2][4];
    #pragma unroll
    for (int nf = 0; nf < 4; nf++)
        #pragma unroll
        for (int p = 0; p < 2; p++)
            #pragma unroll
            for (int e = 0; e < 4; e++) c[nf][p][e] = 0.0f;

    const float scale = 0.044194173824159216f;
    int rbase = wid * 16 + (lane >> 2);

    float prow0[2], prow136[2];
    #pragma unroll
    for (int e2 = 0; e2 < 2; e2++) {
        int trow = t0 + rbase + e2 * 8;
        prow0[e2]   = g_proj[((size_t)bh * TT + trow) * NR];
        prow136[e2] = g_proj[((size_t)bh * TT + trow) * NR + 136];
    }

    for (int kc = 0; kc < 16; kc++) {
        int k0 = kc * 64;
        bool mixed = (k0 > t0 - 131) && (k0 < t0 + 195);
        bool lowside = (k0 < t0);
        __syncthreads();

        #pragma unroll
        for (int s = 0; s < 2; s++) {
            int vec = tid + s * 256;
            int r = vec >> 3, g8 = vec & 7;
            uint32_t dst = SWZ128((uint32_t)(r * 128 + g8 * 16));
            size_t ksrc = qb + (size_t)(k0 + r) * HD + g8 * 8;
            size_t vsrc = vtb + (size_t)r * TT + k0 + g8 * 8;
            *(uint4*)(smc + FA_KHI + dst) = *(const uint4*)(g_khi + ksrc);
            *(uint4*)(smc + FA_KLO + dst) = *(const uint4*)(g_klo + ksrc);
            *(uint4*)(smc + FA_VHI + dst) = *(const uint4*)(g_vthi + vsrc);
            *(uint4*)(smc + FA_VLO + dst) = *(const uint4*)(g_vtlo + vsrc);
        }
        __syncthreads();

        float cs[4][2][4];
        #pragma unroll
        for (int nf = 0; nf < 4; nf++)
            #pragma unroll
            for (int p = 0; p < 2; p++)
                #pragma unroll
                for (int e = 0; e < 4; e++) cs[nf][p][e] = 0.0f;

        #pragma unroll
        for (int ks = 0; ks < 4; ks++) {
            uint32_t aad = SWZ128((uint32_t)(
                (wid * 16 + (lane & 15)) * 128 + (ks * 16 + (lane >> 4) * 8) * 2));
            uint32_t ah[4], al[4];
            ldsm4(ah, uQH + aad);
            ldsm4(al, uQL + aad);
            int br_off = (lane & 7) + ((lane >> 4) << 3);
            int bk = ks * 16 + (((lane >> 3) & 1) << 3);
            #pragma unroll
            for (int nf = 0; nf < 4; nf++) {
                uint32_t bad = SWZ128((uint32_t)((nf * 16 + br_off) * 128 + bk * 2));
                uint32_t bh4[4], bl4[4];
                ldsm4(bh4, uKH + bad);
                ldsm4(bl4, uKL + bad);
                mma16816(cs[nf][0], ah, bh4);
                mma16816(cs[nf][0], ah, bl4);
                mma16816(cs[nf][0], al, bh4);
                mma16816(cs[nf][1], ah, bh4 + 2);
                mma16816(cs[nf][1], ah, bl4 + 2);
                mma16816(cs[nf][1], al, bh4 + 2);
            }
        }

        if (mixed) {
            #pragma unroll
            for (int e2 = 0; e2 < 2; e2++) {
                int rowl = rbase + e2 * 8;
                int trow = t0 + rowl;
                const float* prow = g_proj + ((size_t)bh * TT + trow) * NR;
                float mx = -1e30f;
                #pragma unroll
                for (int nf = 0; nf < 4; nf++)
                    #pragma unroll
                    for (int p = 0; p < 2; p++)
                        #pragma unroll
                        for (int j = 0; j < 2; j++) {
                            int kg = k0 + nf * 16 + p * 8 + (lane & 3) * 2 + j;
                            int dist = kg - trow;
                            dist = dist < -MAXR ? -MAXR : (dist > MAXR ? MAXR : dist);
                            float v = (cs[nf][p][e2 * 2 + j] + prow[dist + MAXR]) * scale;
                            cs[nf][p][e2 * 2 + j] = v;
                            mx = fmaxf(mx, v);
                        }
                mx = fmaxf(mx, __shfl_xor_sync(0xffffffffu, mx, 1));
                mx = fmaxf(mx, __shfl_xor_sync(0xffffffffu, mx, 2));
                float mnew = fmaxf(m[e2], mx);
                float f = __expf(m[e2] - mnew);
                m[e2] = mnew;
                l[e2] *= f; plo[e2] *= f;
                #pragma unroll
                for (int nf = 0; nf < 4; nf++)
                    #pragma unroll
                    for (int p = 0; p < 2; p++) {
                        c[nf][p][e2 * 2]     *= f;
                        c[nf][p][e2 * 2 + 1] *= f;
                    }

                float es = 0.0f, pl = 0.0f;
                #pragma unroll
                for (int nf = 0; nf < 4; nf++)
                    #pragma unroll
                    for (int p = 0; p < 2; p++) {
                        float v0 = cs[nf][p][e2 * 2], v1 = cs[nf][p][e2 * 2 + 1];
                        float p0 = __expf(v0 - mnew), p1 = __expf(v1 - mnew);
                        es += p0 + p1;
                        int kcol = nf * 16 + p * 8 + (lane & 3) * 2;
                        int d0 = (k0 + kcol) - trow;
                        if ((unsigned)(d0 + 67) <= 134u) bandb[rowl * 136 + d0 + 67] = v0;
                        else if (d0 <= -MAXR) pl += p0;
                        int d1 = d0 + 1;
                        if ((unsigned)(d1 + 67) <= 134u) bandb[rowl * 136 + d1 + 67] = v1;
                        else if (d1 <= -MAXR) pl += p1;

                        __nv_bfloat16 h0 = __float2bfloat16(p0);
                        __nv_bfloat16 h1 = __float2bfloat16(p1);
                        uint32_t dst = SWZ128((uint32_t)(rowl * 128 + kcol * 2));
                        *(uint32_t*)(smc + FA_PHI + dst) = pack_bf2(h0, h1);
                        *(uint32_t*)(smc + FA_PLO + dst) = pack_bf2(
                            __float2bfloat16(p0 - __bfloat162float(h0)),
                            __float2bfloat16(p1 - __bfloat162float(h1)));
                    }
                es += __shfl_xor_sync(0xffffffffu, es, 1);
                es += __shfl_xor_sync(0xffffffffu, es, 2);
                pl += __shfl_xor_sync(0xffffffffu, pl, 1);
                pl += __shfl_xor_sync(0xffffffffu, pl, 2);
                l[e2] += es; plo[e2] += pl;
            }
        } else {
            #pragma unroll
            for (int e2 = 0; e2 < 2; e2++) {
                int rowl = rbase + e2 * 8;
                float cadd = lowside ? prow0[e2] : prow136[e2];
                float mx = -1e30f;
                #pragma unroll
                for (int nf = 0; nf < 4; nf++)
                    #pragma unroll
                    for (int p = 0; p < 2; p++)
                        #pragma unroll
                        for (int j = 0; j < 2; j++) {
                            float v = (cs[nf][p][e2 * 2 + j] + cadd) * scale;
                            cs[nf][p][e2 * 2 + j] = v;
                            mx = fmaxf(mx, v);
                        }
                mx = fmaxf(mx, __shfl_xor_sync(0xffffffffu, mx, 1));
                mx = fmaxf(mx, __shfl_xor_sync(0xffffffffu, mx, 2));
                float mnew = fmaxf(m[e2], mx);
                float f = __expf(m[e2] - mnew);
                m[e2] = mnew;
                l[e2] *= f; plo[e2] *= f;
                #pragma unroll
                for (int nf = 0; nf < 4; nf++)
                    #pragma unroll
                    for (int p = 0; p < 2; p++) {
                        c[nf][p][e2 * 2]     *= f;
                        c[nf][p][e2 * 2 + 1] *= f;
                    }

                float es = 0.0f;
                #pragma unroll
                for (int nf = 0; nf < 4; nf++)
                    #pragma unroll
                    for (int p = 0; p < 2; p++) {
                        float p0 = __expf(cs[nf][p][e2 * 2]     - mnew);
                        float p1 = __expf(cs[nf][p][e2 * 2 + 1] - mnew);
                        es += p0 + p1;
                        int kcol = nf * 16 + p * 8 + (lane & 3) * 2;
                        __nv_bfloat16 h0 = __float2bfloat16(p0);
                        __nv_bfloat16 h1 = __float2bfloat16(p1);
                        uint32_t dst = SWZ128((uint32_t)(rowl * 128 + kcol * 2));
                        *(uint32_t*)(smc + FA_PHI + dst) = pack_bf2(h0, h1);
                        *(uint32_t*)(smc + FA_PLO + dst) = pack_bf2(
                            __float2bfloat16(p0 - __bfloat162float(h0)),
                            __float2bfloat16(p1 - __bfloat162float(h1)));
                    }
                es += __shfl_xor_sync(0xffffffffu, es, 1);
                es += __shfl_xor_sync(0xffffffffu, es, 2);
                l[e2] += es;
                if (lowside) plo[e2] += es;
            }
        }
        __syncwarp();

        #pragma unroll
        for (int ks = 0; ks < 4; ks++) {
            uint32_t aad = SWZ128((uint32_t)(
                (wid * 16 + (lane & 15)) * 128 + (ks * 16 + (lane >> 4) * 8) * 2));
            uint32_t ah[4], al[4];
            ldsm4(ah, uPH + aad);
            ldsm4(al, uPL + aad);
            int br_off = (lane & 7) + ((lane >> 4) << 3);
            int bk = ks * 16 + (((lane >> 3) & 1) << 3);
            #pragma unroll
            for (int nf = 0; nf < 4; nf++) {
                uint32_t bad = SWZ128((uint32_t)((nf * 16 + br_off) * 128 + bk * 2));
                uint32_t bh4[4], bl4[4];
                ldsm4(bh4, uVH + bad);
                ldsm4(bl4, uVL + bad);
                mma16816(c[nf][0], ah, bh4);
                mma16816(c[nf][0], ah, bl4);
                mma16816(c[nf][0], al, bh4);
                mma16816(c[nf][1], ah, bh4 + 2);
                mma16816(c[nf][1], ah, bl4 + 2);
                mma16816(c[nf][1], al, bh4 + 2);
            }
        }
    }

    // ---- epilogue: band @ rel_vt via MMA ----
    float* m_s    = (float*)(smc + FA_KHI);
    float* intu_s = (float*)(smc + FA_KHI + 512);
    if ((lane & 3) == 0) {
        m_s[rbase]     = m[0];
        m_s[rbase + 8] = m[1];
    }
    __syncthreads();

    int lrow = tid >> 1;
    float mrow = m_s[lrow];
    float intu_loc = 0.0f;

    for (int ck = 0; ck < 3; ck++) {
        int cb0 = ck * 64;
        #pragma unroll
        for (int g = 0; g < 4; g++) {
            int cc = (tid & 1) * 32 + g * 8;
            float p[8];
            #pragma unroll
            for (int j = 0; j < 8; j++) {
                int col = cb0 + cc + j;
                float lg = (col < 135) ? bandb[lrow * 136 + col] : -1e30f;
                p[j] = __expf(lg - mrow);
                intu_loc += p[j];
            }
            uint32_t hi[4], lo[4];
            #pragma unroll
            for (int j = 0; j < 4; j++) {
                __nv_bfloat16 h0 = __float2bfloat16(p[2 * j]);
                __nv_bfloat16 h1 = __float2bfloat16(p[2 * j + 1]);
                hi[j] = pack_bf2(h0, h1);
                lo[j] = pack_bf2(
                    __float2bfloat16(p[2 * j]     - __bfloat162float(h0)),
                    __float2bfloat16(p[2 * j + 1] - __bfloat162float(h1)));
            }
            uint32_t dst = SWZ128((uint32_t)(lrow * 128 + cc * 2));
            *(uint4*)(smc + FA_PHI + dst) = make_uint4(hi[0], hi[1], hi[2], hi[3]);
            *(uint4*)(smc + FA_PLO + dst) = make_uint4(lo[0], lo[1], lo[2], lo[3]);
        }
        #pragma unroll
        for (int s = 0; s < 2; s++) {
            int vec = tid + s * 256;
            int r = vec >> 3, g8 = vec & 7;
            uint32_t dst = SWZ128((uint32_t)(r * 128 + g8 * 16));
            size_t src = (size_t)r * 192 + cb0 + g8 * 8;
            *(uint4*)(smc + FA_VHI + dst) = *(const uint4*)(g_rvthi + src);
            *(uint4*)(smc + FA_VLO + dst) = *(const uint4*)(g_rvtlo + src);
        }
        __syncthreads();

        #pragma unroll
        for (int ks = 0; ks < 4; ks++) {
            uint32_t aad = SWZ128((uint32_t)(
                (wid * 16 + (lane & 15)) * 128 + (ks * 16 + (lane >> 4) * 8) * 2));
            uint32_t ah[4], al[4];
            ldsm4(ah, uPH + aad);
            ldsm4(al, uPL + aad);
            int br_off = (lane & 7) + ((lane >> 4) << 3);
            int bk = ks * 16 + (((lane >> 3) & 1) << 3);
            #pragma unroll
            for (int nf = 0; nf < 4; nf++) {
                uint32_t bad = SWZ128((uint32_t)((nf * 16 + br_off) * 128 + bk * 2));
                uint32_t bh4[4], bl4[4];
                ldsm4(bh4, uVH + bad);
                ldsm4(bl4, uVL + bad);
                mma16816(c[nf][0], ah, bh4);
                mma16816(c[nf][0], ah, bl4);
                mma16816(c[nf][0], al, bh4);
                mma16816(c[nf][1], ah, bh4 + 2);
                mma16816(c[nf][1], ah, bl4 + 2);
                mma16816(c[nf][1], al, bh4 + 2);
            }
        }
        __syncthreads();
    }

    intu_loc += __shfl_xor_sync(0xffffffffu, intu_loc, 1);
    if ((tid & 1) == 0) intu_s[lrow] = intu_loc;
    __syncthreads();

    int b_ = bh >> 3, h = bh & 7;
    #pragma unroll
    for (int e2 = 0; e2 < 2; e2++) {
        int rowl = rbase + e2 * 8;
        int t = t0 + rowl;
        float lr = l[e2], pl = plo[e2];
        float phi = lr - pl - intu_s[rowl];
        float inv = 1.0f / lr;
        #pragma unroll
        for (int nf = 0; nf < 4; nf++)
            #pragma unroll
            for (int p = 0; p < 2; p++) {
                int d = nf * 16 + p * 8 + (lane & 3) * 2;
                float w0 = c[nf][p][e2 * 2]     + pl * g_rv0[d]
                         + phi * g_rv136[d];
                float w1 = c[nf][p][e2 * 2 + 1] + pl * g_rv0[d + 1]
                         + phi * g_rv136[d + 1];
                float o0 = w0 * inv, o1 = w1 * inv;
                size_t ob = ((size_t)(b_ * TT + t)) * CC + h * HD + d;
                __nv_bfloat16 h0 = __float2bfloat16(o0);
                __nv_bfloat16 h1 = __float2bfloat16(o1);
                *(uint32_t*)(g_yhi + ob) = pack_bf2(h0, h1);
                *(uint32_t*)(g_ylo + ob) = pack_bf2(
                    __float2bfloat16(o0 - __bfloat162float(h0)),
                    __float2bfloat16(o1 - __bfloat162float(h1)));
            }
    }
}

// ---------------------------------------------------------------------------
extern "C" void kernel_launch(void* const* d_in, const int* in_sizes, int n_in,
                              void* d_out, int out_size)
{
    const float* x     = (const float*)d_in[0];
    const float* Wq    = (const float*)d_in[1];
    const float* bq    = (const float*)d_in[2];
    const float* Wk    = (const float*)d_in[3];
    const float* bk    = (const float*)d_in[4];
    const float* Wv    = (const float*)d_in[5];
    const float* bv    = (const float*)d_in[6];
    const float* Wo    = (const float*)d_in[7];
    const float* bo    = (const float*)d_in[8];
    const float* rel_k = (const float*)d_in[9];
    const float* rel_v = (const float*)d_in[10];
    float* out = (float*)d_out;

    cudaFuncSetAttribute(gemm_mma, cudaFuncAttributeMaxDynamicSharedMemorySize,
                         GT_SMEM);
    cudaFuncSetAttribute(proj_mma, cudaFuncAttributeMaxDynamicSharedMemorySize,
                         PJ_SMEM);
    cudaFuncSetAttribute(attn_mma, cudaFuncAttributeMaxDynamicSharedMemorySize,
                         FA_SMEM);

    conv_edge<<<1, 64>>>(rel_v);
    conv_all<<<1024, 512>>>(x, Wq, Wk, Wv, Wo, bq, bk, bv, bo, rel_k, rel_v);
    gemm_mma<<<dim3(12, 64), 256, GT_SMEM>>>(nullptr, 1);
    proj_mma<<<512, 256, PJ_SMEM>>>();
    attn_mma<<<dim3(8, 64), 256, FA_SMEM>>>();
    gemm_mma<<<dim3(4, 64), 256, GT_SMEM>>>(out, 0);
}

// round 13
// speedup vs baseline: 2.9324x; 1.0005x over previous
#include <cuda_runtime.h>
#include <cuda_bf16.h>
#include <cstdint>

// Problem constants
#define BB   8
#define TT   1024
#define CC   512
#define HH   8
#define HD   64
#define NR   137
#define MAXR 68
#define BH   64
#define MM   8192
#define NRP  144

// ---------------------------------------------------------------------------
// Scratch (device globals)
// ---------------------------------------------------------------------------
static __device__ float g_proj[BH * TT * NR];
static __device__ float g_band[BH * TT * 136];          // raw logits, block-private rows
static __device__ float g_rv0[HD];                      // rel_v row 0
static __device__ float g_rv136[HD];                    // rel_v row 136

static __device__ __nv_bfloat16 g_qhi[BH * TT * HD];
static __device__ __nv_bfloat16 g_qlo[BH * TT * HD];
static __device__ __nv_bfloat16 g_khi[BH * TT * HD];
static __device__ __nv_bfloat16 g_klo[BH * TT * HD];
static __device__ __nv_bfloat16 g_vthi[BH * HD * TT];   // [bh][d][t]
static __device__ __nv_bfloat16 g_vtlo[BH * HD * TT];
static __device__ __nv_bfloat16 g_rkhi[NRP * HD];
static __device__ __nv_bfloat16 g_rklo[NRP * HD];
static __device__ __nv_bfloat16 g_rvthi[HD * 192];      // rvt[d][j] = rel_v[j+1][d], j<135
static __device__ __nv_bfloat16 g_rvtlo[HD * 192];

static __device__ __nv_bfloat16 g_xhi[MM * CC];
static __device__ __nv_bfloat16 g_xlo[MM * CC];
static __device__ __nv_bfloat16 g_yhi[MM * CC];
static __device__ __nv_bfloat16 g_ylo[MM * CC];
static __device__ __nv_bfloat16 g_wthi[4 * CC * CC];
static __device__ __nv_bfloat16 g_wtlo[4 * CC * CC];
static __device__ float g_bias[4 * CC];

// ---------------------------------------------------------------------------
// warp-MMA / async-copy helpers
// ---------------------------------------------------------------------------
__device__ __forceinline__ uint32_t smem_u32(const void* p) {
    uint32_t a;
    asm("{ .reg .u64 t; cvta.to.shared.u64 t, %1; cvt.u32.u64 %0, t; }"
        : "=r"(a) : "l"(p));
    return a;
}
__device__ __forceinline__ void ldsm4(uint32_t* r, uint32_t addr) {
    asm volatile("ldmatrix.sync.aligned.m8n8.x4.shared.b16 {%0,%1,%2,%3}, [%4];"
        : "=r"(r[0]), "=r"(r[1]), "=r"(r[2]), "=r"(r[3]) : "r"(addr));
}
__device__ __forceinline__ void ldsm2(uint32_t* r, uint32_t addr) {
    asm volatile("ldmatrix.sync.aligned.m8n8.x2.shared.b16 {%0,%1}, [%2];"
        : "=r"(r[0]), "=r"(r[1]) : "r"(addr));
}
__device__ __forceinline__ void mma16816(float* c, const uint32_t* a, const uint32_t* b) {
    asm volatile(
        "mma.sync.aligned.m16n8k16.row.col.f32.bf16.bf16.f32 "
        "{%0,%1,%2,%3}, {%4,%5,%6,%7}, {%8,%9}, {%0,%1,%2,%3};"
        : "+f"(c[0]), "+f"(c[1]), "+f"(c[2]), "+f"(c[3])
        : "r"(a[0]), "r"(a[1]), "r"(a[2]), "r"(a[3]), "r"(b[0]), "r"(b[1]));
}
#define SWZ128(b) ((b) ^ (((b) >> 3) & 0x70))

#define CP_A16(dst, src) \
    asm volatile("cp.async.cg.shared.global [%0], [%1], 16;" \
                 :: "r"(dst), "l"(src) : "memory")
#define CP_COMMIT() asm volatile("cp.async.commit_group;" ::: "memory")
#define CP_WAIT1()  asm volatile("cp.async.wait_group 1;" ::: "memory")
#define CP_WAIT0()  asm volatile("cp.async.wait_group 0;" ::: "memory")

__device__ __forceinline__ uint32_t pack_bf2(__nv_bfloat16 a, __nv_bfloat16 b) {
    __nv_bfloat162 t = {a, b};
    return *(uint32_t*)&t;
}

// ---------------------------------------------------------------------------
// conv_edge: rel_v edge rows to fp32 globals
// ---------------------------------------------------------------------------
__global__ void conv_edge(const float* __restrict__ rel_v)
{
    int d = threadIdx.x;
    if (d < HD) {
        g_rv0[d]   = rel_v[d];
        g_rv136[d] = rel_v[136 * HD + d];
    }
}

// ---------------------------------------------------------------------------
// conv_all: weights/x/rel_k/rel_v conversion (one launch)
// ---------------------------------------------------------------------------
__global__ __launch_bounds__(512) void conv_all(
    const float* __restrict__ x,
    const float* __restrict__ Wq, const float* __restrict__ Wk,
    const float* __restrict__ Wv, const float* __restrict__ Wo,
    const float* __restrict__ bq, const float* __restrict__ bk,
    const float* __restrict__ bv, const float* __restrict__ bo,
    const float* __restrict__ rel_k, const float* __restrict__ rel_v)
{
    int gid = blockIdx.x * blockDim.x + threadIdx.x;
    int nth = gridDim.x * blockDim.x;
    for (int idx = gid; idx < 4 * CC * CC; idx += nth) {
        int z = idx >> 18;
        int rem = idx & (CC * CC - 1);
        int k = rem >> 9, n = rem & 511;
        const float* W = (z == 0) ? Wq : (z == 1) ? Wk : (z == 2) ? Wv : Wo;
        float v = W[k * CC + n];
        __nv_bfloat16 h = __float2bfloat16(v);
        size_t dst = (size_t)z * CC * CC + (size_t)n * CC + k;
        g_wthi[dst] = h;
        g_wtlo[dst] = __float2bfloat16(v - __bfloat162float(h));
    }
    for (int i = gid; i < MM * CC / 4; i += nth) {
        float4 v = *(const float4*)(x + (size_t)i * 4);
        float vv[4] = {v.x, v.y, v.z, v.w};
        #pragma unroll
        for (int j = 0; j < 4; j++) {
            __nv_bfloat16 h = __float2bfloat16(vv[j]);
            g_xhi[(size_t)i * 4 + j] = h;
            g_xlo[(size_t)i * 4 + j] = __float2bfloat16(vv[j] - __bfloat162float(h));
        }
    }
    for (int idx = gid; idx < NRP * HD; idx += nth) {
        int r = idx >> 6, d = idx & 63;
        float v = (r < NR) ? rel_k[r * HD + d] : 0.0f;
        __nv_bfloat16 h = __float2bfloat16(v);
        g_rkhi[idx] = h;
        g_rklo[idx] = __float2bfloat16(v - __bfloat162float(h));
    }
    for (int idx = gid; idx < HD * 192; idx += nth) {
        int d = idx / 192, j = idx - d * 192;
        float v = (j < 135) ? rel_v[(j + 1) * HD + d] : 0.0f;
        __nv_bfloat16 h = __float2bfloat16(v);
        g_rvthi[idx] = h;
        g_rvtlo[idx] = __float2bfloat16(v - __bfloat162float(h));
    }
    if (gid < 4 * CC) {
        int z = gid >> 9, n = gid & 511;
        const float* bsrc = (z == 0) ? bq : (z == 1) ? bk : (z == 2) ? bv : bo;
        g_bias[gid] = bsrc[n];
    }
}

// ---------------------------------------------------------------------------
// bf16x3 warp-MMA GEMM, 2-stage cp.async pipeline (unchanged)
// ---------------------------------------------------------------------------
#define GT_A_HI 0
#define GT_A_LO 16384
#define GT_B_HI 32768
#define GT_B_LO 49152
#define GT_SMEM 65536

__global__ __launch_bounds__(256, 2) void gemm_mma(float* __restrict__ outp, int mode)
{
    extern __shared__ char smc[];
    const __nv_bfloat16 *Ahi, *Alo, *Bhi, *Blo;
    const float* bias;
    if (mode == 1) {
        Ahi = g_xhi; Alo = g_xlo; Bhi = g_wthi; Blo = g_wtlo; bias = g_bias;
    } else {
        Ahi = g_yhi; Alo = g_ylo;
        Bhi = g_wthi + 3 * CC * CC; Blo = g_wtlo + 3 * CC * CC;
        bias = g_bias + 3 * CC;
    }

    int tid = threadIdx.x, lane = tid & 31, wid = tid >> 5;
    int wm = wid >> 2, wn = wid & 3;
    int row0 = blockIdx.y * 128, col0 = blockIdx.x * 128;

    uint32_t uAH = smem_u32(smc + GT_A_HI);
    uint32_t uAL = smem_u32(smc + GT_A_LO);
    uint32_t uBH = smem_u32(smc + GT_B_HI);
    uint32_t uBL = smem_u32(smc + GT_B_LO);

    float c[4][4][4];
    #pragma unroll
    for (int mi = 0; mi < 4; mi++)
        #pragma unroll
        for (int ni = 0; ni < 4; ni++)
            #pragma unroll
            for (int e = 0; e < 4; e++) c[mi][ni][e] = 0.0f;

    auto load_chunk = [&](int kc) {
        int k0 = kc * 32;
        int sb64 = (kc & 1) * 64;
        #pragma unroll
        for (int s2 = 0; s2 < 2; s2++) {
            int vec = tid + s2 * 256;
            int idx = vec >> 2, v4 = vec & 3;
            int r = (idx & ~7) | ((idx & 1) << 2) | ((idx >> 1) & 3);
            uint32_t dst = SWZ128((uint32_t)(r * 128 + sb64 + v4 * 16));
            size_t asrc = (size_t)(row0 + r) * CC + k0 + v4 * 8;
            size_t bsrc = (size_t)(col0 + r) * CC + k0 + v4 * 8;
            CP_A16(uAH + dst, Ahi + asrc);
            CP_A16(uAL + dst, Alo + asrc);
            CP_A16(uBH + dst, Bhi + bsrc);
            CP_A16(uBL + dst, Blo + bsrc);
        }
        CP_COMMIT();
    };

    load_chunk(0);
    load_chunk(1);

    for (int kc = 0; kc < 16; kc++) {
        if (kc < 15) { CP_WAIT1(); } else { CP_WAIT0(); }
        __syncthreads();

        int sbe = (kc & 1) * 32;
        #pragma unroll
        for (int ks = 0; ks < 2; ks++) {
            int kbase = sbe + ks * 16;
            int lp = lane & 15;
            int bkb = kbase + (lp >> 3) * 8;
            uint32_t bh[4][2], bl[4][2];
            #pragma unroll
            for (int ni = 0; ni < 4; ni++) {
                int nloc = wn * 32 + ni * 8 + (lp & 7);
                uint32_t ad = SWZ128((uint32_t)(nloc * 128 + bkb * 2));
                ldsm2(bh[ni], uBH + ad);
                ldsm2(bl[ni], uBL + ad);
            }
            int akb = kbase + (lane >> 4) * 8;
            int mlp = lane & 15;
            #pragma unroll
            for (int mi = 0; mi < 4; mi++) {
                int mloc = wm * 64 + mi * 16 + mlp;
                uint32_t ad = SWZ128((uint32_t)(mloc * 128 + akb * 2));
                uint32_t ah[4], al[4];
                ldsm4(ah, uAH + ad);
                ldsm4(al, uAL + ad);
                #pragma unroll
                for (int ni = 0; ni < 4; ni++) {
                    mma16816(c[mi][ni], ah, bh[ni]);
                    mma16816(c[mi][ni], ah, bl[ni]);
                    mma16816(c[mi][ni], al, bh[ni]);
                }
            }
        }
        __syncthreads();
        if (kc + 2 < 16) load_chunk(kc + 2);
    }

    int r_base = row0 + wm * 64 + (lane >> 2);
    int n_base = col0 + wn * 32 + (lane & 3) * 2;

    if (mode == 0) {
        #pragma unroll
        for (int mi = 0; mi < 4; mi++) {
            int r = r_base + mi * 16;
            #pragma unroll
            for (int ni = 0; ni < 4; ni++) {
                int n = n_base + ni * 8;
                float b0 = bias[n], b1 = bias[n + 1];
                float2 v0 = make_float2(c[mi][ni][0] + b0, c[mi][ni][1] + b1);
                float2 v1 = make_float2(c[mi][ni][2] + b0, c[mi][ni][3] + b1);
                *(float2*)(outp + (size_t)r * CC + n)       = v0;
                *(float2*)(outp + (size_t)(r + 8) * CC + n) = v1;
            }
        }
    } else {
        int z = col0 >> 9;
        #pragma unroll
        for (int mi = 0; mi < 4; mi++) {
            int r = r_base + mi * 16;
            int b_ = r >> 10, t = r & (TT - 1);
            #pragma unroll
            for (int ni = 0; ni < 4; ni++) {
                int n = n_base + ni * 8;
                int nn = n & 511;
                int h = nn >> 6, d = nn & 63;
                float b0 = bias[n], b1 = bias[n + 1];
                float p00 = c[mi][ni][0] + b0, p01 = c[mi][ni][1] + b1;
                float p10 = c[mi][ni][2] + b0, p11 = c[mi][ni][3] + b1;
                __nv_bfloat16 h00 = __float2bfloat16(p00);
                __nv_bfloat16 h01 = __float2bfloat16(p01);
                __nv_bfloat16 h10 = __float2bfloat16(p10);
                __nv_bfloat16 h11 = __float2bfloat16(p11);
                __nv_bfloat16 l00 = __float2bfloat16(p00 - __bfloat162float(h00));
                __nv_bfloat16 l01 = __float2bfloat16(p01 - __bfloat162float(h01));
                __nv_bfloat16 l10 = __float2bfloat16(p10 - __bfloat162float(h10));
                __nv_bfloat16 l11 = __float2bfloat16(p11 - __bfloat162float(h11));
                if (z == 2) {
                    size_t vb = (((size_t)(b_ * HH + h)) * HD + d) * TT + t;
                    g_vthi[vb]          = h00;
                    g_vthi[vb + TT]     = h01;
                    g_vthi[vb + 8]      = h10;
                    g_vthi[vb + TT + 8] = h11;
                    g_vtlo[vb]          = l00;
                    g_vtlo[vb + TT]     = l01;
                    g_vtlo[vb + 8]      = l10;
                    g_vtlo[vb + TT + 8] = l11;
                } else {
                    __nv_bfloat16* dhi = (z == 0) ? g_qhi : g_khi;
                    __nv_bfloat16* dlo = (z == 0) ? g_qlo : g_klo;
                    size_t o = (((size_t)b_ * HH + h) * TT + t) * HD + d;
                    *(uint32_t*)(dhi + o)          = pack_bf2(h00, h01);
                    *(uint32_t*)(dhi + o + 8 * HD) = pack_bf2(h10, h11);
                    *(uint32_t*)(dlo + o)          = pack_bf2(l00, l01);
                    *(uint32_t*)(dlo + o + 8 * HD) = pack_bf2(l10, l11);
                }
            }
        }
    }
}

// ---------------------------------------------------------------------------
// proj_mma (unchanged)
// ---------------------------------------------------------------------------
#define PJ_Q_HI 0
#define PJ_Q_LO 16384
#define PJ_R_HI 32768
#define PJ_R_LO (32768 + NRP * 128)
#define PJ_SMEM (32768 + 2 * NRP * 128)

__global__ __launch_bounds__(256) void proj_mma()
{
    extern __shared__ char smc[];
    int tid = threadIdx.x, lane = tid & 31, wid = tid >> 5;
    int t0 = blockIdx.x * 128;

    uint32_t sQH = smem_u32(smc + PJ_Q_HI);
    uint32_t sQL = smem_u32(smc + PJ_Q_LO);
    uint32_t sRH = smem_u32(smc + PJ_R_HI);
    uint32_t sRL = smem_u32(smc + PJ_R_LO);

    #pragma unroll
    for (int s = 0; s < 4; s++) {
        int vec = tid + s * 256;
        int r = vec >> 3, g8 = vec & 7;
        uint32_t dst = SWZ128((uint32_t)(r * 128 + g8 * 16));
        size_t src = (size_t)(t0 + r) * HD + g8 * 8;
        *(uint4*)(smc + PJ_Q_HI + dst) = *(const uint4*)(g_qhi + src);
        *(uint4*)(smc + PJ_Q_LO + dst) = *(const uint4*)(g_qlo + src);
    }
    for (int vec = tid; vec < NRP * 8; vec += 256) {
        int r = vec >> 3, g8 = vec & 7;
        uint32_t dst = SWZ128((uint32_t)(r * 128 + g8 * 16));
        size_t src = (size_t)r * HD + g8 * 8;
        *(uint4*)(smc + PJ_R_HI + dst) = *(const uint4*)(g_rkhi + src);
        *(uint4*)(smc + PJ_R_LO + dst) = *(const uint4*)(g_rklo + src);
    }
    __syncthreads();

    float c[9][2][4];
    #pragma unroll
    for (int nf = 0; nf < 9; nf++)
        #pragma unroll
        for (int p = 0; p < 2; p++)
            #pragma unroll
            for (int e = 0; e < 4; e++) c[nf][p][e] = 0.0f;

    #pragma unroll
    for (int ks = 0; ks < 4; ks++) {
        int kbase = ks * 16;
        int akb = kbase + (lane >> 4) * 8;
        uint32_t aad = SWZ128((uint32_t)((wid * 16 + (lane & 15)) * 128 + akb * 2));
        uint32_t ah[4], al[4];
        ldsm4(ah, sQH + aad);
        ldsm4(al, sQL + aad);

        int br_off = (lane & 7) + ((lane >> 4) << 3);
        int bk = kbase + (((lane >> 3) & 1) << 3);
        #pragma unroll
        for (int nf = 0; nf < 9; nf++) {
            uint32_t bad = SWZ128((uint32_t)((nf * 16 + br_off) * 128 + bk * 2));
            uint32_t bh4[4], bl4[4];
            ldsm4(bh4, sRH + bad);
            ldsm4(bl4, sRL + bad);
            mma16816(c[nf][0], ah, bh4);
            mma16816(c[nf][0], ah, bl4);
            mma16816(c[nf][0], al, bh4);
            mma16816(c[nf][1], ah, bh4 + 2);
            mma16816(c[nf][1], ah, bl4 + 2);
            mma16816(c[nf][1], al, bh4 + 2);
        }
    }

    #pragma unroll
    for (int e2 = 0; e2 < 2; e2++) {
        int row = t0 + wid * 16 + (lane >> 2) + e2 * 8;
        float* prow = g_proj + (size_t)row * NR;
        #pragma unroll
        for (int nf = 0; nf < 9; nf++)
            #pragma unroll
            for (int p = 0; p < 2; p++) {
                int col = nf * 16 + p * 8 + (lane & 3) * 2;
                if (col < NR)     prow[col]     = c[nf][p][e2 * 2];
                if (col + 1 < NR) prow[col + 1] = c[nf][p][e2 * 2 + 1];
            }
    }
}

// ---------------------------------------------------------------------------
// attn_mma v3: t-tile 256, 512 threads, 1 CTA/SM, cp.async double-buffered K/V
// smem: Q 64K | K 16K(2st) | Kl 16K | V 16K | Vl 16K | P 32K | Pl 32K = 192K
// ---------------------------------------------------------------------------
#define FA_QHI 0
#define FA_QLO 32768
#define FA_KHI 65536
#define FA_KLO 81920
#define FA_VHI 98304
#define FA_VLO 114688
#define FA_PHI 131072
#define FA_PLO 163840
#define FA_SMEM 196608

__global__ __launch_bounds__(512, 1) void attn_mma()
{
    extern __shared__ char smc[];
    int tid = threadIdx.x, lane = tid & 31, wid = tid >> 5;
    int bh = blockIdx.y, t0 = blockIdx.x * 256;

    uint32_t uQH = smem_u32(smc + FA_QHI);
    uint32_t uQL = smem_u32(smc + FA_QLO);
    uint32_t uKH = smem_u32(smc + FA_KHI);
    uint32_t uKL = smem_u32(smc + FA_KLO);
    uint32_t uVH = smem_u32(smc + FA_VHI);
    uint32_t uVL = smem_u32(smc + FA_VLO);
    uint32_t uPH = smem_u32(smc + FA_PHI);
    uint32_t uPL = smem_u32(smc + FA_PLO);

    size_t qb = (size_t)bh * TT * HD;
    size_t vtb = (size_t)bh * HD * TT;
    float* bandb = g_band + ((size_t)bh * TT + t0) * 136;

    // Q tile (256x64) hi/lo swizzled
    #pragma unroll
    for (int s = 0; s < 4; s++) {
        int vec = tid + s * 512;
        int r = vec >> 3, g8 = vec & 7;
        uint32_t dst = SWZ128((uint32_t)(r * 128 + g8 * 16));
        size_t src = qb + (size_t)(t0 + r) * HD + g8 * 8;
        *(uint4*)(smc + FA_QHI + dst) = *(const uint4*)(g_qhi + src);
        *(uint4*)(smc + FA_QLO + dst) = *(const uint4*)(g_qlo + src);
    }
    for (int idx = tid; idx < 256 * 136; idx += 512) bandb[idx] = -1e30f;

    float m[2] = {-1e30f, -1e30f}, l[2] = {0.0f, 0.0f}, plo[2] = {0.0f, 0.0f};
    float c[4][2][4];
    #pragma unroll
    for (int nf = 0; nf < 4; nf++)
        #pragma unroll
        for (int p = 0; p < 2; p++)
            #pragma unroll
            for (int e = 0; e < 4; e++) c[nf][p][e] = 0.0f;

    const float scale = 0.044194173824159216f;
    int rbase = wid * 16 + (lane >> 2);

    float prow0[2], prow136[2];
    #pragma unroll
    for (int e2 = 0; e2 < 2; e2++) {
        int trow = t0 + rbase + e2 * 8;
        prow0[e2]   = g_proj[((size_t)bh * TT + trow) * NR];
        prow136[e2] = g_proj[((size_t)bh * TT + trow) * NR + 136];
    }

    // cp.async K/V chunk loader (64 k x 64 d), stage = kc&1
    auto load_kv = [&](int kc) {
        int k0 = kc * 64;
        uint32_t koff = (uint32_t)(kc & 1) * 8192u;
        int r = tid >> 3, g8 = tid & 7;        // 512 = 64 rows x 8
        uint32_t dst = SWZ128((uint32_t)(r * 128 + g8 * 16)) + koff;
        size_t ksrc = qb + (size_t)(k0 + r) * HD + g8 * 8;
        size_t vsrc = vtb + (size_t)r * TT + k0 + g8 * 8;
        CP_A16(uKH + dst, g_khi + ksrc);
        CP_A16(uKL + dst, g_klo + ksrc);
        CP_A16(uVH + dst, g_vthi + vsrc);
        CP_A16(uVL + dst, g_vtlo + vsrc);
        CP_COMMIT();
    };

    load_kv(0);
    load_kv(1);

    for (int kc = 0; kc < 16; kc++) {
        int k0 = kc * 64;
        uint32_t koff = (uint32_t)(kc & 1) * 8192u;
        bool mixed = (k0 > t0 - 131) && (k0 < t0 + 323);
        bool lowside = (k0 < t0);

        if (kc < 15) { CP_WAIT1(); } else { CP_WAIT0(); }
        __syncthreads();

        // S chunk MMA
        float cs[4][2][4];
        #pragma unroll
        for (int nf = 0; nf < 4; nf++)
            #pragma unroll
            for (int p = 0; p < 2; p++)
                #pragma unroll
                for (int e = 0; e < 4; e++) cs[nf][p][e] = 0.0f;

        #pragma unroll
        for (int ks = 0; ks < 4; ks++) {
            uint32_t aad = SWZ128((uint32_t)(
                (wid * 16 + (lane & 15)) * 128 + (ks * 16 + (lane >> 4) * 8) * 2));
            uint32_t ah[4], al[4];
            ldsm4(ah, uQH + aad);
            ldsm4(al, uQL + aad);
            int br_off = (lane & 7) + ((lane >> 4) << 3);
            int bk = ks * 16 + (((lane >> 3) & 1) << 3);
            #pragma unroll
            for (int nf = 0; nf < 4; nf++) {
                uint32_t bad = SWZ128((uint32_t)((nf * 16 + br_off) * 128 + bk * 2)) + koff;
                uint32_t bh4[4], bl4[4];
                ldsm4(bh4, uKH + bad);
                ldsm4(bl4, uKL + bad);
                mma16816(cs[nf][0], ah, bh4);
                mma16816(cs[nf][0], ah, bl4);
                mma16816(cs[nf][0], al, bh4);
                mma16816(cs[nf][1], ah, bh4 + 2);
                mma16816(cs[nf][1], ah, bl4 + 2);
                mma16816(cs[nf][1], al, bh4 + 2);
            }
        }

        if (mixed) {
            #pragma unroll
            for (int e2 = 0; e2 < 2; e2++) {
                int rowl = rbase + e2 * 8;
                int trow = t0 + rowl;
                const float* prow = g_proj + ((size_t)bh * TT + trow) * NR;
                float mx = -1e30f;
                #pragma unroll
                for (int nf = 0; nf < 4; nf++)
                    #pragma unroll
                    for (int p = 0; p < 2; p++)
                        #pragma unroll
                        for (int j = 0; j < 2; j++) {
                            int kg = k0 + nf * 16 + p * 8 + (lane & 3) * 2 + j;
                            int dist = kg - trow;
                            dist = dist < -MAXR ? -MAXR : (dist > MAXR ? MAXR : dist);
                            float v = (cs[nf][p][e2 * 2 + j] + prow[dist + MAXR]) * scale;
                            cs[nf][p][e2 * 2 + j] = v;
                            mx = fmaxf(mx, v);
                        }
                mx = fmaxf(mx, __shfl_xor_sync(0xffffffffu, mx, 1));
                mx = fmaxf(mx, __shfl_xor_sync(0xffffffffu, mx, 2));
                float mnew = fmaxf(m[e2], mx);
                float f = __expf(m[e2] - mnew);
                m[e2] = mnew;
                l[e2] *= f; plo[e2] *= f;
                #pragma unroll
                for (int nf = 0; nf < 4; nf++)
                    #pragma unroll
                    for (int p = 0; p < 2; p++) {
                        c[nf][p][e2 * 2]     *= f;
                        c[nf][p][e2 * 2 + 1] *= f;
                    }

                float es = 0.0f, pl = 0.0f;
                #pragma unroll
                for (int nf = 0; nf < 4; nf++)
                    #pragma unroll
                    for (int p = 0; p < 2; p++) {
                        float v0 = cs[nf][p][e2 * 2], v1 = cs[nf][p][e2 * 2 + 1];
                        float p0 = __expf(v0 - mnew), p1 = __expf(v1 - mnew);
                        es += p0 + p1;
                        int kcol = nf * 16 + p * 8 + (lane & 3) * 2;
                        int d0 = (k0 + kcol) - trow;
                        if ((unsigned)(d0 + 67) <= 134u) bandb[rowl * 136 + d0 + 67] = v0;
                        else if (d0 <= -MAXR) pl += p0;
                        int d1 = d0 + 1;
                        if ((unsigned)(d1 + 67) <= 134u) bandb[rowl * 136 + d1 + 67] = v1;
                        else if (d1 <= -MAXR) pl += p1;

                        __nv_bfloat16 h0 = __float2bfloat16(p0);
                        __nv_bfloat16 h1 = __float2bfloat16(p1);
                        uint32_t dst = SWZ128((uint32_t)(rowl * 128 + kcol * 2));
                        *(uint32_t*)(smc + FA_PHI + dst) = pack_bf2(h0, h1);
                        *(uint32_t*)(smc + FA_PLO + dst) = pack_bf2(
                            __float2bfloat16(p0 - __bfloat162float(h0)),
                            __float2bfloat16(p1 - __bfloat162float(h1)));
                    }
                es += __shfl_xor_sync(0xffffffffu, es, 1);
                es += __shfl_xor_sync(0xffffffffu, es, 2);
                pl += __shfl_xor_sync(0xffffffffu, pl, 1);
                pl += __shfl_xor_sync(0xffffffffu, pl, 2);
                l[e2] += es; plo[e2] += pl;
            }
        } else {
            #pragma unroll
            for (int e2 = 0; e2 < 2; e2++) {
                int rowl = rbase + e2 * 8;
                float cadd = lowside ? prow0[e2] : prow136[e2];
                float mx = -1e30f;
                #pragma unroll
                for (int nf = 0; nf < 4; nf++)
                    #pragma unroll
                    for (int p = 0; p < 2; p++)
                        #pragma unroll
                        for (int j = 0; j < 2; j++) {
                            float v = (cs[nf][p][e2 * 2 + j] + cadd) * scale;
                            cs[nf][p][e2 * 2 + j] = v;
                            mx = fmaxf(mx, v);
                        }
                mx = fmaxf(mx, __shfl_xor_sync(0xffffffffu, mx, 1));
                mx = fmaxf(mx, __shfl_xor_sync(0xffffffffu, mx, 2));
                float mnew = fmaxf(m[e2], mx);
                float f = __expf(m[e2] - mnew);
                m[e2] = mnew;
                l[e2] *= f; plo[e2] *= f;
                #pragma unroll
                for (int nf = 0; nf < 4; nf++)
                    #pragma unroll
                    for (int p = 0; p < 2; p++) {
                        c[nf][p][e2 * 2]     *= f;
                        c[nf][p][e2 * 2 + 1] *= f;
                    }

                float es = 0.0f;
                #pragma unroll
                for (int nf = 0; nf < 4; nf++)
                    #pragma unroll
                    for (int p = 0; p < 2; p++) {
                        float p0 = __expf(cs[nf][p][e2 * 2]     - mnew);
                        float p1 = __expf(cs[nf][p][e2 * 2 + 1] - mnew);
                        es += p0 + p1;
                        int kcol = nf * 16 + p * 8 + (lane & 3) * 2;
                        __nv_bfloat16 h0 = __float2bfloat16(p0);
                        __nv_bfloat16 h1 = __float2bfloat16(p1);
                        uint32_t dst = SWZ128((uint32_t)(rowl * 128 + kcol * 2));
                        *(uint32_t*)(smc + FA_PHI + dst) = pack_bf2(h0, h1);
                        *(uint32_t*)(smc + FA_PLO + dst) = pack_bf2(
                            __float2bfloat16(p0 - __bfloat162float(h0)),
                            __float2bfloat16(p1 - __bfloat162float(h1)));
                    }
                es += __shfl_xor_sync(0xffffffffu, es, 1);
                es += __shfl_xor_sync(0xffffffffu, es, 2);
                l[e2] += es;
                if (lowside) plo[e2] += es;
            }
        }
        __syncwarp();

        // PV MMA
        #pragma unroll
        for (int ks = 0; ks < 4; ks++) {
            uint32_t aad = SWZ128((uint32_t)(
                (wid * 16 + (lane & 15)) * 128 + (ks * 16 + (lane >> 4) * 8) * 2));
            uint32_t ah[4], al[4];
            ldsm4(ah, uPH + aad);
            ldsm4(al, uPL + aad);
            int br_off = (lane & 7) + ((lane >> 4) << 3);
            int bk = ks * 16 + (((lane >> 3) & 1) << 3);
            #pragma unroll
            for (int nf = 0; nf < 4; nf++) {
                uint32_t bad = SWZ128((uint32_t)((nf * 16 + br_off) * 128 + bk * 2)) + koff;
                uint32_t bh4[4], bl4[4];
                ldsm4(bh4, uVH + bad);
                ldsm4(bl4, uVL + bad);
                mma16816(c[nf][0], ah, bh4);
                mma16816(c[nf][0], ah, bl4);
                mma16816(c[nf][0], al, bh4);
                mma16816(c[nf][1], ah, bh4 + 2);
                mma16816(c[nf][1], ah, bl4 + 2);
                mma16816(c[nf][1], al, bh4 + 2);
            }
        }
        __syncthreads();
        if (kc + 2 < 16) load_kv(kc + 2);
    }

    // ---- epilogue: band @ rel_vt via MMA ----
    float* m_s    = (float*)(smc + FA_KHI);          // K region dead
    float* intu_s = (float*)(smc + FA_KHI + 1024);
    if ((lane & 3) == 0) {
        m_s[rbase]     = m[0];
        m_s[rbase + 8] = m[1];
    }
    __syncthreads();

    int lrow = tid >> 1;
    float mrow = m_s[lrow];
    float intu_loc = 0.0f;

    for (int ck = 0; ck < 3; ck++) {
        int cb0 = ck * 64;
        #pragma unroll
        for (int g = 0; g < 4; g++) {
            int cc = (tid & 1) * 32 + g * 8;
            float p[8];
            #pragma unroll
            for (int j = 0; j < 8; j++) {
                int col = cb0 + cc + j;
                float lg = (col < 135) ? bandb[lrow * 136 + col] : -1e30f;
                p[j] = __expf(lg - mrow);
                intu_loc += p[j];
            }
            uint32_t hi[4], lo[4];
            #pragma unroll
            for (int j = 0; j < 4; j++) {
                __nv_bfloat16 h0 = __float2bfloat16(p[2 * j]);
                __nv_bfloat16 h1 = __float2bfloat16(p[2 * j + 1]);
                hi[j] = pack_bf2(h0, h1);
                lo[j] = pack_bf2(
                    __float2bfloat16(p[2 * j]     - __bfloat162float(h0)),
                    __float2bfloat16(p[2 * j + 1] - __bfloat162float(h1)));
            }
            uint32_t dst = SWZ128((uint32_t)(lrow * 128 + cc * 2));
            *(uint4*)(smc + FA_PHI + dst) = make_uint4(hi[0], hi[1], hi[2], hi[3]);
            *(uint4*)(smc + FA_PLO + dst) = make_uint4(lo[0], lo[1], lo[2], lo[3]);
        }
        {
            int r = tid >> 3, g8 = tid & 7;      // 64 rows x 8
            uint32_t dst = SWZ128((uint32_t)(r * 128 + g8 * 16));
            size_t src = (size_t)r * 192 + cb0 + g8 * 8;
            *(uint4*)(smc + FA_VHI + dst) = *(const uint4*)(g_rvthi + src);
            *(uint4*)(smc + FA_VLO + dst) = *(const uint4*)(g_rvtlo + src);
        }
        __syncthreads();

        #pragma unroll
        for (int ks = 0; ks < 4; ks++) {
            uint32_t aad = SWZ128((uint32_t)(
                (wid * 16 + (lane & 15)) * 128 + (ks * 16 + (lane >> 4) * 8) * 2));
            uint32_t ah[4], al[4];
            ldsm4(ah, uPH + aad);
            ldsm4(al, uPL + aad);
            int br_off = (lane & 7) + ((lane >> 4) << 3);
            int bk = ks * 16 + (((lane >> 3) & 1) << 3);
            #pragma unroll
            for (int nf = 0; nf < 4; nf++) {
                uint32_t bad = SWZ128((uint32_t)((nf * 16 + br_off) * 128 + bk * 2));
                uint32_t bh4[4], bl4[4];
                ldsm4(bh4, uVH + bad);
                ldsm4(bl4, uVL + bad);
                mma16816(c[nf][0], ah, bh4);
                mma16816(c[nf][0], ah, bl4);
                mma16816(c[nf][0], al, bh4);
                mma16816(c[nf][1], ah, bh4 + 2);
                mma16816(c[nf][1], ah, bl4 + 2);
                mma16816(c[nf][1], al, bh4 + 2);
            }
        }
        __syncthreads();
    }

    intu_loc += __shfl_xor_sync(0xffffffffu, intu_loc, 1);
    if ((tid & 1) == 0) intu_s[lrow] = intu_loc;
    __syncthreads();

    int b_ = bh >> 3, h = bh & 7;
    #pragma unroll
    for (int e2 = 0; e2 < 2; e2++) {
        int rowl = rbase + e2 * 8;
        int t = t0 + rowl;
        float lr = l[e2], pl = plo[e2];
        float phi = lr - pl - intu_s[rowl];
        float inv = 1.0f / lr;
        #pragma unroll
        for (int nf = 0; nf < 4; nf++)
            #pragma unroll
            for (int p = 0; p < 2; p++) {
                int d = nf * 16 + p * 8 + (lane & 3) * 2;
                float w0 = c[nf][p][e2 * 2]     + pl * g_rv0[d]
                         + phi * g_rv136[d];
                float w1 = c[nf][p][e2 * 2 + 1] + pl * g_rv0[d + 1]
                         + phi * g_rv136[d + 1];
                float o0 = w0 * inv, o1 = w1 * inv;
                size_t ob = ((size_t)(b_ * TT + t)) * CC + h * HD + d;
                __nv_bfloat16 h0 = __float2bfloat16(o0);
                __nv_bfloat16 h1 = __float2bfloat16(o1);
                *(uint32_t*)(g_yhi + ob) = pack_bf2(h0, h1);
                *(uint32_t*)(g_ylo + ob) = pack_bf2(
                    __float2bfloat16(o0 - __bfloat162float(h0)),
                    __float2bfloat16(o1 - __bfloat162float(h1)));
            }
    }
}

// ---------------------------------------------------------------------------
extern "C" void kernel_launch(void* const* d_in, const int* in_sizes, int n_in,
                              void* d_out, int out_size)
{
    const float* x     = (const float*)d_in[0];
    const float* Wq    = (const float*)d_in[1];
    const float* bq    = (const float*)d_in[2];
    const float* Wk    = (const float*)d_in[3];
    const float* bk    = (const float*)d_in[4];
    const float* Wv    = (const float*)d_in[5];
    const float* bv    = (const float*)d_in[6];
    const float* Wo    = (const float*)d_in[7];
    const float* bo    = (const float*)d_in[8];
    const float* rel_k = (const float*)d_in[9];
    const float* rel_v = (const float*)d_in[10];
    float* out = (float*)d_out;

    cudaFuncSetAttribute(gemm_mma, cudaFuncAttributeMaxDynamicSharedMemorySize,
                         GT_SMEM);
    cudaFuncSetAttribute(proj_mma, cudaFuncAttributeMaxDynamicSharedMemorySize,
                         PJ_SMEM);
    cudaFuncSetAttribute(attn_mma, cudaFuncAttributeMaxDynamicSharedMemorySize,
                         FA_SMEM);

    conv_edge<<<1, 64>>>(rel_v);
    conv_all<<<1024, 512>>>(x, Wq, Wk, Wv, Wo, bq, bk, bv, bo, rel_k, rel_v);
    gemm_mma<<<dim3(12, 64), 256, GT_SMEM>>>(nullptr, 1);
    proj_mma<<<512, 256, PJ_SMEM>>>();
    attn_mma<<<dim3(4, 64), 512, FA_SMEM>>>();
    gemm_mma<<<dim3(4, 64), 256, GT_SMEM>>>(out, 0);
}

// round 14
// speedup vs baseline: 3.0167x; 1.0288x over previous
#include <cuda_runtime.h>
#include <cuda_bf16.h>
#include <cstdint>

// Problem constants
#define BB   8
#define TT   1024
#define CC   512
#define HH   8
#define HD   64
#define NR   137
#define MAXR 68
#define BH   64
#define MM   8192
#define NRP  144

// ---------------------------------------------------------------------------
// Scratch (device globals)
// ---------------------------------------------------------------------------
static __device__ float g_proj[BH * TT * NR];
static __device__ float g_band[BH * TT * 136];
static __device__ float g_rv0[HD];
static __device__ float g_rv136[HD];

static __device__ __nv_bfloat16 g_qhi[BH * TT * HD];
static __device__ __nv_bfloat16 g_qlo[BH * TT * HD];
static __device__ __nv_bfloat16 g_khi[BH * TT * HD];
static __device__ __nv_bfloat16 g_klo[BH * TT * HD];
static __device__ __nv_bfloat16 g_vthi[BH * HD * TT];   // [bh][d][t]
static __device__ __nv_bfloat16 g_vtlo[BH * HD * TT];
static __device__ __nv_bfloat16 g_rkhi[NRP * HD];
static __device__ __nv_bfloat16 g_rklo[NRP * HD];
static __device__ __nv_bfloat16 g_rvthi[HD * 192];      // rvt[d][j] = rel_v[j+1][d]
static __device__ __nv_bfloat16 g_rvtlo[HD * 192];

static __device__ __nv_bfloat16 g_xhi[MM * CC];
static __device__ __nv_bfloat16 g_xlo[MM * CC];
static __device__ __nv_bfloat16 g_yhi[MM * CC];
static __device__ __nv_bfloat16 g_ylo[MM * CC];
static __device__ __nv_bfloat16 g_wthi[4 * CC * CC];
static __device__ __nv_bfloat16 g_wtlo[4 * CC * CC];
static __device__ float g_bias[4 * CC];

// ---------------------------------------------------------------------------
// helpers
// ---------------------------------------------------------------------------
__device__ __forceinline__ uint32_t smem_u32(const void* p) {
    uint32_t a;
    asm("{ .reg .u64 t; cvta.to.shared.u64 t, %1; cvt.u32.u64 %0, t; }"
        : "=r"(a) : "l"(p));
    return a;
}
__device__ __forceinline__ void ldsm4(uint32_t* r, uint32_t addr) {
    asm volatile("ldmatrix.sync.aligned.m8n8.x4.shared.b16 {%0,%1,%2,%3}, [%4];"
        : "=r"(r[0]), "=r"(r[1]), "=r"(r[2]), "=r"(r[3]) : "r"(addr));
}
__device__ __forceinline__ void ldsm2(uint32_t* r, uint32_t addr) {
    asm volatile("ldmatrix.sync.aligned.m8n8.x2.shared.b16 {%0,%1}, [%2];"
        : "=r"(r[0]), "=r"(r[1]) : "r"(addr));
}
__device__ __forceinline__ void mma16816(float* c, const uint32_t* a, const uint32_t* b) {
    asm volatile(
        "mma.sync.aligned.m16n8k16.row.col.f32.bf16.bf16.f32 "
        "{%0,%1,%2,%3}, {%4,%5,%6,%7}, {%8,%9}, {%0,%1,%2,%3};"
        : "+f"(c[0]), "+f"(c[1]), "+f"(c[2]), "+f"(c[3])
        : "r"(a[0]), "r"(a[1]), "r"(a[2]), "r"(a[3]), "r"(b[0]), "r"(b[1]));
}
#define SWZ128(b) ((b) ^ (((b) >> 3) & 0x70))

#define CP_A16(dst, src) \
    asm volatile("cp.async.cg.shared.global [%0], [%1], 16;" \
                 :: "r"(dst), "l"(src) : "memory")
#define CP_COMMIT() asm volatile("cp.async.commit_group;" ::: "memory")
#define CP_WAIT1()  asm volatile("cp.async.wait_group 1;" ::: "memory")
#define CP_WAIT0()  asm volatile("cp.async.wait_group 0;" ::: "memory")

__device__ __forceinline__ uint32_t pack_bf2(__nv_bfloat16 a, __nv_bfloat16 b) {
    __nv_bfloat162 t = {a, b};
    return *(uint32_t*)&t;
}

// packed hi/lo split: {p0,p1} -> bf16x2 hi (1 cvt) + bf16x2 residual (1 cvt)
__device__ __forceinline__ void split2(float p0, float p1, uint32_t& hi, uint32_t& lo)
{
    uint32_t h;
    asm("cvt.rn.bf16x2.f32 %0, %1, %2;" : "=r"(h) : "f"(p1), "f"(p0));
    float f0 = __uint_as_float(h << 16);
    float f1 = __uint_as_float(h & 0xFFFF0000u);
    uint32_t l;
    asm("cvt.rn.bf16x2.f32 %0, %1, %2;" : "=r"(l) : "f"(p1 - f1), "f"(p0 - f0));
    hi = h; lo = l;
}

// ---------------------------------------------------------------------------
__global__ void conv_edge(const float* __restrict__ rel_v)
{
    int d = threadIdx.x;
    if (d < HD) {
        g_rv0[d]   = rel_v[d];
        g_rv136[d] = rel_v[136 * HD + d];
    }
}

__global__ __launch_bounds__(512) void conv_all(
    const float* __restrict__ x,
    const float* __restrict__ Wq, const float* __restrict__ Wk,
    const float* __restrict__ Wv, const float* __restrict__ Wo,
    const float* __restrict__ bq, const float* __restrict__ bk,
    const float* __restrict__ bv, const float* __restrict__ bo,
    const float* __restrict__ rel_k, const float* __restrict__ rel_v)
{
    int gid = blockIdx.x * blockDim.x + threadIdx.x;
    int nth = gridDim.x * blockDim.x;
    for (int idx = gid; idx < 4 * CC * CC; idx += nth) {
        int z = idx >> 18;
        int rem = idx & (CC * CC - 1);
        int k = rem >> 9, n = rem & 511;
        const float* W = (z == 0) ? Wq : (z == 1) ? Wk : (z == 2) ? Wv : Wo;
        float v = W[k * CC + n];
        __nv_bfloat16 h = __float2bfloat16(v);
        size_t dst = (size_t)z * CC * CC + (size_t)n * CC + k;
        g_wthi[dst] = h;
        g_wtlo[dst] = __float2bfloat16(v - __bfloat162float(h));
    }
    for (int i = gid; i < MM * CC / 4; i += nth) {
        float4 v = *(const float4*)(x + (size_t)i * 4);
        float vv[4] = {v.x, v.y, v.z, v.w};
        #pragma unroll
        for (int j = 0; j < 4; j++) {
            __nv_bfloat16 h = __float2bfloat16(vv[j]);
            g_xhi[(size_t)i * 4 + j] = h;
            g_xlo[(size_t)i * 4 + j] = __float2bfloat16(vv[j] - __bfloat162float(h));
        }
    }
    for (int idx = gid; idx < NRP * HD; idx += nth) {
        int r = idx >> 6, d = idx & 63;
        float v = (r < NR) ? rel_k[r * HD + d] : 0.0f;
        __nv_bfloat16 h = __float2bfloat16(v);
        g_rkhi[idx] = h;
        g_rklo[idx] = __float2bfloat16(v - __bfloat162float(h));
    }
    for (int idx = gid; idx < HD * 192; idx += nth) {
        int d = idx / 192, j = idx - d * 192;
        float v = (j < 135) ? rel_v[(j + 1) * HD + d] : 0.0f;
        __nv_bfloat16 h = __float2bfloat16(v);
        g_rvthi[idx] = h;
        g_rvtlo[idx] = __float2bfloat16(v - __bfloat162float(h));
    }
    if (gid < 4 * CC) {
        int z = gid >> 9, n = gid & 511;
        const float* bsrc = (z == 0) ? bq : (z == 1) ? bk : (z == 2) ? bv : bo;
        g_bias[gid] = bsrc[n];
    }
}

// ---------------------------------------------------------------------------
// bf16x3 warp-MMA GEMM, 2-stage cp.async pipeline (unchanged)
// ---------------------------------------------------------------------------
#define GT_A_HI 0
#define GT_A_LO 16384
#define GT_B_HI 32768
#define GT_B_LO 49152
#define GT_SMEM 65536

__global__ __launch_bounds__(256, 2) void gemm_mma(float* __restrict__ outp, int mode)
{
    extern __shared__ char smc[];
    const __nv_bfloat16 *Ahi, *Alo, *Bhi, *Blo;
    const float* bias;
    if (mode == 1) {
        Ahi = g_xhi; Alo = g_xlo; Bhi = g_wthi; Blo = g_wtlo; bias = g_bias;
    } else {
        Ahi = g_yhi; Alo = g_ylo;
        Bhi = g_wthi + 3 * CC * CC; Blo = g_wtlo + 3 * CC * CC;
        bias = g_bias + 3 * CC;
    }

    int tid = threadIdx.x, lane = tid & 31, wid = tid >> 5;
    int wm = wid >> 2, wn = wid & 3;
    int row0 = blockIdx.y * 128, col0 = blockIdx.x * 128;

    uint32_t uAH = smem_u32(smc + GT_A_HI);
    uint32_t uAL = smem_u32(smc + GT_A_LO);
    uint32_t uBH = smem_u32(smc + GT_B_HI);
    uint32_t uBL = smem_u32(smc + GT_B_LO);

    float c[4][4][4];
    #pragma unroll
    for (int mi = 0; mi < 4; mi++)
        #pragma unroll
        for (int ni = 0; ni < 4; ni++)
            #pragma unroll
            for (int e = 0; e < 4; e++) c[mi][ni][e] = 0.0f;

    auto load_chunk = [&](int kc) {
        int k0 = kc * 32;
        int sb64 = (kc & 1) * 64;
        #pragma unroll
        for (int s2 = 0; s2 < 2; s2++) {
            int vec = tid + s2 * 256;
            int idx = vec >> 2, v4 = vec & 3;
            int r = (idx & ~7) | ((idx & 1) << 2) | ((idx >> 1) & 3);
            uint32_t dst = SWZ128((uint32_t)(r * 128 + sb64 + v4 * 16));
            size_t asrc = (size_t)(row0 + r) * CC + k0 + v4 * 8;
            size_t bsrc = (size_t)(col0 + r) * CC + k0 + v4 * 8;
            CP_A16(uAH + dst, Ahi + asrc);
            CP_A16(uAL + dst, Alo + asrc);
            CP_A16(uBH + dst, Bhi + bsrc);
            CP_A16(uBL + dst, Blo + bsrc);
        }
        CP_COMMIT();
    };

    load_chunk(0);
    load_chunk(1);

    for (int kc = 0; kc < 16; kc++) {
        if (kc < 15) { CP_WAIT1(); } else { CP_WAIT0(); }
        __syncthreads();

        int sbe = (kc & 1) * 32;
        #pragma unroll
        for (int ks = 0; ks < 2; ks++) {
            int kbase = sbe + ks * 16;
            int lp = lane & 15;
            int bkb = kbase + (lp >> 3) * 8;
            uint32_t bh[4][2], bl[4][2];
            #pragma unroll
            for (int ni = 0; ni < 4; ni++) {
                int nloc = wn * 32 + ni * 8 + (lp & 7);
                uint32_t ad = SWZ128((uint32_t)(nloc * 128 + bkb * 2));
                ldsm2(bh[ni], uBH + ad);
                ldsm2(bl[ni], uBL + ad);
            }
            int akb = kbase + (lane >> 4) * 8;
            int mlp = lane & 15;
            #pragma unroll
            for (int mi = 0; mi < 4; mi++) {
                int mloc = wm * 64 + mi * 16 + mlp;
                uint32_t ad = SWZ128((uint32_t)(mloc * 128 + akb * 2));
                uint32_t ah[4], al[4];
                ldsm4(ah, uAH + ad);
                ldsm4(al, uAL + ad);
                #pragma unroll
                for (int ni = 0; ni < 4; ni++) {
                    mma16816(c[mi][ni], ah, bh[ni]);
                    mma16816(c[mi][ni], ah, bl[ni]);
                    mma16816(c[mi][ni], al, bh[ni]);
                }
            }
        }
        __syncthreads();
        if (kc + 2 < 16) load_chunk(kc + 2);
    }

    int r_base = row0 + wm * 64 + (lane >> 2);
    int n_base = col0 + wn * 32 + (lane & 3) * 2;

    if (mode == 0) {
        #pragma unroll
        for (int mi = 0; mi < 4; mi++) {
            int r = r_base + mi * 16;
            #pragma unroll
            for (int ni = 0; ni < 4; ni++) {
                int n = n_base + ni * 8;
                float b0 = bias[n], b1 = bias[n + 1];
                float2 v0 = make_float2(c[mi][ni][0] + b0, c[mi][ni][1] + b1);
                float2 v1 = make_float2(c[mi][ni][2] + b0, c[mi][ni][3] + b1);
                *(float2*)(outp + (size_t)r * CC + n)       = v0;
                *(float2*)(outp + (size_t)(r + 8) * CC + n) = v1;
            }
        }
    } else {
        int z = col0 >> 9;
        #pragma unroll
        for (int mi = 0; mi < 4; mi++) {
            int r = r_base + mi * 16;
            int b_ = r >> 10, t = r & (TT - 1);
            #pragma unroll
            for (int ni = 0; ni < 4; ni++) {
                int n = n_base + ni * 8;
                int nn = n & 511;
                int h = nn >> 6, d = nn & 63;
                float b0 = bias[n], b1 = bias[n + 1];
                float p00 = c[mi][ni][0] + b0, p01 = c[mi][ni][1] + b1;
                float p10 = c[mi][ni][2] + b0, p11 = c[mi][ni][3] + b1;
                __nv_bfloat16 h00 = __float2bfloat16(p00);
                __nv_bfloat16 h01 = __float2bfloat16(p01);
                __nv_bfloat16 h10 = __float2bfloat16(p10);
                __nv_bfloat16 h11 = __float2bfloat16(p11);
                __nv_bfloat16 l00 = __float2bfloat16(p00 - __bfloat162float(h00));
                __nv_bfloat16 l01 = __float2bfloat16(p01 - __bfloat162float(h01));
                __nv_bfloat16 l10 = __float2bfloat16(p10 - __bfloat162float(h10));
                __nv_bfloat16 l11 = __float2bfloat16(p11 - __bfloat162float(h11));
                if (z == 2) {
                    size_t vb = (((size_t)(b_ * HH + h)) * HD + d) * TT + t;
                    g_vthi[vb]          = h00;
                    g_vthi[vb + TT]     = h01;
                    g_vthi[vb + 8]      = h10;
                    g_vthi[vb + TT + 8] = h11;
                    g_vtlo[vb]          = l00;
                    g_vtlo[vb + TT]     = l01;
                    g_vtlo[vb + 8]      = l10;
                    g_vtlo[vb + TT + 8] = l11;
                } else {
                    __nv_bfloat16* dhi = (z == 0) ? g_qhi : g_khi;
                    __nv_bfloat16* dlo = (z == 0) ? g_qlo : g_klo;
                    size_t o = (((size_t)b_ * HH + h) * TT + t) * HD + d;
                    *(uint32_t*)(dhi + o)          = pack_bf2(h00, h01);
                    *(uint32_t*)(dhi + o + 8 * HD) = pack_bf2(h10, h11);
                    *(uint32_t*)(dlo + o)          = pack_bf2(l00, l01);
                    *(uint32_t*)(dlo + o + 8 * HD) = pack_bf2(l10, l11);
                }
            }
        }
    }
}

// ---------------------------------------------------------------------------
// attn_mma v4: in-kernel proj + slimmed softmax (packed cvt, rescale-skip)
// t-tile 256, 512 threads, 1 CTA/SM, cp.async double-buffered K/V
// ---------------------------------------------------------------------------
#define FA_QHI 0
#define FA_QLO 32768
#define FA_KHI 65536
#define FA_KLO 81920
#define FA_VHI 98304
#define FA_VLO 114688
#define FA_PHI 131072
#define FA_PLO 163840
#define FA_SMEM 196608

__global__ __launch_bounds__(512, 1) void attn_mma()
{
    extern __shared__ char smc[];
    int tid = threadIdx.x, lane = tid & 31, wid = tid >> 5;
    int bh = blockIdx.y, t0 = blockIdx.x * 256;

    uint32_t uQH = smem_u32(smc + FA_QHI);
    uint32_t uQL = smem_u32(smc + FA_QLO);
    uint32_t uKH = smem_u32(smc + FA_KHI);
    uint32_t uKL = smem_u32(smc + FA_KLO);
    uint32_t uVH = smem_u32(smc + FA_VHI);
    uint32_t uVL = smem_u32(smc + FA_VLO);
    uint32_t uPH = smem_u32(smc + FA_PHI);
    uint32_t uPL = smem_u32(smc + FA_PLO);

    size_t qb = (size_t)bh * TT * HD;
    size_t vtb = (size_t)bh * HD * TT;
    float* bandb = g_band + ((size_t)bh * TT + t0) * 136;

    // Q tile (256x64) hi/lo swizzled; rel_k staged into K/V scratch
    #pragma unroll
    for (int s = 0; s < 4; s++) {
        int vec = tid + s * 512;
        int r = vec >> 3, g8 = vec & 7;
        uint32_t dst = SWZ128((uint32_t)(r * 128 + g8 * 16));
        size_t src = qb + (size_t)(t0 + r) * HD + g8 * 8;
        *(uint4*)(smc + FA_QHI + dst) = *(const uint4*)(g_qhi + src);
        *(uint4*)(smc + FA_QLO + dst) = *(const uint4*)(g_qlo + src);
    }
    for (int vec = tid; vec < NRP * 8; vec += 512) {
        int r = vec >> 3, g8 = vec & 7;
        uint32_t dst = SWZ128((uint32_t)(r * 128 + g8 * 16));
        size_t src = (size_t)r * HD + g8 * 8;
        *(uint4*)(smc + FA_KHI + dst) = *(const uint4*)(g_rkhi + src);   // rkhi
        *(uint4*)(smc + FA_VHI + dst) = *(const uint4*)(g_rklo + src);   // rklo
    }
    for (int idx = tid; idx < 256 * 136; idx += 512) bandb[idx] = -1e30f;
    __syncthreads();

    int rbase = wid * 16 + (lane >> 2);

    // ---- in-kernel proj: proj[t, r] = q . rel_k^T for block rows ----
    {
        float cp[9][2][4];
        #pragma unroll
        for (int nf = 0; nf < 9; nf++)
            #pragma unroll
            for (int p = 0; p < 2; p++)
                #pragma unroll
                for (int e = 0; e < 4; e++) cp[nf][p][e] = 0.0f;

        #pragma unroll
        for (int ks = 0; ks < 4; ks++) {
            uint32_t aad = SWZ128((uint32_t)(
                (wid * 16 + (lane & 15)) * 128 + (ks * 16 + (lane >> 4) * 8) * 2));
            uint32_t ah[4], al[4];
            ldsm4(ah, uQH + aad);
            ldsm4(al, uQL + aad);
            int br_off = (lane & 7) + ((lane >> 4) << 3);
            int bk = ks * 16 + (((lane >> 3) & 1) << 3);
            #pragma unroll
            for (int nf = 0; nf < 9; nf++) {
                uint32_t bad = SWZ128((uint32_t)((nf * 16 + br_off) * 128 + bk * 2));
                uint32_t bh4[4], bl4[4];
                ldsm4(bh4, uKH + bad);
                ldsm4(bl4, uVH + bad);
                mma16816(cp[nf][0], ah, bh4);
                mma16816(cp[nf][0], ah, bl4);
                mma16816(cp[nf][0], al, bh4);
                mma16816(cp[nf][1], ah, bh4 + 2);
                mma16816(cp[nf][1], ah, bl4 + 2);
                mma16816(cp[nf][1], al, bh4 + 2);
            }
        }
        #pragma unroll
        for (int e2 = 0; e2 < 2; e2++) {
            int row = t0 + rbase + e2 * 8;
            float* prow = g_proj + ((size_t)bh * TT + row) * NR;
            #pragma unroll
            for (int nf = 0; nf < 9; nf++)
                #pragma unroll
                for (int p = 0; p < 2; p++) {
                    int col = nf * 16 + p * 8 + (lane & 3) * 2;
                    if (col < NR)     prow[col]     = cp[nf][p][e2 * 2];
                    if (col + 1 < NR) prow[col + 1] = cp[nf][p][e2 * 2 + 1];
                }
        }
    }
    __syncthreads();

    float m[2] = {-1e30f, -1e30f}, l[2] = {0.0f, 0.0f}, plo[2] = {0.0f, 0.0f};
    float c[4][2][4];
    #pragma unroll
    for (int nf = 0; nf < 4; nf++)
        #pragma unroll
        for (int p = 0; p < 2; p++)
            #pragma unroll
            for (int e = 0; e < 4; e++) c[nf][p][e] = 0.0f;

    const float scale = 0.044194173824159216f;

    float prow0[2], prow136[2];
    #pragma unroll
    for (int e2 = 0; e2 < 2; e2++) {
        int trow = t0 + rbase + e2 * 8;
        prow0[e2]   = g_proj[((size_t)bh * TT + trow) * NR];
        prow136[e2] = g_proj[((size_t)bh * TT + trow) * NR + 136];
    }

    auto load_kv = [&](int kc) {
        int k0 = kc * 64;
        uint32_t koff = (uint32_t)(kc & 1) * 8192u;
        int r = tid >> 3, g8 = tid & 7;
        uint32_t dst = SWZ128((uint32_t)(r * 128 + g8 * 16)) + koff;
        size_t ksrc = qb + (size_t)(k0 + r) * HD + g8 * 8;
        size_t vsrc = vtb + (size_t)r * TT + k0 + g8 * 8;
        CP_A16(uKH + dst, g_khi + ksrc);
        CP_A16(uKL + dst, g_klo + ksrc);
        CP_A16(uVH + dst, g_vthi + vsrc);
        CP_A16(uVL + dst, g_vtlo + vsrc);
        CP_COMMIT();
    };

    load_kv(0);
    load_kv(1);

    for (int kc = 0; kc < 16; kc++) {
        int k0 = kc * 64;
        uint32_t koff = (uint32_t)(kc & 1) * 8192u;
        bool mixed = (k0 > t0 - 131) && (k0 < t0 + 323);
        bool lowside = (k0 < t0);

        if (kc < 15) { CP_WAIT1(); } else { CP_WAIT0(); }
        __syncthreads();

        float cs[4][2][4];
        #pragma unroll
        for (int nf = 0; nf < 4; nf++)
            #pragma unroll
            for (int p = 0; p < 2; p++)
                #pragma unroll
                for (int e = 0; e < 4; e++) cs[nf][p][e] = 0.0f;

        #pragma unroll
        for (int ks = 0; ks < 4; ks++) {
            uint32_t aad = SWZ128((uint32_t)(
                (wid * 16 + (lane & 15)) * 128 + (ks * 16 + (lane >> 4) * 8) * 2));
            uint32_t ah[4], al[4];
            ldsm4(ah, uQH + aad);
            ldsm4(al, uQL + aad);
            int br_off = (lane & 7) + ((lane >> 4) << 3);
            int bk = ks * 16 + (((lane >> 3) & 1) << 3);
            #pragma unroll
            for (int nf = 0; nf < 4; nf++) {
                uint32_t bad = SWZ128((uint32_t)((nf * 16 + br_off) * 128 + bk * 2)) + koff;
                uint32_t bh4[4], bl4[4];
                ldsm4(bh4, uKH + bad);
                ldsm4(bl4, uKL + bad);
                mma16816(cs[nf][0], ah, bh4);
                mma16816(cs[nf][0], ah, bl4);
                mma16816(cs[nf][0], al, bh4);
                mma16816(cs[nf][1], ah, bh4 + 2);
                mma16816(cs[nf][1], ah, bl4 + 2);
                mma16816(cs[nf][1], al, bh4 + 2);
            }
        }

        if (mixed) {
            #pragma unroll
            for (int e2 = 0; e2 < 2; e2++) {
                int rowl = rbase + e2 * 8;
                int trow = t0 + rowl;
                const float* prow = g_proj + ((size_t)bh * TT + trow) * NR;
                float mx = -1e30f;
                #pragma unroll
                for (int nf = 0; nf < 4; nf++)
                    #pragma unroll
                    for (int p = 0; p < 2; p++)
                        #pragma unroll
                        for (int j = 0; j < 2; j++) {
                            int kg = k0 + nf * 16 + p * 8 + (lane & 3) * 2 + j;
                            int dist = kg - trow;
                            dist = dist < -MAXR ? -MAXR : (dist > MAXR ? MAXR : dist);
                            float v = (cs[nf][p][e2 * 2 + j] + prow[dist + MAXR]) * scale;
                            cs[nf][p][e2 * 2 + j] = v;
                            mx = fmaxf(mx, v);
                        }
                mx = fmaxf(mx, __shfl_xor_sync(0xffffffffu, mx, 1));
                mx = fmaxf(mx, __shfl_xor_sync(0xffffffffu, mx, 2));
                if (mx > m[e2]) {
                    float f = __expf(m[e2] - mx);
                    m[e2] = mx;
                    l[e2] *= f; plo[e2] *= f;
                    #pragma unroll
                    for (int nf = 0; nf < 4; nf++)
                        #pragma unroll
                        for (int p = 0; p < 2; p++) {
                            c[nf][p][e2 * 2]     *= f;
                            c[nf][p][e2 * 2 + 1] *= f;
                        }
                }
                float mnew = m[e2];

                float es = 0.0f, pl = 0.0f;
                #pragma unroll
                for (int nf = 0; nf < 4; nf++)
                    #pragma unroll
                    for (int p = 0; p < 2; p++) {
                        float v0 = cs[nf][p][e2 * 2], v1 = cs[nf][p][e2 * 2 + 1];
                        float p0 = __expf(v0 - mnew), p1 = __expf(v1 - mnew);
                        es += p0 + p1;
                        int kcol = nf * 16 + p * 8 + (lane & 3) * 2;
                        int d0 = (k0 + kcol) - trow;
                        if ((unsigned)(d0 + 67) <= 134u) bandb[rowl * 136 + d0 + 67] = v0;
                        else if (d0 <= -MAXR) pl += p0;
                        int d1 = d0 + 1;
                        if ((unsigned)(d1 + 67) <= 134u) bandb[rowl * 136 + d1 + 67] = v1;
                        else if (d1 <= -MAXR) pl += p1;

                        uint32_t hp, lp;
                        split2(p0, p1, hp, lp);
                        uint32_t dst = SWZ128((uint32_t)(rowl * 128 + kcol * 2));
                        *(uint32_t*)(smc + FA_PHI + dst) = hp;
                        *(uint32_t*)(smc + FA_PLO + dst) = lp;
                    }
                es += __shfl_xor_sync(0xffffffffu, es, 1);
                es += __shfl_xor_sync(0xffffffffu, es, 2);
                pl += __shfl_xor_sync(0xffffffffu, pl, 1);
                pl += __shfl_xor_sync(0xffffffffu, pl, 2);
                l[e2] += es; plo[e2] += pl;
            }
        } else {
            #pragma unroll
            for (int e2 = 0; e2 < 2; e2++) {
                int rowl = rbase + e2 * 8;
                float cadd = lowside ? prow0[e2] : prow136[e2];
                float mx = -1e30f;
                #pragma unroll
                for (int nf = 0; nf < 4; nf++)
                    #pragma unroll
                    for (int p = 0; p < 2; p++)
                        #pragma unroll
                        for (int j = 0; j < 2; j++) {
                            float v = (cs[nf][p][e2 * 2 + j] + cadd) * scale;
                            cs[nf][p][e2 * 2 + j] = v;
                            mx = fmaxf(mx, v);
                        }
                mx = fmaxf(mx, __shfl_xor_sync(0xffffffffu, mx, 1));
                mx = fmaxf(mx, __shfl_xor_sync(0xffffffffu, mx, 2));
                if (mx > m[e2]) {
                    float f = __expf(m[e2] - mx);
                    m[e2] = mx;
                    l[e2] *= f; plo[e2] *= f;
                    #pragma unroll
                    for (int nf = 0; nf < 4; nf++)
                        #pragma unroll
                        for (int p = 0; p < 2; p++) {
                            c[nf][p][e2 * 2]     *= f;
                            c[nf][p][e2 * 2 + 1] *= f;
                        }
                }
                float mnew = m[e2];

                float es = 0.0f;
                #pragma unroll
                for (int nf = 0; nf < 4; nf++)
                    #pragma unroll
                    for (int p = 0; p < 2; p++) {
                        float p0 = __expf(cs[nf][p][e2 * 2]     - mnew);
                        float p1 = __expf(cs[nf][p][e2 * 2 + 1] - mnew);
                        es += p0 + p1;
                        int kcol = nf * 16 + p * 8 + (lane & 3) * 2;
                        uint32_t hp, lp;
                        split2(p0, p1, hp, lp);
                        uint32_t dst = SWZ128((uint32_t)(rowl * 128 + kcol * 2));
                        *(uint32_t*)(smc + FA_PHI + dst) = hp;
                        *(uint32_t*)(smc + FA_PLO + dst) = lp;
                    }
                es += __shfl_xor_sync(0xffffffffu, es, 1);
                es += __shfl_xor_sync(0xffffffffu, es, 2);
                l[e2] += es;
                if (lowside) plo[e2] += es;
            }
        }
        __syncwarp();

        #pragma unroll
        for (int ks = 0; ks < 4; ks++) {
            uint32_t aad = SWZ128((uint32_t)(
                (wid * 16 + (lane & 15)) * 128 + (ks * 16 + (lane >> 4) * 8) * 2));
            uint32_t ah[4], al[4];
            ldsm4(ah, uPH + aad);
            ldsm4(al, uPL + aad);
            int br_off = (lane & 7) + ((lane >> 4) << 3);
            int bk = ks * 16 + (((lane >> 3) & 1) << 3);
            #pragma unroll
            for (int nf = 0; nf < 4; nf++) {
                uint32_t bad = SWZ128((uint32_t)((nf * 16 + br_off) * 128 + bk * 2)) + koff;
                uint32_t bh4[4], bl4[4];
                ldsm4(bh4, uVH + bad);
                ldsm4(bl4, uVL + bad);
                mma16816(c[nf][0], ah, bh4);
                mma16816(c[nf][0], ah, bl4);
                mma16816(c[nf][0], al, bh4);
                mma16816(c[nf][1], ah, bh4 + 2);
                mma16816(c[nf][1], ah, bl4 + 2);
                mma16816(c[nf][1], al, bh4 + 2);
            }
        }
        __syncthreads();
        if (kc + 2 < 16) load_kv(kc + 2);
    }

    // ---- epilogue: band @ rel_vt via MMA ----
    float* m_s    = (float*)(smc + FA_KHI);
    float* intu_s = (float*)(smc + FA_KHI + 1024);
    if ((lane & 3) == 0) {
        m_s[rbase]     = m[0];
        m_s[rbase + 8] = m[1];
    }
    __syncthreads();

    int lrow = tid >> 1;
    float mrow = m_s[lrow];
    float intu_loc = 0.0f;

    for (int ck = 0; ck < 3; ck++) {
        int cb0 = ck * 64;
        #pragma unroll
        for (int g = 0; g < 4; g++) {
            int cc = (tid & 1) * 32 + g * 8;
            float p[8];
            #pragma unroll
            for (int j = 0; j < 8; j++) {
                int col = cb0 + cc + j;
                float lg = (col < 135) ? bandb[lrow * 136 + col] : -1e30f;
                p[j] = __expf(lg - mrow);
                intu_loc += p[j];
            }
            uint32_t hi[4], lo[4];
            #pragma unroll
            for (int j = 0; j < 4; j++)
                split2(p[2 * j], p[2 * j + 1], hi[j], lo[j]);
            uint32_t dst = SWZ128((uint32_t)(lrow * 128 + cc * 2));
            *(uint4*)(smc + FA_PHI + dst) = make_uint4(hi[0], hi[1], hi[2], hi[3]);
            *(uint4*)(smc + FA_PLO + dst) = make_uint4(lo[0], lo[1], lo[2], lo[3]);
        }
        {
            int r = tid >> 3, g8 = tid & 7;
            uint32_t dst = SWZ128((uint32_t)(r * 128 + g8 * 16));
            size_t src = (size_t)r * 192 + cb0 + g8 * 8;
            *(uint4*)(smc + FA_VHI + dst) = *(const uint4*)(g_rvthi + src);
            *(uint4*)(smc + FA_VLO + dst) = *(const uint4*)(g_rvtlo + src);
        }
        __syncthreads();

        #pragma unroll
        for (int ks = 0; ks < 4; ks++) {
            uint32_t aad = SWZ128((uint32_t)(
                (wid * 16 + (lane & 15)) * 128 + (ks * 16 + (lane >> 4) * 8) * 2));
            uint32_t ah[4], al[4];
            ldsm4(ah, uPH + aad);
            ldsm4(al, uPL + aad);
            int br_off = (lane & 7) + ((lane >> 4) << 3);
            int bk = ks * 16 + (((lane >> 3) & 1) << 3);
            #pragma unroll
            for (int nf = 0; nf < 4; nf++) {
                uint32_t bad = SWZ128((uint32_t)((nf * 16 + br_off) * 128 + bk * 2));
                uint32_t bh4[4], bl4[4];
                ldsm4(bh4, uVH + bad);
                ldsm4(bl4, uVL + bad);
                mma16816(c[nf][0], ah, bh4);
                mma16816(c[nf][0], ah, bl4);
                mma16816(c[nf][0], al, bh4);
                mma16816(c[nf][1], ah, bh4 + 2);
                mma16816(c[nf][1], ah, bl4 + 2);
                mma16816(c[nf][1], al, bh4 + 2);
            }
        }
        __syncthreads();
    }

    intu_loc += __shfl_xor_sync(0xffffffffu, intu_loc, 1);
    if ((tid & 1) == 0) intu_s[lrow] = intu_loc;
    __syncthreads();

    int b_ = bh >> 3, h = bh & 7;
    #pragma unroll
    for (int e2 = 0; e2 < 2; e2++) {
        int rowl = rbase + e2 * 8;
        int t = t0 + rowl;
        float lr = l[e2], pl = plo[e2];
        float phi = lr - pl - intu_s[rowl];
        float inv = 1.0f / lr;
        #pragma unroll
        for (int nf = 0; nf < 4; nf++)
            #pragma unroll
            for (int p = 0; p < 2; p++) {
                int d = nf * 16 + p * 8 + (lane & 3) * 2;
                float w0 = c[nf][p][e2 * 2]     + pl * g_rv0[d]
                         + phi * g_rv136[d];
                float w1 = c[nf][p][e2 * 2 + 1] + pl * g_rv0[d + 1]
                         + phi * g_rv136[d + 1];
                float o0 = w0 * inv, o1 = w1 * inv;
                size_t ob = ((size_t)(b_ * TT + t)) * CC + h * HD + d;
                uint32_t hp, lp2;
                split2(o0, o1, hp, lp2);
                *(uint32_t*)(g_yhi + ob) = hp;
                *(uint32_t*)(g_ylo + ob) = lp2;
            }
    }
}

// ---------------------------------------------------------------------------
extern "C" void kernel_launch(void* const* d_in, const int* in_sizes, int n_in,
                              void* d_out, int out_size)
{
    const float* x     = (const float*)d_in[0];
    const float* Wq    = (const float*)d_in[1];
    const float* bq    = (const float*)d_in[2];
    const float* Wk    = (const float*)d_in[3];
    const float* bk    = (const float*)d_in[4];
    const float* Wv    = (const float*)d_in[5];
    const float* bv    = (const float*)d_in[6];
    const float* Wo    = (const float*)d_in[7];
    const float* bo    = (const float*)d_in[8];
    const float* rel_k = (const float*)d_in[9];
    const float* rel_v = (const float*)d_in[10];
    float* out = (float*)d_out;

    cudaFuncSetAttribute(gemm_mma, cudaFuncAttributeMaxDynamicSharedMemorySize,
                         GT_SMEM);
    cudaFuncSetAttribute(attn_mma, cudaFuncAttributeMaxDynamicSharedMemorySize,
                         FA_SMEM);

    conv_edge<<<1, 64>>>(rel_v);
    conv_all<<<1024, 512>>>(x, Wq, Wk, Wv, Wo, bq, bk, bv, bo, rel_k, rel_v);
    gemm_mma<<<dim3(12, 64), 256, GT_SMEM>>>(nullptr, 1);
    attn_mma<<<dim3(4, 64), 512, FA_SMEM>>>();
    gemm_mma<<<dim3(4, 64), 256, GT_SMEM>>>(out, 0);
}

// round 15
// speedup vs baseline: 3.2202x; 1.0675x over previous
#include <cuda_runtime.h>
#include <cuda_bf16.h>
#include <cstdint>

// Problem constants
#define BB   8
#define TT   1024
#define CC   512
#define HH   8
#define HD   64
#define NR   137
#define MAXR 68
#define BH   64
#define MM   8192
#define NRP  144

// ---------------------------------------------------------------------------
// Scratch (device globals)
// ---------------------------------------------------------------------------
static __device__ float g_proj[BH * TT * NR];
static __device__ float g_band[BH * TT * 136];
static __device__ float g_rv0[HD];
static __device__ float g_rv136[HD];

static __device__ __nv_bfloat16 g_qhi[BH * TT * HD];
static __device__ __nv_bfloat16 g_qlo[BH * TT * HD];
static __device__ __nv_bfloat16 g_khi[BH * TT * HD];
static __device__ __nv_bfloat16 g_klo[BH * TT * HD];
static __device__ __nv_bfloat16 g_vthi[BH * HD * TT];   // [bh][d][t]
static __device__ __nv_bfloat16 g_vtlo[BH * HD * TT];
static __device__ __nv_bfloat16 g_rkhi[NRP * HD];
static __device__ __nv_bfloat16 g_rklo[NRP * HD];
static __device__ __nv_bfloat16 g_rvthi[HD * 192];      // rvt[d][j] = rel_v[j+1][d]
static __device__ __nv_bfloat16 g_rvtlo[HD * 192];

static __device__ __nv_bfloat16 g_xhi[MM * CC];
static __device__ __nv_bfloat16 g_xlo[MM * CC];
static __device__ __nv_bfloat16 g_yhi[MM * CC];
static __device__ __nv_bfloat16 g_ylo[MM * CC];
static __device__ __nv_bfloat16 g_wthi[4 * CC * CC];
static __device__ __nv_bfloat16 g_wtlo[4 * CC * CC];
static __device__ float g_bias[4 * CC];

// ---------------------------------------------------------------------------
// helpers
// ---------------------------------------------------------------------------
__device__ __forceinline__ uint32_t smem_u32(const void* p) {
    uint32_t a;
    asm("{ .reg .u64 t; cvta.to.shared.u64 t, %1; cvt.u32.u64 %0, t; }"
        : "=r"(a) : "l"(p));
    return a;
}
__device__ __forceinline__ void ldsm4(uint32_t* r, uint32_t addr) {
    asm volatile("ldmatrix.sync.aligned.m8n8.x4.shared.b16 {%0,%1,%2,%3}, [%4];"
        : "=r"(r[0]), "=r"(r[1]), "=r"(r[2]), "=r"(r[3]) : "r"(addr));
}
__device__ __forceinline__ void ldsm2(uint32_t* r, uint32_t addr) {
    asm volatile("ldmatrix.sync.aligned.m8n8.x2.shared.b16 {%0,%1}, [%2];"
        : "=r"(r[0]), "=r"(r[1]) : "r"(addr));
}
__device__ __forceinline__ void mma16816(float* c, const uint32_t* a, const uint32_t* b) {
    asm volatile(
        "mma.sync.aligned.m16n8k16.row.col.f32.bf16.bf16.f32 "
        "{%0,%1,%2,%3}, {%4,%5,%6,%7}, {%8,%9}, {%0,%1,%2,%3};"
        : "+f"(c[0]), "+f"(c[1]), "+f"(c[2]), "+f"(c[3])
        : "r"(a[0]), "r"(a[1]), "r"(a[2]), "r"(a[3]), "r"(b[0]), "r"(b[1]));
}
#define SWZ128(b) ((b) ^ (((b) >> 3) & 0x70))

#define CP_A16(dst, src) \
    asm volatile("cp.async.cg.shared.global [%0], [%1], 16;" \
                 :: "r"(dst), "l"(src) : "memory")
#define CP_COMMIT() asm volatile("cp.async.commit_group;" ::: "memory")
#define CP_WAIT1()  asm volatile("cp.async.wait_group 1;" ::: "memory")
#define CP_WAIT0()  asm volatile("cp.async.wait_group 0;" ::: "memory")

__device__ __forceinline__ uint32_t pack_bf2(__nv_bfloat16 a, __nv_bfloat16 b) {
    __nv_bfloat162 t = {a, b};
    return *(uint32_t*)&t;
}

// packed hi/lo split: {p0 low, p1 high}
__device__ __forceinline__ void split2(float p0, float p1, uint32_t& hi, uint32_t& lo)
{
    uint32_t h;
    asm("cvt.rn.bf16x2.f32 %0, %1, %2;" : "=r"(h) : "f"(p1), "f"(p0));
    float f0 = __uint_as_float(h << 16);
    float f1 = __uint_as_float(h & 0xFFFF0000u);
    uint32_t l;
    asm("cvt.rn.bf16x2.f32 %0, %1, %2;" : "=r"(l) : "f"(p1 - f1), "f"(p0 - f0));
    hi = h; lo = l;
}

// ---------------------------------------------------------------------------
__global__ void conv_edge(const float* __restrict__ rel_v)
{
    int d = threadIdx.x;
    if (d < HD) {
        g_rv0[d]   = rel_v[d];
        g_rv136[d] = rel_v[136 * HD + d];
    }
}

__global__ __launch_bounds__(512) void conv_all(
    const float* __restrict__ x,
    const float* __restrict__ Wq, const float* __restrict__ Wk,
    const float* __restrict__ Wv, const float* __restrict__ Wo,
    const float* __restrict__ bq, const float* __restrict__ bk,
    const float* __restrict__ bv, const float* __restrict__ bo,
    const float* __restrict__ rel_k, const float* __restrict__ rel_v)
{
    int gid = blockIdx.x * blockDim.x + threadIdx.x;
    int nth = gridDim.x * blockDim.x;
    for (int idx = gid; idx < 4 * CC * CC; idx += nth) {
        int z = idx >> 18;
        int rem = idx & (CC * CC - 1);
        int k = rem >> 9, n = rem & 511;
        const float* W = (z == 0) ? Wq : (z == 1) ? Wk : (z == 2) ? Wv : Wo;
        float v = W[k * CC + n];
        __nv_bfloat16 h = __float2bfloat16(v);
        size_t dst = (size_t)z * CC * CC + (size_t)n * CC + k;
        g_wthi[dst] = h;
        g_wtlo[dst] = __float2bfloat16(v - __bfloat162float(h));
    }
    for (int i = gid; i < MM * CC / 4; i += nth) {
        float4 v = *(const float4*)(x + (size_t)i * 4);
        float vv[4] = {v.x, v.y, v.z, v.w};
        #pragma unroll
        for (int j = 0; j < 4; j++) {
            __nv_bfloat16 h = __float2bfloat16(vv[j]);
            g_xhi[(size_t)i * 4 + j] = h;
            g_xlo[(size_t)i * 4 + j] = __float2bfloat16(vv[j] - __bfloat162float(h));
        }
    }
    for (int idx = gid; idx < NRP * HD; idx += nth) {
        int r = idx >> 6, d = idx & 63;
        float v = (r < NR) ? rel_k[r * HD + d] : 0.0f;
        __nv_bfloat16 h = __float2bfloat16(v);
        g_rkhi[idx] = h;
        g_rklo[idx] = __float2bfloat16(v - __bfloat162float(h));
    }
    for (int idx = gid; idx < HD * 192; idx += nth) {
        int d = idx / 192, j = idx - d * 192;
        float v = (j < 135) ? rel_v[(j + 1) * HD + d] : 0.0f;
        __nv_bfloat16 h = __float2bfloat16(v);
        g_rvthi[idx] = h;
        g_rvtlo[idx] = __float2bfloat16(v - __bfloat162float(h));
    }
    if (gid < 4 * CC) {
        int z = gid >> 9, n = gid & 511;
        const float* bsrc = (z == 0) ? bq : (z == 1) ? bk : (z == 2) ? bv : bo;
        g_bias[gid] = bsrc[n];
    }
}

// ---------------------------------------------------------------------------
// bf16x3 warp-MMA GEMM, 2-stage cp.async pipeline (unchanged)
// ---------------------------------------------------------------------------
#define GT_A_HI 0
#define GT_A_LO 16384
#define GT_B_HI 32768
#define GT_B_LO 49152
#define GT_SMEM 65536

__global__ __launch_bounds__(256, 2) void gemm_mma(float* __restrict__ outp, int mode)
{
    extern __shared__ char smc[];
    const __nv_bfloat16 *Ahi, *Alo, *Bhi, *Blo;
    const float* bias;
    if (mode == 1) {
        Ahi = g_xhi; Alo = g_xlo; Bhi = g_wthi; Blo = g_wtlo; bias = g_bias;
    } else {
        Ahi = g_yhi; Alo = g_ylo;
        Bhi = g_wthi + 3 * CC * CC; Blo = g_wtlo + 3 * CC * CC;
        bias = g_bias + 3 * CC;
    }

    int tid = threadIdx.x, lane = tid & 31, wid = tid >> 5;
    int wm = wid >> 2, wn = wid & 3;
    int row0 = blockIdx.y * 128, col0 = blockIdx.x * 128;

    uint32_t uAH = smem_u32(smc + GT_A_HI);
    uint32_t uAL = smem_u32(smc + GT_A_LO);
    uint32_t uBH = smem_u32(smc + GT_B_HI);
    uint32_t uBL = smem_u32(smc + GT_B_LO);

    float c[4][4][4];
    #pragma unroll
    for (int mi = 0; mi < 4; mi++)
        #pragma unroll
        for (int ni = 0; ni < 4; ni++)
            #pragma unroll
            for (int e = 0; e < 4; e++) c[mi][ni][e] = 0.0f;

    auto load_chunk = [&](int kc) {
        int k0 = kc * 32;
        int sb64 = (kc & 1) * 64;
        #pragma unroll
        for (int s2 = 0; s2 < 2; s2++) {
            int vec = tid + s2 * 256;
            int idx = vec >> 2, v4 = vec & 3;
            int r = (idx & ~7) | ((idx & 1) << 2) | ((idx >> 1) & 3);
            uint32_t dst = SWZ128((uint32_t)(r * 128 + sb64 + v4 * 16));
            size_t asrc = (size_t)(row0 + r) * CC + k0 + v4 * 8;
            size_t bsrc = (size_t)(col0 + r) * CC + k0 + v4 * 8;
            CP_A16(uAH + dst, Ahi + asrc);
            CP_A16(uAL + dst, Alo + asrc);
            CP_A16(uBH + dst, Bhi + bsrc);
            CP_A16(uBL + dst, Blo + bsrc);
        }
        CP_COMMIT();
    };

    load_chunk(0);
    load_chunk(1);

    for (int kc = 0; kc < 16; kc++) {
        if (kc < 15) { CP_WAIT1(); } else { CP_WAIT0(); }
        __syncthreads();

        int sbe = (kc & 1) * 32;
        #pragma unroll
        for (int ks = 0; ks < 2; ks++) {
            int kbase = sbe + ks * 16;
            int lp = lane & 15;
            int bkb = kbase + (lp >> 3) * 8;
            uint32_t bh[4][2], bl[4][2];
            #pragma unroll
            for (int ni = 0; ni < 4; ni++) {
                int nloc = wn * 32 + ni * 8 + (lp & 7);
                uint32_t ad = SWZ128((uint32_t)(nloc * 128 + bkb * 2));
                ldsm2(bh[ni], uBH + ad);
                ldsm2(bl[ni], uBL + ad);
            }
            int akb = kbase + (lane >> 4) * 8;
            int mlp = lane & 15;
            #pragma unroll
            for (int mi = 0; mi < 4; mi++) {
                int mloc = wm * 64 + mi * 16 + mlp;
                uint32_t ad = SWZ128((uint32_t)(mloc * 128 + akb * 2));
                uint32_t ah[4], al[4];
                ldsm4(ah, uAH + ad);
                ldsm4(al, uAL + ad);
                #pragma unroll
                for (int ni = 0; ni < 4; ni++) {
                    mma16816(c[mi][ni], ah, bh[ni]);
                    mma16816(c[mi][ni], ah, bl[ni]);
                    mma16816(c[mi][ni], al, bh[ni]);
                }
            }
        }
        __syncthreads();
        if (kc + 2 < 16) load_chunk(kc + 2);
    }

    int r_base = row0 + wm * 64 + (lane >> 2);
    int n_base = col0 + wn * 32 + (lane & 3) * 2;

    if (mode == 0) {
        #pragma unroll
        for (int mi = 0; mi < 4; mi++) {
            int r = r_base + mi * 16;
            #pragma unroll
            for (int ni = 0; ni < 4; ni++) {
                int n = n_base + ni * 8;
                float b0 = bias[n], b1 = bias[n + 1];
                float2 v0 = make_float2(c[mi][ni][0] + b0, c[mi][ni][1] + b1);
                float2 v1 = make_float2(c[mi][ni][2] + b0, c[mi][ni][3] + b1);
                *(float2*)(outp + (size_t)r * CC + n)       = v0;
                *(float2*)(outp + (size_t)(r + 8) * CC + n) = v1;
            }
        }
    } else {
        int z = col0 >> 9;
        #pragma unroll
        for (int mi = 0; mi < 4; mi++) {
            int r = r_base + mi * 16;
            int b_ = r >> 10, t = r & (TT - 1);
            #pragma unroll
            for (int ni = 0; ni < 4; ni++) {
                int n = n_base + ni * 8;
                int nn = n & 511;
                int h = nn >> 6, d = nn & 63;
                float b0 = bias[n], b1 = bias[n + 1];
                float p00 = c[mi][ni][0] + b0, p01 = c[mi][ni][1] + b1;
                float p10 = c[mi][ni][2] + b0, p11 = c[mi][ni][3] + b1;
                __nv_bfloat16 h00 = __float2bfloat16(p00);
                __nv_bfloat16 h01 = __float2bfloat16(p01);
                __nv_bfloat16 h10 = __float2bfloat16(p10);
                __nv_bfloat16 h11 = __float2bfloat16(p11);
                __nv_bfloat16 l00 = __float2bfloat16(p00 - __bfloat162float(h00));
                __nv_bfloat16 l01 = __float2bfloat16(p01 - __bfloat162float(h01));
                __nv_bfloat16 l10 = __float2bfloat16(p10 - __bfloat162float(h10));
                __nv_bfloat16 l11 = __float2bfloat16(p11 - __bfloat162float(h11));
                if (z == 2) {
                    size_t vb = (((size_t)(b_ * HH + h)) * HD + d) * TT + t;
                    g_vthi[vb]          = h00;
                    g_vthi[vb + TT]     = h01;
                    g_vthi[vb + 8]      = h10;
                    g_vthi[vb + TT + 8] = h11;
                    g_vtlo[vb]          = l00;
                    g_vtlo[vb + TT]     = l01;
                    g_vtlo[vb + 8]      = l10;
                    g_vtlo[vb + TT + 8] = l11;
                } else {
                    __nv_bfloat16* dhi = (z == 0) ? g_qhi : g_khi;
                    __nv_bfloat16* dlo = (z == 0) ? g_qlo : g_klo;
                    size_t o = (((size_t)b_ * HH + h) * TT + t) * HD + d;
                    *(uint32_t*)(dhi + o)          = pack_bf2(h00, h01);
                    *(uint32_t*)(dhi + o + 8 * HD) = pack_bf2(h10, h11);
                    *(uint32_t*)(dlo + o)          = pack_bf2(l00, l01);
                    *(uint32_t*)(dlo + o + 8 * HD) = pack_bf2(l10, l11);
                }
            }
        }
    }
}

// ---------------------------------------------------------------------------
// attn_mma v5: register-resident P fragments, fragment-layout epilogue, exp2
// t-tile 256, 512 threads, smem 128 KB
// ---------------------------------------------------------------------------
#define FA_QHI 0
#define FA_QLO 32768
#define FA_KHI 65536
#define FA_KLO 81920
#define FA_VHI 98304
#define FA_VLO 114688
#define FA_SMEM 131072

__global__ __launch_bounds__(512, 1) void attn_mma()
{
    extern __shared__ char smc[];
    int tid = threadIdx.x, lane = tid & 31, wid = tid >> 5;
    int bh = blockIdx.y, t0 = blockIdx.x * 256;

    uint32_t uQH = smem_u32(smc + FA_QHI);
    uint32_t uQL = smem_u32(smc + FA_QLO);
    uint32_t uKH = smem_u32(smc + FA_KHI);
    uint32_t uKL = smem_u32(smc + FA_KLO);
    uint32_t uVH = smem_u32(smc + FA_VHI);
    uint32_t uVL = smem_u32(smc + FA_VLO);

    size_t qb = (size_t)bh * TT * HD;
    size_t vtb = (size_t)bh * HD * TT;
    float* bandb = g_band + ((size_t)bh * TT + t0) * 136;

    // Q tile (256x64) hi/lo swizzled; rel_k staged into K/V scratch
    #pragma unroll
    for (int s = 0; s < 4; s++) {
        int vec = tid + s * 512;
        int r = vec >> 3, g8 = vec & 7;
        uint32_t dst = SWZ128((uint32_t)(r * 128 + g8 * 16));
        size_t src = qb + (size_t)(t0 + r) * HD + g8 * 8;
        *(uint4*)(smc + FA_QHI + dst) = *(const uint4*)(g_qhi + src);
        *(uint4*)(smc + FA_QLO + dst) = *(const uint4*)(g_qlo + src);
    }
    for (int vec = tid; vec < NRP * 8; vec += 512) {
        int r = vec >> 3, g8 = vec & 7;
        uint32_t dst = SWZ128((uint32_t)(r * 128 + g8 * 16));
        size_t src = (size_t)r * HD + g8 * 8;
        *(uint4*)(smc + FA_KHI + dst) = *(const uint4*)(g_rkhi + src);
        *(uint4*)(smc + FA_VHI + dst) = *(const uint4*)(g_rklo + src);
    }
    for (int idx = tid; idx < 256 * 136; idx += 512) bandb[idx] = -1e30f;
    __syncthreads();

    int rbase = wid * 16 + (lane >> 2);

    // ---- in-kernel proj (raw, unscaled) ----
    {
        float cp[9][2][4];
        #pragma unroll
        for (int nf = 0; nf < 9; nf++)
            #pragma unroll
            for (int p = 0; p < 2; p++)
                #pragma unroll
                for (int e = 0; e < 4; e++) cp[nf][p][e] = 0.0f;

        #pragma unroll
        for (int ks = 0; ks < 4; ks++) {
            uint32_t aad = SWZ128((uint32_t)(
                (wid * 16 + (lane & 15)) * 128 + (ks * 16 + (lane >> 4) * 8) * 2));
            uint32_t ah[4], al[4];
            ldsm4(ah, uQH + aad);
            ldsm4(al, uQL + aad);
            int br_off = (lane & 7) + ((lane >> 4) << 3);
            int bk = ks * 16 + (((lane >> 3) & 1) << 3);
            #pragma unroll
            for (int nf = 0; nf < 9; nf++) {
                uint32_t bad = SWZ128((uint32_t)((nf * 16 + br_off) * 128 + bk * 2));
                uint32_t bh4[4], bl4[4];
                ldsm4(bh4, uKH + bad);
                ldsm4(bl4, uVH + bad);
                mma16816(cp[nf][0], ah, bh4);
                mma16816(cp[nf][0], ah, bl4);
                mma16816(cp[nf][0], al, bh4);
                mma16816(cp[nf][1], ah, bh4 + 2);
                mma16816(cp[nf][1], ah, bl4 + 2);
                mma16816(cp[nf][1], al, bh4 + 2);
            }
        }
        #pragma unroll
        for (int e2 = 0; e2 < 2; e2++) {
            int row = t0 + rbase + e2 * 8;
            float* prow = g_proj + ((size_t)bh * TT + row) * NR;
            #pragma unroll
            for (int nf = 0; nf < 9; nf++)
                #pragma unroll
                for (int p = 0; p < 2; p++) {
                    int col = nf * 16 + p * 8 + (lane & 3) * 2;
                    if (col < NR)     prow[col]     = cp[nf][p][e2 * 2];
                    if (col + 1 < NR) prow[col + 1] = cp[nf][p][e2 * 2 + 1];
                }
        }
    }
    __syncthreads();

    float m[2] = {-1e30f, -1e30f}, l[2] = {0.0f, 0.0f}, plo[2] = {0.0f, 0.0f};
    float c[4][2][4];
    #pragma unroll
    for (int nf = 0; nf < 4; nf++)
        #pragma unroll
        for (int p = 0; p < 2; p++)
            #pragma unroll
            for (int e = 0; e < 4; e++) c[nf][p][e] = 0.0f;

    // base-2 logits: scale * log2(e)
    const float SCALE2 = 0.044194173824159216f * 1.4426950408889634f;

    float prow0[2], prow136[2];
    #pragma unroll
    for (int e2 = 0; e2 < 2; e2++) {
        int trow = t0 + rbase + e2 * 8;
        prow0[e2]   = g_proj[((size_t)bh * TT + trow) * NR];
        prow136[e2] = g_proj[((size_t)bh * TT + trow) * NR + 136];
    }

    auto load_kv = [&](int kc) {
        int k0 = kc * 64;
        uint32_t koff = (uint32_t)(kc & 1) * 8192u;
        int r = tid >> 3, g8 = tid & 7;
        uint32_t dst = SWZ128((uint32_t)(r * 128 + g8 * 16)) + koff;
        size_t ksrc = qb + (size_t)(k0 + r) * HD + g8 * 8;
        size_t vsrc = vtb + (size_t)r * TT + k0 + g8 * 8;
        CP_A16(uKH + dst, g_khi + ksrc);
        CP_A16(uKL + dst, g_klo + ksrc);
        CP_A16(uVH + dst, g_vthi + vsrc);
        CP_A16(uVL + dst, g_vtlo + vsrc);
        CP_COMMIT();
    };

    load_kv(0);
    load_kv(1);

    for (int kc = 0; kc < 16; kc++) {
        int k0 = kc * 64;
        uint32_t koff = (uint32_t)(kc & 1) * 8192u;
        bool mixed = (k0 > t0 - 131) && (k0 < t0 + 323);
        bool lowside = (k0 < t0);

        if (kc < 15) { CP_WAIT1(); } else { CP_WAIT0(); }
        __syncthreads();

        float cs[4][2][4];
        #pragma unroll
        for (int nf = 0; nf < 4; nf++)
            #pragma unroll
            for (int p = 0; p < 2; p++)
                #pragma unroll
                for (int e = 0; e < 4; e++) cs[nf][p][e] = 0.0f;

        #pragma unroll
        for (int ks = 0; ks < 4; ks++) {
            uint32_t aad = SWZ128((uint32_t)(
                (wid * 16 + (lane & 15)) * 128 + (ks * 16 + (lane >> 4) * 8) * 2));
            uint32_t ah[4], al[4];
            ldsm4(ah, uQH + aad);
            ldsm4(al, uQL + aad);
            int br_off = (lane & 7) + ((lane >> 4) << 3);
            int bk = ks * 16 + (((lane >> 3) & 1) << 3);
            #pragma unroll
            for (int nf = 0; nf < 4; nf++) {
                uint32_t bad = SWZ128((uint32_t)((nf * 16 + br_off) * 128 + bk * 2)) + koff;
                uint32_t bh4[4], bl4[4];
                ldsm4(bh4, uKH + bad);
                ldsm4(bl4, uKL + bad);
                mma16816(cs[nf][0], ah, bh4);
                mma16816(cs[nf][0], ah, bl4);
                mma16816(cs[nf][0], al, bh4);
                mma16816(cs[nf][1], ah, bh4 + 2);
                mma16816(cs[nf][1], ah, bl4 + 2);
                mma16816(cs[nf][1], al, bh4 + 2);
            }
        }

        uint32_t pah[4][4], pal[4][4];   // A-fragments: [nf][e2 + 2*p]

        if (mixed) {
            #pragma unroll
            for (int e2 = 0; e2 < 2; e2++) {
                int rowl = rbase + e2 * 8;
                int trow = t0 + rowl;
                const float* prow = g_proj + ((size_t)bh * TT + trow) * NR;
                float mx = -1e30f;
                #pragma unroll
                for (int nf = 0; nf < 4; nf++)
                    #pragma unroll
                    for (int p = 0; p < 2; p++)
                        #pragma unroll
                        for (int j = 0; j < 2; j++) {
                            int kg = k0 + nf * 16 + p * 8 + (lane & 3) * 2 + j;
                            int dist = kg - trow;
                            dist = dist < -MAXR ? -MAXR : (dist > MAXR ? MAXR : dist);
                            float v = (cs[nf][p][e2 * 2 + j] + prow[dist + MAXR]) * SCALE2;
                            cs[nf][p][e2 * 2 + j] = v;
                            mx = fmaxf(mx, v);
                        }
                mx = fmaxf(mx, __shfl_xor_sync(0xffffffffu, mx, 1));
                mx = fmaxf(mx, __shfl_xor_sync(0xffffffffu, mx, 2));
                if (mx > m[e2]) {
                    float f = exp2f(m[e2] - mx);
                    m[e2] = mx;
                    l[e2] *= f; plo[e2] *= f;
                    #pragma unroll
                    for (int nf = 0; nf < 4; nf++)
                        #pragma unroll
                        for (int p = 0; p < 2; p++) {
                            c[nf][p][e2 * 2]     *= f;
                            c[nf][p][e2 * 2 + 1] *= f;
                        }
                }
                float mnew = m[e2];

                float es = 0.0f, pl = 0.0f;
                #pragma unroll
                for (int nf = 0; nf < 4; nf++)
                    #pragma unroll
                    for (int p = 0; p < 2; p++) {
                        float v0 = cs[nf][p][e2 * 2], v1 = cs[nf][p][e2 * 2 + 1];
                        float p0 = exp2f(v0 - mnew), p1 = exp2f(v1 - mnew);
                        es += p0 + p1;
                        int kcol = nf * 16 + p * 8 + (lane & 3) * 2;
                        int d0 = (k0 + kcol) - trow;
                        if ((unsigned)(d0 + 67) <= 134u) bandb[rowl * 136 + d0 + 67] = v0;
                        else if (d0 <= -MAXR) pl += p0;
                        int d1 = d0 + 1;
                        if ((unsigned)(d1 + 67) <= 134u) bandb[rowl * 136 + d1 + 67] = v1;
                        else if (d1 <= -MAXR) pl += p1;
                        split2(p0, p1, pah[nf][e2 + 2 * p], pal[nf][e2 + 2 * p]);
                    }
                es += __shfl_xor_sync(0xffffffffu, es, 1);
                es += __shfl_xor_sync(0xffffffffu, es, 2);
                pl += __shfl_xor_sync(0xffffffffu, pl, 1);
                pl += __shfl_xor_sync(0xffffffffu, pl, 2);
                l[e2] += es; plo[e2] += pl;
            }
        } else {
            #pragma unroll
            for (int e2 = 0; e2 < 2; e2++) {
                float cadd = lowside ? prow0[e2] : prow136[e2];
                float mx = -1e30f;
                #pragma unroll
                for (int nf = 0; nf < 4; nf++)
                    #pragma unroll
                    for (int p = 0; p < 2; p++)
                        #pragma unroll
                        for (int j = 0; j < 2; j++) {
                            float v = (cs[nf][p][e2 * 2 + j] + cadd) * SCALE2;
                            cs[nf][p][e2 * 2 + j] = v;
                            mx = fmaxf(mx, v);
                        }
                mx = fmaxf(mx, __shfl_xor_sync(0xffffffffu, mx, 1));
                mx = fmaxf(mx, __shfl_xor_sync(0xffffffffu, mx, 2));
                if (mx > m[e2]) {
                    float f = exp2f(m[e2] - mx);
                    m[e2] = mx;
                    l[e2] *= f; plo[e2] *= f;
                    #pragma unroll
                    for (int nf = 0; nf < 4; nf++)
                        #pragma unroll
                        for (int p = 0; p < 2; p++) {
                            c[nf][p][e2 * 2]     *= f;
                            c[nf][p][e2 * 2 + 1] *= f;
                        }
                }
                float mnew = m[e2];

                float es = 0.0f;
                #pragma unroll
                for (int nf = 0; nf < 4; nf++)
                    #pragma unroll
                    for (int p = 0; p < 2; p++) {
                        float p0 = exp2f(cs[nf][p][e2 * 2]     - mnew);
                        float p1 = exp2f(cs[nf][p][e2 * 2 + 1] - mnew);
                        es += p0 + p1;
                        split2(p0, p1, pah[nf][e2 + 2 * p], pal[nf][e2 + 2 * p]);
                    }
                es += __shfl_xor_sync(0xffffffffu, es, 1);
                es += __shfl_xor_sync(0xffffffffu, es, 2);
                l[e2] += es;
                if (lowside) plo[e2] += es;
            }
        }

        // PV MMA: A = register fragments (ks = k/16 group), B = Vt chunk
        #pragma unroll
        for (int ks = 0; ks < 4; ks++) {
            int br_off = (lane & 7) + ((lane >> 4) << 3);
            int bk = ks * 16 + (((lane >> 3) & 1) << 3);
            #pragma unroll
            for (int nf = 0; nf < 4; nf++) {
                uint32_t bad = SWZ128((uint32_t)((nf * 16 + br_off) * 128 + bk * 2)) + koff;
                uint32_t bh4[4], bl4[4];
                ldsm4(bh4, uVH + bad);
                ldsm4(bl4, uVL + bad);
                mma16816(c[nf][0], pah[ks], bh4);
                mma16816(c[nf][0], pah[ks], bl4);
                mma16816(c[nf][0], pal[ks], bh4);
                mma16816(c[nf][1], pah[ks], bh4 + 2);
                mma16816(c[nf][1], pah[ks], bl4 + 2);
                mma16816(c[nf][1], pal[ks], bh4 + 2);
            }
        }
        __syncthreads();
        if (kc + 2 < 16) load_kv(kc + 2);
    }

    // ---- epilogue: band @ rel_vt via MMA, fragment layout, no P smem ----
    float intu[2] = {0.0f, 0.0f};

    for (int ck = 0; ck < 3; ck++) {
        int cb0 = ck * 64;
        {
            int r = tid >> 3, g8 = tid & 7;
            uint32_t dst = SWZ128((uint32_t)(r * 128 + g8 * 16));
            size_t src = (size_t)r * 192 + cb0 + g8 * 8;
            *(uint4*)(smc + FA_VHI + dst) = *(const uint4*)(g_rvthi + src);
            *(uint4*)(smc + FA_VLO + dst) = *(const uint4*)(g_rvtlo + src);
        }
        __syncthreads();

        uint32_t pah[4][4], pal[4][4];
        #pragma unroll
        for (int nf = 0; nf < 4; nf++)
            #pragma unroll
            for (int p = 0; p < 2; p++)
                #pragma unroll
                for (int e2 = 0; e2 < 2; e2++) {
                    int rowl = rbase + e2 * 8;
                    int col = cb0 + nf * 16 + p * 8 + (lane & 3) * 2;
                    float v0 = (col < 135)     ? bandb[rowl * 136 + col]     : -1e30f;
                    float v1 = (col + 1 < 135) ? bandb[rowl * 136 + col + 1] : -1e30f;
                    float p0 = exp2f(v0 - m[e2]);
                    float p1 = exp2f(v1 - m[e2]);
                    intu[e2] += p0 + p1;
                    split2(p0, p1, pah[nf][e2 + 2 * p], pal[nf][e2 + 2 * p]);
                }

        #pragma unroll
        for (int ks = 0; ks < 4; ks++) {
            int br_off = (lane & 7) + ((lane >> 4) << 3);
            int bk = ks * 16 + (((lane >> 3) & 1) << 3);
            #pragma unroll
            for (int nf = 0; nf < 4; nf++) {
                uint32_t bad = SWZ128((uint32_t)((nf * 16 + br_off) * 128 + bk * 2));
                uint32_t bh4[4], bl4[4];
                ldsm4(bh4, uVH + bad);
                ldsm4(bl4, uVL + bad);
                mma16816(c[nf][0], pah[ks], bh4);
                mma16816(c[nf][0], pah[ks], bl4);
                mma16816(c[nf][0], pal[ks], bh4);
                mma16816(c[nf][1], pah[ks], bh4 + 2);
                mma16816(c[nf][1], pah[ks], bl4 + 2);
                mma16816(c[nf][1], pal[ks], bh4 + 2);
            }
        }
        __syncthreads();
    }

    #pragma unroll
    for (int e2 = 0; e2 < 2; e2++) {
        intu[e2] += __shfl_xor_sync(0xffffffffu, intu[e2], 1);
        intu[e2] += __shfl_xor_sync(0xffffffffu, intu[e2], 2);
    }

    int b_ = bh >> 3, h = bh & 7;
    #pragma unroll
    for (int e2 = 0; e2 < 2; e2++) {
        int rowl = rbase + e2 * 8;
        int t = t0 + rowl;
        float lr = l[e2], pl = plo[e2];
        float phi = lr - pl - intu[e2];
        float inv = 1.0f / lr;
        #pragma unroll
        for (int nf = 0; nf < 4; nf++)
            #pragma unroll
            for (int p = 0; p < 2; p++) {
                int d = nf * 16 + p * 8 + (lane & 3) * 2;
                float w0 = c[nf][p][e2 * 2]     + pl * g_rv0[d]
                         + phi * g_rv136[d];
                float w1 = c[nf][p][e2 * 2 + 1] + pl * g_rv0[d + 1]
                         + phi * g_rv136[d + 1];
                float o0 = w0 * inv, o1 = w1 * inv;
                size_t ob = ((size_t)(b_ * TT + t)) * CC + h * HD + d;
                uint32_t hp, lp2;
                split2(o0, o1, hp, lp2);
                *(uint32_t*)(g_yhi + ob) = hp;
                *(uint32_t*)(g_ylo + ob) = lp2;
            }
    }
}

// ---------------------------------------------------------------------------
extern "C" void kernel_launch(void* const* d_in, const int* in_sizes, int n_in,
                              void* d_out, int out_size)
{
    const float* x     = (const float*)d_in[0];
    const float* Wq    = (const float*)d_in[1];
    const float* bq    = (const float*)d_in[2];
    const float* Wk    = (const float*)d_in[3];
    const float* bk    = (const float*)d_in[4];
    const float* Wv    = (const float*)d_in[5];
    const float* bv    = (const float*)d_in[6];
    const float* Wo    = (const float*)d_in[7];
    const float* bo    = (const float*)d_in[8];
    const float* rel_k = (const float*)d_in[9];
    const float* rel_v = (const float*)d_in[10];
    float* out = (float*)d_out;

    cudaFuncSetAttribute(gemm_mma, cudaFuncAttributeMaxDynamicSharedMemorySize,
                         GT_SMEM);
    cudaFuncSetAttribute(attn_mma, cudaFuncAttributeMaxDynamicSharedMemorySize,
                         FA_SMEM);

    conv_edge<<<1, 64>>>(rel_v);
    conv_all<<<1024, 512>>>(x, Wq, Wk, Wv, Wo, bq, bk, bv, bo, rel_k, rel_v);
    gemm_mma<<<dim3(12, 64), 256, GT_SMEM>>>(nullptr, 1);
    attn_mma<<<dim3(4, 64), 512, FA_SMEM>>>();
    gemm_mma<<<dim3(4, 64), 256, GT_SMEM>>>(out, 0);
}

// round 17
// speedup vs baseline: 3.2788x; 1.0182x over previous
#include <cuda_runtime.h>
#include <cuda_bf16.h>
#include <cstdint>

// Problem constants
#define BB   8
#define TT   1024
#define CC   512
#define HH   8
#define HD   64
#define NR   137
#define MAXR 68
#define BH   64
#define MM   8192
#define NRP  144

// ---------------------------------------------------------------------------
// Scratch (device globals)
// ---------------------------------------------------------------------------
static __device__ float g_proj[BH * TT * NR];
static __device__ float g_band[BH * TT * 136];
static __device__ float g_rv0[HD];
static __device__ float g_rv136[HD];

static __device__ __nv_bfloat16 g_qhi[BH * TT * HD];
static __device__ __nv_bfloat16 g_qlo[BH * TT * HD];
static __device__ __nv_bfloat16 g_khi[BH * TT * HD];
static __device__ __nv_bfloat16 g_klo[BH * TT * HD];
static __device__ __nv_bfloat16 g_vthi[BH * HD * TT];   // [bh][d][t]
static __device__ __nv_bfloat16 g_vtlo[BH * HD * TT];
static __device__ __nv_bfloat16 g_rkhi[NRP * HD];
static __device__ __nv_bfloat16 g_rklo[NRP * HD];
static __device__ __nv_bfloat16 g_rvthi[HD * 192];      // rvt[d][j] = rel_v[j+1][d]
static __device__ __nv_bfloat16 g_rvtlo[HD * 192];

static __device__ __nv_bfloat16 g_xhi[MM * CC];
static __device__ __nv_bfloat16 g_xlo[MM * CC];
static __device__ __nv_bfloat16 g_yhi[MM * CC];
static __device__ __nv_bfloat16 g_ylo[MM * CC];
static __device__ __nv_bfloat16 g_wthi[4 * CC * CC];
static __device__ __nv_bfloat16 g_wtlo[4 * CC * CC];
static __device__ float g_bias[4 * CC];

// ---------------------------------------------------------------------------
// helpers
// ---------------------------------------------------------------------------
__device__ __forceinline__ uint32_t smem_u32(const void* p) {
    uint32_t a;
    asm("{ .reg .u64 t; cvta.to.shared.u64 t, %1; cvt.u32.u64 %0, t; }"
        : "=r"(a) : "l"(p));
    return a;
}
__device__ __forceinline__ void ldsm4(uint32_t* r, uint32_t addr) {
    asm volatile("ldmatrix.sync.aligned.m8n8.x4.shared.b16 {%0,%1,%2,%3}, [%4];"
        : "=r"(r[0]), "=r"(r[1]), "=r"(r[2]), "=r"(r[3]) : "r"(addr));
}
__device__ __forceinline__ void ldsm2(uint32_t* r, uint32_t addr) {
    asm volatile("ldmatrix.sync.aligned.m8n8.x2.shared.b16 {%0,%1}, [%2];"
        : "=r"(r[0]), "=r"(r[1]) : "r"(addr));
}
__device__ __forceinline__ void mma16816(float* c, const uint32_t* a, const uint32_t* b) {
    asm volatile(
        "mma.sync.aligned.m16n8k16.row.col.f32.bf16.bf16.f32 "
        "{%0,%1,%2,%3}, {%4,%5,%6,%7}, {%8,%9}, {%0,%1,%2,%3};"
        : "+f"(c[0]), "+f"(c[1]), "+f"(c[2]), "+f"(c[3])
        : "r"(a[0]), "r"(a[1]), "r"(a[2]), "r"(a[3]), "r"(b[0]), "r"(b[1]));
}
#define SWZ128(b) ((b) ^ (((b) >> 3) & 0x70))

#define CP_A16(dst, src) \
    asm volatile("cp.async.cg.shared.global [%0], [%1], 16;" \
                 :: "r"(dst), "l"(src) : "memory")
#define CP_COMMIT() asm volatile("cp.async.commit_group;" ::: "memory")
#define CP_WAIT1()  asm volatile("cp.async.wait_group 1;" ::: "memory")
#define CP_WAIT0()  asm volatile("cp.async.wait_group 0;" ::: "memory")

__device__ __forceinline__ uint32_t pack_bf2(__nv_bfloat16 a, __nv_bfloat16 b) {
    __nv_bfloat162 t = {a, b};
    return *(uint32_t*)&t;
}

// packed hi/lo split: {p0 low, p1 high}
__device__ __forceinline__ void split2(float p0, float p1, uint32_t& hi, uint32_t& lo)
{
    uint32_t h;
    asm("cvt.rn.bf16x2.f32 %0, %1, %2;" : "=r"(h) : "f"(p1), "f"(p0));
    float f0 = __uint_as_float(h << 16);
    float f1 = __uint_as_float(h & 0xFFFF0000u);
    uint32_t l;
    asm("cvt.rn.bf16x2.f32 %0, %1, %2;" : "=r"(l) : "f"(p1 - f1), "f"(p0 - f0));
    hi = h; lo = l;
}

// ---------------------------------------------------------------------------
// conv_all: all input conversions in one launch (includes rel_v edge rows)
// ---------------------------------------------------------------------------
__global__ __launch_bounds__(512) void conv_all(
    const float* __restrict__ x,
    const float* __restrict__ Wq, const float* __restrict__ Wk,
    const float* __restrict__ Wv, const float* __restrict__ Wo,
    const float* __restrict__ bq, const float* __restrict__ bk,
    const float* __restrict__ bv, const float* __restrict__ bo,
    const float* __restrict__ rel_k, const float* __restrict__ rel_v)
{
    int gid = blockIdx.x * blockDim.x + threadIdx.x;
    int nth = gridDim.x * blockDim.x;
    for (int idx = gid; idx < 4 * CC * CC; idx += nth) {
        int z = idx >> 18;
        int rem = idx & (CC * CC - 1);
        int k = rem >> 9, n = rem & 511;
        const float* W = (z == 0) ? Wq : (z == 1) ? Wk : (z == 2) ? Wv : Wo;
        float v = W[k * CC + n];
        __nv_bfloat16 h = __float2bfloat16(v);
        size_t dst = (size_t)z * CC * CC + (size_t)n * CC + k;
        g_wthi[dst] = h;
        g_wtlo[dst] = __float2bfloat16(v - __bfloat162float(h));
    }
    for (int i = gid; i < MM * CC / 4; i += nth) {
        float4 v = *(const float4*)(x + (size_t)i * 4);
        float vv[4] = {v.x, v.y, v.z, v.w};
        #pragma unroll
        for (int j = 0; j < 4; j++) {
            __nv_bfloat16 h = __float2bfloat16(vv[j]);
            g_xhi[(size_t)i * 4 + j] = h;
            g_xlo[(size_t)i * 4 + j] = __float2bfloat16(vv[j] - __bfloat162float(h));
        }
    }
    for (int idx = gid; idx < NRP * HD; idx += nth) {
        int r = idx >> 6, d = idx & 63;
        float v = (r < NR) ? rel_k[r * HD + d] : 0.0f;
        __nv_bfloat16 h = __float2bfloat16(v);
        g_rkhi[idx] = h;
        g_rklo[idx] = __float2bfloat16(v - __bfloat162float(h));
    }
    for (int idx = gid; idx < HD * 192; idx += nth) {
        int d = idx / 192, j = idx - d * 192;
        float v = (j < 135) ? rel_v[(j + 1) * HD + d] : 0.0f;
        __nv_bfloat16 h = __float2bfloat16(v);
        g_rvthi[idx] = h;
        g_rvtlo[idx] = __float2bfloat16(v - __bfloat162float(h));
    }
    if (gid < 4 * CC) {
        int z = gid >> 9, n = gid & 511;
        const float* bsrc = (z == 0) ? bq : (z == 1) ? bk : (z == 2) ? bv : bo;
        g_bias[gid] = bsrc[n];
    }
    if (gid < HD) {
        g_rv0[gid]   = rel_v[gid];
        g_rv136[gid] = rel_v[136 * HD + gid];
    }
}

// ---------------------------------------------------------------------------
// bf16x3 warp-MMA GEMM, 2-stage cp.async pipeline (unchanged)
// ---------------------------------------------------------------------------
#define GT_A_HI 0
#define GT_A_LO 16384
#define GT_B_HI 32768
#define GT_B_LO 49152
#define GT_SMEM 65536

__global__ __launch_bounds__(256, 2) void gemm_mma(float* __restrict__ outp, int mode)
{
    extern __shared__ char smc[];
    const __nv_bfloat16 *Ahi, *Alo, *Bhi, *Blo;
    const float* bias;
    if (mode == 1) {
        Ahi = g_xhi; Alo = g_xlo; Bhi = g_wthi; Blo = g_wtlo; bias = g_bias;
    } else {
        Ahi = g_yhi; Alo = g_ylo;
        Bhi = g_wthi + 3 * CC * CC; Blo = g_wtlo + 3 * CC * CC;
        bias = g_bias + 3 * CC;
    }

    int tid = threadIdx.x, lane = tid & 31, wid = tid >> 5;
    int wm = wid >> 2, wn = wid & 3;
    int row0 = blockIdx.y * 128, col0 = blockIdx.x * 128;

    uint32_t uAH = smem_u32(smc + GT_A_HI);
    uint32_t uAL = smem_u32(smc + GT_A_LO);
    uint32_t uBH = smem_u32(smc + GT_B_HI);
    uint32_t uBL = smem_u32(smc + GT_B_LO);

    float c[4][4][4];
    #pragma unroll
    for (int mi = 0; mi < 4; mi++)
        #pragma unroll
        for (int ni = 0; ni < 4; ni++)
            #pragma unroll
            for (int e = 0; e < 4; e++) c[mi][ni][e] = 0.0f;

    auto load_chunk = [&](int kc) {
        int k0 = kc * 32;
        int sb64 = (kc & 1) * 64;
        #pragma unroll
        for (int s2 = 0; s2 < 2; s2++) {
            int vec = tid + s2 * 256;
            int idx = vec >> 2, v4 = vec & 3;
            int r = (idx & ~7) | ((idx & 1) << 2) | ((idx >> 1) & 3);
            uint32_t dst = SWZ128((uint32_t)(r * 128 + sb64 + v4 * 16));
            size_t asrc = (size_t)(row0 + r) * CC + k0 + v4 * 8;
            size_t bsrc = (size_t)(col0 + r) * CC + k0 + v4 * 8;
            CP_A16(uAH + dst, Ahi + asrc);
            CP_A16(uAL + dst, Alo + asrc);
            CP_A16(uBH + dst, Bhi + bsrc);
            CP_A16(uBL + dst, Blo + bsrc);
        }
        CP_COMMIT();
    };

    load_chunk(0);
    load_chunk(1);

    for (int kc = 0; kc < 16; kc++) {
        if (kc < 15) { CP_WAIT1(); } else { CP_WAIT0(); }
        __syncthreads();

        int sbe = (kc & 1) * 32;
        #pragma unroll
        for (int ks = 0; ks < 2; ks++) {
            int kbase = sbe + ks * 16;
            int lp = lane & 15;
            int bkb = kbase + (lp >> 3) * 8;
            uint32_t bh[4][2], bl[4][2];
            #pragma unroll
            for (int ni = 0; ni < 4; ni++) {
                int nloc = wn * 32 + ni * 8 + (lp & 7);
                uint32_t ad = SWZ128((uint32_t)(nloc * 128 + bkb * 2));
                ldsm2(bh[ni], uBH + ad);
                ldsm2(bl[ni], uBL + ad);
            }
            int akb = kbase + (lane >> 4) * 8;
            int mlp = lane & 15;
            #pragma unroll
            for (int mi = 0; mi < 4; mi++) {
                int mloc = wm * 64 + mi * 16 + mlp;
                uint32_t ad = SWZ128((uint32_t)(mloc * 128 + akb * 2));
                uint32_t ah[4], al[4];
                ldsm4(ah, uAH + ad);
                ldsm4(al, uAL + ad);
                #pragma unroll
                for (int ni = 0; ni < 4; ni++) {
                    mma16816(c[mi][ni], ah, bh[ni]);
                    mma16816(c[mi][ni], ah, bl[ni]);
                    mma16816(c[mi][ni], al, bh[ni]);
                }
            }
        }
        __syncthreads();
        if (kc + 2 < 16) load_chunk(kc + 2);
    }

    int r_base = row0 + wm * 64 + (lane >> 2);
    int n_base = col0 + wn * 32 + (lane & 3) * 2;

    if (mode == 0) {
        #pragma unroll
        for (int mi = 0; mi < 4; mi++) {
            int r = r_base + mi * 16;
            #pragma unroll
            for (int ni = 0; ni < 4; ni++) {
                int n = n_base + ni * 8;
                float b0 = bias[n], b1 = bias[n + 1];
                float2 v0 = make_float2(c[mi][ni][0] + b0, c[mi][ni][1] + b1);
                float2 v1 = make_float2(c[mi][ni][2] + b0, c[mi][ni][3] + b1);
                *(float2*)(outp + (size_t)r * CC + n)       = v0;
                *(float2*)(outp + (size_t)(r + 8) * CC + n) = v1;
            }
        }
    } else {
        int z = col0 >> 9;
        #pragma unroll
        for (int mi = 0; mi < 4; mi++) {
            int r = r_base + mi * 16;
            int b_ = r >> 10, t = r & (TT - 1);
            #pragma unroll
            for (int ni = 0; ni < 4; ni++) {
                int n = n_base + ni * 8;
                int nn = n & 511;
                int h = nn >> 6, d = nn & 63;
                float b0 = bias[n], b1 = bias[n + 1];
                float p00 = c[mi][ni][0] + b0, p01 = c[mi][ni][1] + b1;
                float p10 = c[mi][ni][2] + b0, p11 = c[mi][ni][3] + b1;
                __nv_bfloat16 h00 = __float2bfloat16(p00);
                __nv_bfloat16 h01 = __float2bfloat16(p01);
                __nv_bfloat16 h10 = __float2bfloat16(p10);
                __nv_bfloat16 h11 = __float2bfloat16(p11);
                __nv_bfloat16 l00 = __float2bfloat16(p00 - __bfloat162float(h00));
                __nv_bfloat16 l01 = __float2bfloat16(p01 - __bfloat162float(h01));
                __nv_bfloat16 l10 = __float2bfloat16(p10 - __bfloat162float(h10));
                __nv_bfloat16 l11 = __float2bfloat16(p11 - __bfloat162float(h11));
                if (z == 2) {
                    size_t vb = (((size_t)(b_ * HH + h)) * HD + d) * TT + t;
                    g_vthi[vb]          = h00;
                    g_vthi[vb + TT]     = h01;
                    g_vthi[vb + 8]      = h10;
                    g_vthi[vb + TT + 8] = h11;
                    g_vtlo[vb]          = l00;
                    g_vtlo[vb + TT]     = l01;
                    g_vtlo[vb + 8]      = l10;
                    g_vtlo[vb + TT + 8] = l11;
                } else {
                    __nv_bfloat16* dhi = (z == 0) ? g_qhi : g_khi;
                    __nv_bfloat16* dlo = (z == 0) ? g_qlo : g_klo;
                    size_t o = (((size_t)b_ * HH + h) * TT + t) * HD + d;
                    *(uint32_t*)(dhi + o)          = pack_bf2(h00, h01);
                    *(uint32_t*)(dhi + o + 8 * HD) = pack_bf2(h10, h11);
                    *(uint32_t*)(dlo + o)          = pack_bf2(l00, l01);
                    *(uint32_t*)(dlo + o + 8 * HD) = pack_bf2(l10, l11);
                }
            }
        }
    }
}

// ---------------------------------------------------------------------------
// attn_mma v6: hoisted addresses, trimmed epilogue, selective band init
// ---------------------------------------------------------------------------
#define FA_QHI 0
#define FA_QLO 32768
#define FA_KHI 65536
#define FA_KLO 81920
#define FA_VHI 98304
#define FA_VLO 114688
#define FA_SMEM 131072

__global__ __launch_bounds__(512, 1) void attn_mma()
{
    extern __shared__ char smc[];
    int tid = threadIdx.x, lane = tid & 31, wid = tid >> 5;
    int bh = blockIdx.y, t0 = blockIdx.x * 256;

    uint32_t uQH = smem_u32(smc + FA_QHI);
    uint32_t uQL = smem_u32(smc + FA_QLO);
    uint32_t uKH = smem_u32(smc + FA_KHI);
    uint32_t uKL = smem_u32(smc + FA_KLO);
    uint32_t uVH = smem_u32(smc + FA_VHI);
    uint32_t uVL = smem_u32(smc + FA_VLO);

    size_t qb = (size_t)bh * TT * HD;
    size_t vtb = (size_t)bh * HD * TT;
    float* bandb = g_band + ((size_t)bh * TT + t0) * 136;

    #pragma unroll
    for (int s = 0; s < 4; s++) {
        int vec = tid + s * 512;
        int r = vec >> 3, g8 = vec & 7;
        uint32_t dst = SWZ128((uint32_t)(r * 128 + g8 * 16));
        size_t src = qb + (size_t)(t0 + r) * HD + g8 * 8;
        *(uint4*)(smc + FA_QHI + dst) = *(const uint4*)(g_qhi + src);
        *(uint4*)(smc + FA_QLO + dst) = *(const uint4*)(g_qlo + src);
    }
    for (int vec = tid; vec < NRP * 8; vec += 512) {
        int r = vec >> 3, g8 = vec & 7;
        uint32_t dst = SWZ128((uint32_t)(r * 128 + g8 * 16));
        size_t src = (size_t)r * HD + g8 * 8;
        *(uint4*)(smc + FA_KHI + dst) = *(const uint4*)(g_rkhi + src);
        *(uint4*)(smc + FA_VHI + dst) = *(const uint4*)(g_rklo + src);
    }
    // band init only needed where rows have unreachable cols (edge t-blocks)
    if (blockIdx.x == 0 || blockIdx.x == 3)
        for (int idx = tid; idx < 256 * 136; idx += 512) bandb[idx] = -1e30f;
    __syncthreads();

    int rbase = wid * 16 + (lane >> 2);

    // hoisted fragment addresses (SWZ(addr) = SWZ(base) + nf*2048)
    uint32_t aadr[4], bB[4];
    {
        int br_off = (lane & 7) + ((lane >> 4) << 3);
        #pragma unroll
        for (int ks = 0; ks < 4; ks++) {
            aadr[ks] = SWZ128((uint32_t)(
                (wid * 16 + (lane & 15)) * 128 + (ks * 16 + (lane >> 4) * 8) * 2));
            int bk = ks * 16 + (((lane >> 3) & 1) << 3);
            bB[ks] = SWZ128((uint32_t)(br_off * 128 + bk * 2));
        }
    }

    // ---- in-kernel proj ----
    {
        float cp[9][2][4];
        #pragma unroll
        for (int nf = 0; nf < 9; nf++)
            #pragma unroll
            for (int p = 0; p < 2; p++)
                #pragma unroll
                for (int e = 0; e < 4; e++) cp[nf][p][e] = 0.0f;

        #pragma unroll
        for (int ks = 0; ks < 4; ks++) {
            uint32_t ah[4], al[4];
            ldsm4(ah, uQH + aadr[ks]);
            ldsm4(al, uQL + aadr[ks]);
            #pragma unroll
            for (int nf = 0; nf < 9; nf++) {
                uint32_t bad = bB[ks] + (uint32_t)nf * 2048u;
                uint32_t bh4[4], bl4[4];
                ldsm4(bh4, uKH + bad);
                ldsm4(bl4, uVH + bad);
                mma16816(cp[nf][0], ah, bh4);
                mma16816(cp[nf][0], ah, bl4);
                mma16816(cp[nf][0], al, bh4);
                mma16816(cp[nf][1], ah, bh4 + 2);
                mma16816(cp[nf][1], ah, bl4 + 2);
                mma16816(cp[nf][1], al, bh4 + 2);
            }
        }
        #pragma unroll
        for (int e2 = 0; e2 < 2; e2++) {
            int row = t0 + rbase + e2 * 8;
            float* prow = g_proj + ((size_t)bh * TT + row) * NR;
            #pragma unroll
            for (int nf = 0; nf < 9; nf++)
                #pragma unroll
                for (int p = 0; p < 2; p++) {
                    int col = nf * 16 + p * 8 + (lane & 3) * 2;
                    if (col < NR)     prow[col]     = cp[nf][p][e2 * 2];
                    if (col + 1 < NR) prow[col + 1] = cp[nf][p][e2 * 2 + 1];
                }
        }
    }
    __syncthreads();

    float m[2] = {-1e30f, -1e30f}, l[2] = {0.0f, 0.0f}, plo[2] = {0.0f, 0.0f};
    float c[4][2][4];
    #pragma unroll
    for (int nf = 0; nf < 4; nf++)
        #pragma unroll
        for (int p = 0; p < 2; p++)
            #pragma unroll
            for (int e = 0; e < 4; e++) c[nf][p][e] = 0.0f;

    const float SCALE2 = 0.044194173824159216f * 1.4426950408889634f;

    float prow0[2], prow136[2];
    #pragma unroll
    for (int e2 = 0; e2 < 2; e2++) {
        int trow = t0 + rbase + e2 * 8;
        prow0[e2]   = g_proj[((size_t)bh * TT + trow) * NR];
        prow136[e2] = g_proj[((size_t)bh * TT + trow) * NR + 136];
    }

    auto load_kv = [&](int kc) {
        int k0 = kc * 64;
        uint32_t koff = (uint32_t)(kc & 1) * 8192u;
        int r = tid >> 3, g8 = tid & 7;
        uint32_t dst = SWZ128((uint32_t)(r * 128 + g8 * 16)) + koff;
        size_t ksrc = qb + (size_t)(k0 + r) * HD + g8 * 8;
        size_t vsrc = vtb + (size_t)r * TT + k0 + g8 * 8;
        CP_A16(uKH + dst, g_khi + ksrc);
        CP_A16(uKL + dst, g_klo + ksrc);
        CP_A16(uVH + dst, g_vthi + vsrc);
        CP_A16(uVL + dst, g_vtlo + vsrc);
        CP_COMMIT();
    };

    load_kv(0);
    load_kv(1);

    for (int kc = 0; kc < 16; kc++) {
        int k0 = kc * 64;
        uint32_t koff = (uint32_t)(kc & 1) * 8192u;
        bool mixed = (k0 > t0 - 131) && (k0 < t0 + 323);
        bool lowside = (k0 < t0);

        if (kc < 15) { CP_WAIT1(); } else { CP_WAIT0(); }
        __syncthreads();

        float cs[4][2][4];
        #pragma unroll
        for (int nf = 0; nf < 4; nf++)
            #pragma unroll
            for (int p = 0; p < 2; p++)
                #pragma unroll
                for (int e = 0; e < 4; e++) cs[nf][p][e] = 0.0f;

        #pragma unroll
        for (int ks = 0; ks < 4; ks++) {
            uint32_t ah[4], al[4];
            ldsm4(ah, uQH + aadr[ks]);
            ldsm4(al, uQL + aadr[ks]);
            #pragma unroll
            for (int nf = 0; nf < 4; nf++) {
                uint32_t bad = bB[ks] + (uint32_t)nf * 2048u + koff;
                uint32_t bh4[4], bl4[4];
                ldsm4(bh4, uKH + bad);
                ldsm4(bl4, uKL + bad);
                mma16816(cs[nf][0], ah, bh4);
                mma16816(cs[nf][0], ah, bl4);
                mma16816(cs[nf][0], al, bh4);
                mma16816(cs[nf][1], ah, bh4 + 2);
                mma16816(cs[nf][1], ah, bl4 + 2);
                mma16816(cs[nf][1], al, bh4 + 2);
            }
        }

        uint32_t pah[4][4], pal[4][4];

        if (mixed) {
            #pragma unroll
            for (int e2 = 0; e2 < 2; e2++) {
                int rowl = rbase + e2 * 8;
                int trow = t0 + rowl;
                const float* prow = g_proj + ((size_t)bh * TT + trow) * NR;
                float mx = -1e30f;
                #pragma unroll
                for (int nf = 0; nf < 4; nf++)
                    #pragma unroll
                    for (int p = 0; p < 2; p++)
                        #pragma unroll
                        for (int j = 0; j < 2; j++) {
                            int kg = k0 + nf * 16 + p * 8 + (lane & 3) * 2 + j;
                            int dist = kg - trow;
                            dist = dist < -MAXR ? -MAXR : (dist > MAXR ? MAXR : dist);
                            float v = (cs[nf][p][e2 * 2 + j] + prow[dist + MAXR]) * SCALE2;
                            cs[nf][p][e2 * 2 + j] = v;
                            mx = fmaxf(mx, v);
                        }
                mx = fmaxf(mx, __shfl_xor_sync(0xffffffffu, mx, 1));
                mx = fmaxf(mx, __shfl_xor_sync(0xffffffffu, mx, 2));
                if (mx > m[e2]) {
                    float f = exp2f(m[e2] - mx);
                    m[e2] = mx;
                    l[e2] *= f; plo[e2] *= f;
                    #pragma unroll
                    for (int nf = 0; nf < 4; nf++)
                        #pragma unroll
                        for (int p = 0; p < 2; p++) {
                            c[nf][p][e2 * 2]     *= f;
                            c[nf][p][e2 * 2 + 1] *= f;
                        }
                }
                float mnew = m[e2];

                float es = 0.0f, pl = 0.0f;
                #pragma unroll
                for (int nf = 0; nf < 4; nf++)
                    #pragma unroll
                    for (int p = 0; p < 2; p++) {
                        float v0 = cs[nf][p][e2 * 2], v1 = cs[nf][p][e2 * 2 + 1];
                        float p0 = exp2f(v0 - mnew), p1 = exp2f(v1 - mnew);
                        es += p0 + p1;
                        int kcol = nf * 16 + p * 8 + (lane & 3) * 2;
                        int d0 = (k0 + kcol) - trow;
                        if ((unsigned)(d0 + 67) <= 134u) bandb[rowl * 136 + d0 + 67] = v0;
                        else if (d0 <= -MAXR) pl += p0;
                        int d1 = d0 + 1;
                        if ((unsigned)(d1 + 67) <= 134u) bandb[rowl * 136 + d1 + 67] = v1;
                        else if (d1 <= -MAXR) pl += p1;
                        split2(p0, p1, pah[nf][e2 + 2 * p], pal[nf][e2 + 2 * p]);
                    }
                es += __shfl_xor_sync(0xffffffffu, es, 1);
                es += __shfl_xor_sync(0xffffffffu, es, 2);
                pl += __shfl_xor_sync(0xffffffffu, pl, 1);
                pl += __shfl_xor_sync(0xffffffffu, pl, 2);
                l[e2] += es; plo[e2] += pl;
            }
        } else {
            #pragma unroll
            for (int e2 = 0; e2 < 2; e2++) {
                float cadd = lowside ? prow0[e2] : prow136[e2];
                float mx = -1e30f;
                #pragma unroll
                for (int nf = 0; nf < 4; nf++)
                    #pragma unroll
                    for (int p = 0; p < 2; p++)
                        #pragma unroll
                        for (int j = 0; j < 2; j++) {
                            float v = (cs[nf][p][e2 * 2 + j] + cadd) * SCALE2;
                            cs[nf][p][e2 * 2 + j] = v;
                            mx = fmaxf(mx, v);
                        }
                mx = fmaxf(mx, __shfl_xor_sync(0xffffffffu, mx, 1));
                mx = fmaxf(mx, __shfl_xor_sync(0xffffffffu, mx, 2));
                if (mx > m[e2]) {
                    float f = exp2f(m[e2] - mx);
                    m[e2] = mx;
                    l[e2] *= f; plo[e2] *= f;
                    #pragma unroll
                    for (int nf = 0; nf < 4; nf++)
                        #pragma unroll
                        for (int p = 0; p < 2; p++) {
                            c[nf][p][e2 * 2]     *= f;
                            c[nf][p][e2 * 2 + 1] *= f;
                        }
                }
                float mnew = m[e2];

                float es = 0.0f;
                #pragma unroll
                for (int nf = 0; nf < 4; nf++)
                    #pragma unroll
                    for (int p = 0; p < 2; p++) {
                        float p0 = exp2f(cs[nf][p][e2 * 2]     - mnew);
                        float p1 = exp2f(cs[nf][p][e2 * 2 + 1] - mnew);
                        es += p0 + p1;
                        split2(p0, p1, pah[nf][e2 + 2 * p], pal[nf][e2 + 2 * p]);
                    }
                es += __shfl_xor_sync(0xffffffffu, es, 1);
                es += __shfl_xor_sync(0xffffffffu, es, 2);
                l[e2] += es;
                if (lowside) plo[e2] += es;
            }
        }

        #pragma unroll
        for (int ks = 0; ks < 4; ks++) {
            #pragma unroll
            for (int nf = 0; nf < 4; nf++) {
                uint32_t bad = bB[ks] + (uint32_t)nf * 2048u + koff;
                uint32_t bh4[4], bl4[4];
                ldsm4(bh4, uVH + bad);
                ldsm4(bl4, uVL + bad);
                mma16816(c[nf][0], pah[ks], bh4);
                mma16816(c[nf][0], pah[ks], bl4);
                mma16816(c[nf][0], pal[ks], bh4);
                mma16816(c[nf][1], pah[ks], bh4 + 2);
                mma16816(c[nf][1], pah[ks], bl4 + 2);
                mma16816(c[nf][1], pal[ks], bh4 + 2);
            }
        }
        __syncthreads();
        if (kc + 2 < 16) load_kv(kc + 2);
    }

    // ---- epilogue: band @ rel_vt via MMA, fragment layout ----
    float intu[2] = {0.0f, 0.0f};

    for (int ck = 0; ck < 3; ck++) {
        int cb0 = ck * 64;
        int nfmax = (ck == 2) ? 1 : 4;      // cols >= 144 are all empty
        {
            int r = tid >> 3, g8 = tid & 7;
            uint32_t dst = SWZ128((uint32_t)(r * 128 + g8 * 16));
            size_t src = (size_t)r * 192 + cb0 + g8 * 8;
            *(uint4*)(smc + FA_VHI + dst) = *(const uint4*)(g_rvthi + src);
            *(uint4*)(smc + FA_VLO + dst) = *(const uint4*)(g_rvtlo + src);
        }
        __syncthreads();

        uint32_t pah[4][4], pal[4][4];
        for (int nf = 0; nf < nfmax; nf++)
            #pragma unroll
            for (int p = 0; p < 2; p++)
                #pragma unroll
                for (int e2 = 0; e2 < 2; e2++) {
                    int rowl = rbase + e2 * 8;
                    int col = cb0 + nf * 16 + p * 8 + (lane & 3) * 2;
                    float v0 = (col < 135)     ? bandb[rowl * 136 + col]     : -1e30f;
                    float v1 = (col + 1 < 135) ? bandb[rowl * 136 + col + 1] : -1e30f;
                    float p0 = exp2f(v0 - m[e2]);
                    float p1 = exp2f(v1 - m[e2]);
                    intu[e2] += p0 + p1;
                    split2(p0, p1, pah[nf][e2 + 2 * p], pal[nf][e2 + 2 * p]);
                }

        for (int ks = 0; ks < nfmax; ks++) {      // k-groups beyond cols are zero
            #pragma unroll
            for (int nf = 0; nf < 4; nf++) {
                uint32_t bad = bB[ks] + (uint32_t)nf * 2048u;
                uint32_t bh4[4], bl4[4];
                ldsm4(bh4, uVH + bad);
                ldsm4(bl4, uVL + bad);
                mma16816(c[nf][0], pah[ks], bh4);
                mma16816(c[nf][0], pah[ks], bl4);
                mma16816(c[nf][0], pal[ks], bh4);
                mma16816(c[nf][1], pah[ks], bh4 + 2);
                mma16816(c[nf][1], pah[ks], bl4 + 2);
                mma16816(c[nf][1], pal[ks], bh4 + 2);
            }
        }
        __syncthreads();
    }

    #pragma unroll
    for (int e2 = 0; e2 < 2; e2++) {
        intu[e2] += __shfl_xor_sync(0xffffffffu, intu[e2], 1);
        intu[e2] += __shfl_xor_sync(0xffffffffu, intu[e2], 2);
    }

    int b_ = bh >> 3, h = bh & 7;
    #pragma unroll
    for (int e2 = 0; e2 < 2; e2++) {
        int rowl = rbase + e2 * 8;
        int t = t0 + rowl;
        float lr = l[e2], pl = plo[e2];
        float phi = lr - pl - intu[e2];
        float inv = 1.0f / lr;
        #pragma unroll
        for (int nf = 0; nf < 4; nf++)
            #pragma unroll
            for (int p = 0; p < 2; p++) {
                int d = nf * 16 + p * 8 + (lane & 3) * 2;
                float w0 = c[nf][p][e2 * 2]     + pl * g_rv0[d]
                         + phi * g_rv136[d];
                float w1 = c[nf][p][e2 * 2 + 1] + pl * g_rv0[d + 1]
                         + phi * g_rv136[d + 1];
                float o0 = w0 * inv, o1 = w1 * inv;
                size_t ob = ((size_t)(b_ * TT + t)) * CC + h * HD + d;
                uint32_t hp, lp2;
                split2(o0, o1, hp, lp2);
                *(uint32_t*)(g_yhi + ob) = hp;
                *(uint32_t*)(g_ylo + ob) = lp2;
            }
    }
}

// ---------------------------------------------------------------------------
extern "C" void kernel_launch(void* const* d_in, const int* in_sizes, int n_in,
                              void* d_out, int out_size)
{
    const float* x     = (const float*)d_in[0];
    const float* Wq    = (const float*)d_in[1];
    const float* bq    = (const float*)d_in[2];
    const float* Wk    = (const float*)d_in[3];
    const float* bk    = (const float*)d_in[4];
    const float* Wv    = (const float*)d_in[5];
    const float* bv    = (const float*)d_in[6];
    const float* Wo    = (const float*)d_in[7];
    const float* bo    = (const float*)d_in[8];
    const float* rel_k = (const float*)d_in[9];
    const float* rel_v = (const float*)d_in[10];
    float* out = (float*)d_out;

    cudaFuncSetAttribute(gemm_mma, cudaFuncAttributeMaxDynamicSharedMemorySize,
                         GT_SMEM);
    cudaFuncSetAttribute(attn_mma, cudaFuncAttributeMaxDynamicSharedMemorySize,
                         FA_SMEM);

    conv_all<<<1024, 512>>>(x, Wq, Wk, Wv, Wo, bq, bk, bv, bo, rel_k, rel_v);
    gemm_mma<<<dim3(12, 64), 256, GT_SMEM>>>(nullptr, 1);
    attn_mma<<<dim3(4, 64), 512, FA_SMEM>>>();
    gemm_mma<<<dim3(4, 64), 256, GT_SMEM>>>(out, 0);
}